// round 9
// baseline (speedup 1.0000x reference)
#include <cuda_runtime.h>
#include <cuda_bf16.h>
#include <cuda_fp16.h>
#include <cstdint>

#define BB 4
#define DD 512
#define NN 1536
#define HH 8
#define DH 64
#define PS 40   // smem row stride in halves (32 k + 8 pad -> conflict-free ldmatrix)

typedef unsigned short u16;
typedef unsigned int   u32;

// ---------------- scratch (device globals) -----------------------------------
__device__ __align__(16) u16 g_ith[(size_t)3 * BB * NN * DD];  // inputs^T hi [which][b][n][c]
__device__ __align__(16) u16 g_itl[(size_t)3 * BB * NN * DD];  // inputs^T lo
__device__ __align__(16) u16 g_wh[(size_t)4 * DD * DD];        // weights hi [which][o][c]
__device__ __align__(16) u16 g_wl[(size_t)4 * DD * DD];
__device__ __align__(16) u16 g_qh[(size_t)BB * HH * NN * DH];  // [b,h,n,d]
__device__ __align__(16) u16 g_ql[(size_t)BB * HH * NN * DH];
__device__ __align__(16) u16 g_kh[(size_t)BB * HH * NN * DH];  // [b,h,m,d]
__device__ __align__(16) u16 g_kl[(size_t)BB * HH * NN * DH];
__device__ __align__(16) u16 g_vh[(size_t)BB * HH * DH * NN];  // [b,h,d,m]
__device__ __align__(16) u16 g_vl[(size_t)BB * HH * DH * NN];
__device__ __align__(16) u16 g_s16[(size_t)BB * HH * NN * NN]; // fp16 scores [bh][n][m]
__device__ float g_mx[(size_t)BB * HH * NN];   // row max (with penalty semantics)
__device__ float g_iv[(size_t)BB * HH * NN];   // row 1/sum
__device__ __align__(16) u16 g_xth[(size_t)BB * NN * DD];      // PV out^T hi [b][n][c]
__device__ __align__(16) u16 g_xtl[(size_t)BB * NN * DD];
__device__ unsigned char g_mask[(size_t)NN * NN];
__device__ u32 g_minenc;
__device__ u32 g_maskflags;

// ---------------- helpers ----------------------------------------------------
__device__ __forceinline__ u32 enc_f(float x) {
    u32 b = __float_as_uint(x);
    return (b & 0x80000000u) ? ~b : (b | 0x80000000u);
}
__device__ __forceinline__ float dec_f(u32 e) {
    return (e & 0x80000000u) ? __uint_as_float(e ^ 0x80000000u)
                             : __uint_as_float(~e);
}
__device__ __forceinline__ u16 b16hi(float x) {
    return __bfloat16_as_ushort(__float2bfloat16(x));
}
__device__ __forceinline__ u16 b16lo(float x) {
    float hf = __bfloat162float(__float2bfloat16(x));
    return __bfloat16_as_ushort(__float2bfloat16(x - hf));
}
__device__ __forceinline__ void cp16(u32 dst, const void* src) {
    asm volatile("cp.async.ca.shared.global [%0], [%1], 16;" :: "r"(dst), "l"(src));
}
#define CP_COMMIT() asm volatile("cp.async.commit_group;" ::: "memory")
#define CP_WAIT0()  asm volatile("cp.async.wait_group 0;" ::: "memory")

__global__ void init_kernel() { g_minenc = 0xFFFFFFFFu; g_maskflags = 0u; }

// ---------------- mask dtype classification + normalization ------------------
__global__ void __launch_bounds__(256)
mask_classify_kernel(const u32* __restrict__ mw) {
    const int total = NN * NN / 4;
    u32 local = 0;
    for (int i = blockIdx.x * 256 + threadIdx.x; i < total; i += gridDim.x * 256) {
        u32 w = mw[i];
        if (w != 0u && w != 1u)          local |= 1u;
        if (w != 0u && w != 0x3f800000u) local |= 2u;
    }
#pragma unroll
    for (int o = 16; o > 0; o >>= 1) local |= __shfl_xor_sync(0xffffffffu, local, o);
    if ((threadIdx.x & 31) == 0 && local) atomicOr(&g_maskflags, local);
}

__global__ void __launch_bounds__(256)
mask_convert_kernel(const void* __restrict__ mraw) {
    const u32 f = g_maskflags;
    const int mode = ((f & 2u) == 0u) ? 2 : (((f & 1u) == 0u) ? 1 : 0);
    const int total = NN * NN;
    if (mode == 0) {
        const unsigned char* m8 = (const unsigned char*)mraw;
        for (int i = blockIdx.x * 256 + threadIdx.x; i < total; i += gridDim.x * 256)
            g_mask[i] = m8[i] ? 1 : 0;
    } else if (mode == 1) {
        const int* mi = (const int*)mraw;
        for (int i = blockIdx.x * 256 + threadIdx.x; i < total; i += gridDim.x * 256)
            g_mask[i] = mi[i] ? 1 : 0;
    } else {
        const float* mf = (const float*)mraw;
        for (int i = blockIdx.x * 256 + threadIdx.x; i < total; i += gridDim.x * 256)
            g_mask[i] = (mf[i] != 0.0f) ? 1 : 0;
    }
}

// ---------------- prepasses: split inputs/weights into bf16 planes -----------
__global__ void __launch_bounds__(256)
presplit_in_kernel(const float* __restrict__ q, const float* __restrict__ k,
                   const float* __restrict__ v) {
    __shared__ float tile[32][33];
    const int which = blockIdx.z >> 2, b = blockIdx.z & 3;
    const float* src = (which == 0 ? q : which == 1 ? k : v) + (size_t)b * DD * NN;
    const int n0 = blockIdx.x * 32, c0 = blockIdx.y * 32;
    const int tx = threadIdx.x, ty = threadIdx.y;  // 32 x 8
#pragma unroll
    for (int i = 0; i < 32; i += 8)
        tile[ty + i][tx] = src[(size_t)(c0 + ty + i) * NN + n0 + tx];
    __syncthreads();
    u16* dh = g_ith + (size_t)(which * BB + b) * NN * DD;
    u16* dl = g_itl + (size_t)(which * BB + b) * NN * DD;
#pragma unroll
    for (int i = 0; i < 32; i += 8) {
        float x = tile[tx][ty + i];
        size_t o = (size_t)(n0 + ty + i) * DD + c0 + tx;
        dh[o] = b16hi(x);
        dl[o] = b16lo(x);
    }
}

__global__ void __launch_bounds__(256)
presplit_w_kernel(const float* __restrict__ Wq, const float* __restrict__ Wk,
                  const float* __restrict__ Wv, const float* __restrict__ Wm) {
    const int total = 4 * DD * DD;
    for (int i = blockIdx.x * 256 + threadIdx.x; i < total; i += gridDim.x * 256) {
        int w = i >> 18;
        int r = i & (DD * DD - 1);
        const float* src = (w == 0 ? Wq : w == 1 ? Wk : w == 2 ? Wv : Wm);
        float x = src[r];
        g_wh[i] = b16hi(x);
        g_wl[i] = b16lo(x);
    }
}

// ---------------- mma.sync machinery -----------------------------------------
__device__ __forceinline__ void ldm4(u32& r0, u32& r1, u32& r2, u32& r3, u32 addr) {
    asm volatile("ldmatrix.sync.aligned.m8n8.x4.shared.b16 {%0,%1,%2,%3}, [%4];"
                 : "=r"(r0), "=r"(r1), "=r"(r2), "=r"(r3) : "r"(addr));
}
__device__ __forceinline__ void mma16816(float* c, u32 a0, u32 a1, u32 a2, u32 a3,
                                         u32 b0, u32 b1) {
    asm volatile("mma.sync.aligned.m16n8k16.row.col.f32.bf16.bf16.f32 "
                 "{%0,%1,%2,%3}, {%4,%5,%6,%7}, {%8,%9}, {%0,%1,%2,%3};"
                 : "+f"(c[0]), "+f"(c[1]), "+f"(c[2]), "+f"(c[3])
                 : "r"(a0), "r"(a1), "r"(a2), "r"(a3), "r"(b0), "r"(b1));
}
template <int SPS>
__device__ __forceinline__ u32 ldm_addr(u32 base, int lane, int row0, int col0) {
    int r = row0 + (lane & 7) + ((lane >> 3) & 1) * 8;
    int c = col0 + (lane >> 4) * 8;
    return base + (u32)(r * SPS + c) * 2u;
}
// One k16 step of split-bf16: acc += Ah*Bh + Ah*Bl + Al*Bh
template <int IM, int SPS>
__device__ __forceinline__ void mma_step(float (*acc)[4][4],
                                         u32 baAh, u32 baAl, u32 baBh, u32 baBl,
                                         int lane, int mBase, int nBase, int kk) {
    u32 A[IM][4], B[4][2], C[4][2];
    u32 x0, x1, x2, x3;
#pragma unroll
    for (int im = 0; im < IM; im++)
        ldm4(A[im][0], A[im][1], A[im][2], A[im][3],
             ldm_addr<SPS>(baAh, lane, mBase + im * 16, kk));
    ldm4(x0, x1, x2, x3, ldm_addr<SPS>(baBh, lane, nBase, kk));
    B[0][0] = x0; B[0][1] = x2; B[1][0] = x1; B[1][1] = x3;
    ldm4(x0, x1, x2, x3, ldm_addr<SPS>(baBh, lane, nBase + 16, kk));
    B[2][0] = x0; B[2][1] = x2; B[3][0] = x1; B[3][1] = x3;
#pragma unroll
    for (int im = 0; im < IM; im++)
#pragma unroll
        for (int jn = 0; jn < 4; jn++)
            mma16816(acc[im][jn], A[im][0], A[im][1], A[im][2], A[im][3], B[jn][0], B[jn][1]);
    ldm4(x0, x1, x2, x3, ldm_addr<SPS>(baBl, lane, nBase, kk));
    C[0][0] = x0; C[0][1] = x2; C[1][0] = x1; C[1][1] = x3;
    ldm4(x0, x1, x2, x3, ldm_addr<SPS>(baBl, lane, nBase + 16, kk));
    C[2][0] = x0; C[2][1] = x2; C[3][0] = x1; C[3][1] = x3;
#pragma unroll
    for (int im = 0; im < IM; im++)
#pragma unroll
        for (int jn = 0; jn < 4; jn++)
            mma16816(acc[im][jn], A[im][0], A[im][1], A[im][2], A[im][3], C[jn][0], C[jn][1]);
#pragma unroll
    for (int im = 0; im < IM; im++)
        ldm4(A[im][0], A[im][1], A[im][2], A[im][3],
             ldm_addr<SPS>(baAl, lane, mBase + im * 16, kk));
#pragma unroll
    for (int im = 0; im < IM; im++)
#pragma unroll
        for (int jn = 0; jn < 4; jn++)
            mma16816(acc[im][jn], A[im][0], A[im][1], A[im][2], A[im][3], B[jn][0], B[jn][1]);
}

// ---------------- projection: Y[b,o,n] = sum_c W[o,c] X[b,c,n] + bias[o] -----
template <int MODE>
__global__ void __launch_bounds__(256)
proj_kernel(const u16* __restrict__ XTh, const u16* __restrict__ XTl,
            const u16* __restrict__ Wh, const u16* __restrict__ Wl,
            const float* __restrict__ bias, void* __restrict__ y0, void* __restrict__ y1) {
    __shared__ u16 sWh[64][PS], sWl[64][PS], sXh[128][PS], sXl[128][PS];
    const int b = blockIdx.z, o0 = blockIdx.y * 64, n0 = blockIdx.x * 128;
    const int t = threadIdx.x, lane = t & 31, w = t >> 5;
    const int wm = w & 1, wn = w >> 1;
    const u16* Xh = XTh + (size_t)b * NN * DD;
    const u16* Xl = XTl + (size_t)b * NN * DD;
    const int ar = t >> 2, as = (t & 3) * 8;

    const u32 baWh = (u32)__cvta_generic_to_shared(&sWh[0][0]);
    const u32 baWl = (u32)__cvta_generic_to_shared(&sWl[0][0]);
    const u32 baXh = (u32)__cvta_generic_to_shared(&sXh[0][0]);
    const u32 baXl = (u32)__cvta_generic_to_shared(&sXl[0][0]);

    uint4 pa0, pa1, pbh[2], pbl[2];
    float acc[2][4][4];
#pragma unroll
    for (int i = 0; i < 2; i++)
#pragma unroll
        for (int j = 0; j < 4; j++)
#pragma unroll
            for (int k = 0; k < 4; k++) acc[i][j][k] = 0.f;

    auto load_regs = [&](int c0) {
        pa0    = *(const uint4*)&Wh[(size_t)(o0 + ar) * DD + c0 + as];
        pa1    = *(const uint4*)&Wl[(size_t)(o0 + ar) * DD + c0 + as];
        pbh[0] = *(const uint4*)&Xh[(size_t)(n0 + ar) * DD + c0 + as];
        pbl[0] = *(const uint4*)&Xl[(size_t)(n0 + ar) * DD + c0 + as];
        pbh[1] = *(const uint4*)&Xh[(size_t)(n0 + ar + 64) * DD + c0 + as];
        pbl[1] = *(const uint4*)&Xl[(size_t)(n0 + ar + 64) * DD + c0 + as];
    };
    auto store_smem = [&]() {
        *(uint4*)&sWh[ar][as]      = pa0;
        *(uint4*)&sWl[ar][as]      = pa1;
        *(uint4*)&sXh[ar][as]      = pbh[0];
        *(uint4*)&sXl[ar][as]      = pbl[0];
        *(uint4*)&sXh[ar + 64][as] = pbh[1];
        *(uint4*)&sXl[ar + 64][as] = pbl[1];
    };

    load_regs(0); store_smem(); __syncthreads();
    const int NC = DD / 32;
    for (int c = 0; c < NC; c++) {
        if (c + 1 < NC) load_regs((c + 1) * 32);
        mma_step<2, PS>(acc, baWh, baWl, baXh, baXl, lane, wm * 32, wn * 32, 0);
        mma_step<2, PS>(acc, baWh, baWl, baXh, baXl, lane, wm * 32, wn * 32, 16);
        if (c + 1 < NC) { __syncthreads(); store_smem(); __syncthreads(); }
    }

#pragma unroll
    for (int im = 0; im < 2; im++) {
        const int ob = o0 + wm * 32 + im * 16 + (lane >> 2);
        const float bs0 = bias[ob], bs1 = bias[ob + 8];
#pragma unroll
        for (int jn = 0; jn < 4; jn++) {
            float* cc = acc[im][jn];
            const int n = n0 + wn * 32 + jn * 8 + 2 * (lane & 3);
            const float v0 = cc[0] + bs0, v1 = cc[1] + bs0;
            const float v2 = cc[2] + bs1, v3 = cc[3] + bs1;
            if (MODE == 0) {
                float* Y = (float*)y0;
                *(float2*)&Y[((size_t)b * DD + ob) * NN + n]     = make_float2(v0, v1);
                *(float2*)&Y[((size_t)b * DD + ob + 8) * NN + n] = make_float2(v2, v3);
            } else if (MODE == 1) {
                u32* Yh = (u32*)y0;
                u32* Yl = (u32*)y1;
                const int h = ob & 7, d = ob >> 3;
                size_t i0 = (((size_t)(b * HH + h) * NN + n) * DH + d) >> 1;
                Yh[i0]      = (u32)b16hi(v0) | ((u32)b16hi(v2) << 16);
                Yl[i0]      = (u32)b16lo(v0) | ((u32)b16lo(v2) << 16);
                Yh[i0 + 32] = (u32)b16hi(v1) | ((u32)b16hi(v3) << 16);
                Yl[i0 + 32] = (u32)b16lo(v1) | ((u32)b16lo(v3) << 16);
            } else {
                u32* Yh = (u32*)y0;
                u32* Yl = (u32*)y1;
                const int h = ob & 7, d = ob >> 3;
                size_t i0 = (((size_t)(b * HH + h) * DH + d) * NN + n) >> 1;
                Yh[i0] = (u32)b16hi(v0) | ((u32)b16hi(v1) << 16);
                Yl[i0] = (u32)b16lo(v0) | ((u32)b16lo(v1) << 16);
                size_t i1 = i0 + (NN >> 1);
                Yh[i1] = (u32)b16hi(v2) | ((u32)b16hi(v3) << 16);
                Yl[i1] = (u32)b16lo(v2) | ((u32)b16lo(v3) << 16);
            }
        }
    }
}

// ---------------- scores: single k-chunk of 64, cp.async fill, fp16 out ------
#define PS2 72
#define SC_PLANE (128 * PS2 * 2)              // 18432 B
#define SC_SMEM  (4 * SC_PLANE)               // 73728 B
__global__ void __launch_bounds__(512)
scores_kernel() {
    extern __shared__ __align__(16) char dsm[];
    __shared__ float sred[16];
    const int bh = blockIdx.z, n0 = blockIdx.y * 128, m0 = blockIdx.x * 128;
    const int t = threadIdx.x, lane = t & 31, w = t >> 5;
    const int wm = w & 3, wn = w >> 2;   // warp tile 32(n) x 32(m)
    const u16* Qh = g_qh + (size_t)bh * NN * DH;
    const u16* Ql = g_ql + (size_t)bh * NN * DH;
    const u16* Kh = g_kh + (size_t)bh * NN * DH;
    const u16* Kl = g_kl + (size_t)bh * NN * DH;

    const u32 sbase = (u32)__cvta_generic_to_shared(dsm);
    const u32 baQh = sbase, baQl = sbase + SC_PLANE;
    const u32 baKh = sbase + 2 * SC_PLANE, baKl = sbase + 3 * SC_PLANE;

#pragma unroll
    for (int rep = 0; rep < 2; rep++) {
        const int idx = t + rep * 512;
        const int row = idx >> 3, c8 = (idx & 7) * 8;
        const u32 off = (u32)(row * PS2 + c8) * 2u;
        cp16(baQh + off, &Qh[(size_t)(n0 + row) * DH + c8]);
        cp16(baQl + off, &Ql[(size_t)(n0 + row) * DH + c8]);
        cp16(baKh + off, &Kh[(size_t)(m0 + row) * DH + c8]);
        cp16(baKl + off, &Kl[(size_t)(m0 + row) * DH + c8]);
    }
    CP_COMMIT();
    CP_WAIT0();
    __syncthreads();

    float acc[2][4][4];
#pragma unroll
    for (int i = 0; i < 2; i++)
#pragma unroll
        for (int j = 0; j < 4; j++)
#pragma unroll
            for (int k = 0; k < 4; k++) acc[i][j][k] = 0.f;

#pragma unroll
    for (int kk = 0; kk < 64; kk += 16)
        mma_step<2, PS2>(acc, baQh, baQl, baKh, baKl, lane, wm * 32, wn * 32, kk);

    float mn = __int_as_float(0x7f800000);
#pragma unroll
    for (int im = 0; im < 2; im++) {
        const int n = n0 + wm * 32 + im * 16 + (lane >> 2);
#pragma unroll
        for (int jn = 0; jn < 4; jn++) {
            float* cc = acc[im][jn];
            const int m = m0 + wn * 32 + jn * 8 + 2 * (lane & 3);
            float2 r0 = make_float2(cc[0] * 0.125f, cc[1] * 0.125f);
            float2 r1 = make_float2(cc[2] * 0.125f, cc[3] * 0.125f);
            mn = fminf(mn, fminf(fminf(r0.x, r0.y), fminf(r1.x, r1.y)));
            __half2 h0 = __floats2half2_rn(r0.x, r0.y);
            __half2 h1 = __floats2half2_rn(r1.x, r1.y);
            *(u32*)&g_s16[((size_t)bh * NN + n) * NN + m]     = *(u32*)&h0;
            *(u32*)&g_s16[((size_t)bh * NN + n + 8) * NN + m] = *(u32*)&h1;
        }
    }
#pragma unroll
    for (int o = 16; o > 0; o >>= 1) mn = fminf(mn, __shfl_xor_sync(0xffffffffu, mn, o));
    if (lane == 0) sred[w] = mn;
    __syncthreads();
    if (t == 0) {
        float v = sred[0];
#pragma unroll
        for (int i = 1; i < 16; i++) v = fminf(v, sred[i]);
        atomicMin(&g_minenc, enc_f(v));
    }
}

// ---------------- fused out2 + softmax stats ---------------------------------
// block = (n, b); reads fp16 scores once, writes out2 row + per-head (mx, inv).
__global__ void __launch_bounds__(256)
osmax_kernel(float* __restrict__ O2) {
    const int n = blockIdx.x, b = blockIdx.y;
    const int tid = threadIdx.x, lane = tid & 31, wid = tid >> 5;
    const float pen = dec_f(g_minenc) - 20.0f;
    const unsigned char* mrow = g_mask + (size_t)n * NN;

    __shared__ float sred[8][9];

    bool km[6];
#pragma unroll
    for (int i = 0; i < 6; i++) km[i] = mrow[tid + i * 256] != 0;

    float v[8][6];
#pragma unroll
    for (int h = 0; h < 8; h++) {
        const __half* S = (const __half*)(g_s16 + ((size_t)(b * HH + h) * NN + n) * NN);
#pragma unroll
        for (int i = 0; i < 6; i++) {
            float s = __half2float(S[tid + i * 256]);
            if (!km[i]) s += pen;
            v[h][i] = s;
        }
    }

    // out2 row: mean over heads (pen folds in exactly; same for all h)
    {
        float* o2 = &O2[((size_t)b * NN + n) * NN];
#pragma unroll
        for (int i = 0; i < 6; i++) {
            float s = v[0][i] + v[1][i] + v[2][i] + v[3][i]
                    + v[4][i] + v[5][i] + v[6][i] + v[7][i];
            o2[tid + i * 256] = s * 0.125f;
        }
    }

    // per-head max
    float mx[8];
#pragma unroll
    for (int h = 0; h < 8; h++) {
        float m = v[h][0];
#pragma unroll
        for (int i = 1; i < 6; i++) m = fmaxf(m, v[h][i]);
#pragma unroll
        for (int o = 16; o > 0; o >>= 1) m = fmaxf(m, __shfl_xor_sync(0xffffffffu, m, o));
        mx[h] = m;
    }
    if (lane == 0)
#pragma unroll
        for (int h = 0; h < 8; h++) sred[h][wid] = mx[h];
    __syncthreads();
#pragma unroll
    for (int h = 0; h < 8; h++) {
        float m = sred[h][0];
#pragma unroll
        for (int w2 = 1; w2 < 8; w2++) m = fmaxf(m, sred[h][w2]);
        mx[h] = m;
    }
    __syncthreads();

    // exp + per-head sum
    float iv[8];
#pragma unroll
    for (int h = 0; h < 8; h++) {
        float s = 0.f;
#pragma unroll
        for (int i = 0; i < 6; i++) s += __expf(v[h][i] - mx[h]);
#pragma unroll
        for (int o = 16; o > 0; o >>= 1) s += __shfl_xor_sync(0xffffffffu, s, o);
        iv[h] = s;
    }
    if (lane == 0)
#pragma unroll
        for (int h = 0; h < 8; h++) sred[h][wid] = iv[h];
    __syncthreads();
    if (tid == 0) {
#pragma unroll
        for (int h = 0; h < 8; h++) {
            float s = sred[h][0];
#pragma unroll
            for (int w2 = 1; w2 < 8; w2++) s += sred[h][w2];
            g_mx[(size_t)(b * HH + h) * NN + n] = mx[h];
            g_iv[(size_t)(b * HH + h) * NN + n] = 1.0f / s;
        }
    }
}

// ---------------- PV: p computed on the fly from fp16 scores + stats ---------
__global__ void __launch_bounds__(256)
pv_kernel() {
    __shared__ u16 sPh[128][PS], sPl[128][PS], sVh[64][PS], sVl[64][PS];
    const int bh = blockIdx.y, n0 = blockIdx.x * 128;
    const int t = threadIdx.x, lane = t & 31, w = t >> 5;
    const int wm = w >> 1, wn = w & 1;
    const u16* Vh = g_vh + (size_t)bh * DH * NN;
    const u16* Vl = g_vl + (size_t)bh * DH * NN;

    const u32 baPh = (u32)__cvta_generic_to_shared(&sPh[0][0]);
    const u32 baPl = (u32)__cvta_generic_to_shared(&sPl[0][0]);
    const u32 baVh = (u32)__cvta_generic_to_shared(&sVh[0][0]);
    const u32 baVl = (u32)__cvta_generic_to_shared(&sVl[0][0]);

    const int pr = t >> 2, psv = (t & 3) * 8;
    const int rowA = n0 + pr, rowB = rowA + 64;
    const u16* SA = g_s16 + ((size_t)bh * NN + rowA) * NN;
    const u16* SB = g_s16 + ((size_t)bh * NN + rowB) * NN;
    const unsigned char* mA = g_mask + (size_t)rowA * NN;
    const unsigned char* mB = g_mask + (size_t)rowB * NN;
    const float mxA = g_mx[(size_t)bh * NN + rowA], ivA = g_iv[(size_t)bh * NN + rowA];
    const float mxB = g_mx[(size_t)bh * NN + rowB], ivB = g_iv[(size_t)bh * NN + rowB];

    uint4 psA, psB, pvh, pvl;
    uint2 pmA, pmB;
    float acc[2][4][4];
#pragma unroll
    for (int i = 0; i < 2; i++)
#pragma unroll
        for (int j = 0; j < 4; j++)
#pragma unroll
            for (int k = 0; k < 4; k++) acc[i][j][k] = 0.f;

    auto load_regs = [&](int m0c) {
        psA = *(const uint4*)&SA[m0c + psv];
        psB = *(const uint4*)&SB[m0c + psv];
        pmA = *(const uint2*)&mA[m0c + psv];
        pmB = *(const uint2*)&mB[m0c + psv];
        pvh = *(const uint4*)&Vh[(size_t)pr * NN + m0c + psv];
        pvl = *(const uint4*)&Vl[(size_t)pr * NN + m0c + psv];
    };
    auto store_smem = [&]() {
        const unsigned char* mba = (const unsigned char*)&pmA;
        const unsigned char* mbb = (const unsigned char*)&pmB;
#pragma unroll
        for (int j = 0; j < 4; j++) {
            __half2 hA = ((const __half2*)&psA)[j];
            float2 fA = __half22float2(hA);
            float p0 = mba[2 * j]     ? __expf(fA.x - mxA) * ivA : 0.f;
            float p1 = mba[2 * j + 1] ? __expf(fA.y - mxA) * ivA : 0.f;
            ((u32*)&sPh[pr][psv])[j] = (u32)b16hi(p0) | ((u32)b16hi(p1) << 16);
            ((u32*)&sPl[pr][psv])[j] = (u32)b16lo(p0) | ((u32)b16lo(p1) << 16);
            __half2 hB = ((const __half2*)&psB)[j];
            float2 fB = __half22float2(hB);
            float q0 = mbb[2 * j]     ? __expf(fB.x - mxB) * ivB : 0.f;
            float q1 = mbb[2 * j + 1] ? __expf(fB.y - mxB) * ivB : 0.f;
            ((u32*)&sPh[pr + 64][psv])[j] = (u32)b16hi(q0) | ((u32)b16hi(q1) << 16);
            ((u32*)&sPl[pr + 64][psv])[j] = (u32)b16lo(q0) | ((u32)b16lo(q1) << 16);
        }
        *(uint4*)&sVh[pr][psv] = pvh;
        *(uint4*)&sVl[pr][psv] = pvl;
    };

    load_regs(0); store_smem(); __syncthreads();
    const int NC = NN / 32;
    for (int c = 0; c < NC; c++) {
        if (c + 1 < NC) load_regs((c + 1) * 32);
        mma_step<2, PS>(acc, baPh, baPl, baVh, baVl, lane, wm * 32, wn * 32, 0);
        mma_step<2, PS>(acc, baPh, baPl, baVh, baVl, lane, wm * 32, wn * 32, 16);
        if (c + 1 < NC) { __syncthreads(); store_smem(); __syncthreads(); }
    }

    const int b = bh >> 3, h = bh & 7;
#pragma unroll
    for (int im = 0; im < 2; im++) {
        const int n = n0 + wm * 32 + im * 16 + (lane >> 2);
#pragma unroll
        for (int jn = 0; jn < 4; jn++) {
            float* cc = acc[im][jn];
            const int d  = wn * 32 + jn * 8 + 2 * (lane & 3);
            const int c0i = d * 8 + h, c1i = (d + 1) * 8 + h;
            size_t base0 = ((size_t)b * NN + n) * DD;
            size_t base1 = base0 + (size_t)8 * DD;
            g_xth[base0 + c0i] = b16hi(cc[0]);  g_xtl[base0 + c0i] = b16lo(cc[0]);
            g_xth[base0 + c1i] = b16hi(cc[1]);  g_xtl[base0 + c1i] = b16lo(cc[1]);
            g_xth[base1 + c0i] = b16hi(cc[2]);  g_xtl[base1 + c0i] = b16lo(cc[2]);
            g_xth[base1 + c1i] = b16hi(cc[3]);  g_xtl[base1 + c1i] = b16lo(cc[3]);
        }
    }
}

// ---------------- launch ------------------------------------------------------
extern "C" void kernel_launch(void* const* d_in, const int* in_sizes, int n_in,
                              void* d_out, int out_size) {
    const float* query = (const float*)d_in[0];
    const float* key   = (const float*)d_in[1];
    const float* value = (const float*)d_in[2];
    // d_in[3] = dist (unused)
    const void* mask   = d_in[4];
    const float* Wq = (const float*)d_in[5];
    const float* bq = (const float*)d_in[6];
    const float* Wk = (const float*)d_in[7];
    const float* bk = (const float*)d_in[8];
    const float* Wv = (const float*)d_in[9];
    const float* bv = (const float*)d_in[10];
    const float* Wm = (const float*)d_in[11];
    const float* bm = (const float*)d_in[12];

    float* out  = (float*)d_out;                 // [B, D, N]
    float* out2 = out + (size_t)BB * DD * NN;    // [B, N, N]

    void *pih, *pil, *pwh, *pwl, *pqh, *pql, *pkh, *pkl, *pvh, *pvl, *pxth, *pxtl;
    cudaGetSymbolAddress(&pih, g_ith);
    cudaGetSymbolAddress(&pil, g_itl);
    cudaGetSymbolAddress(&pwh, g_wh);
    cudaGetSymbolAddress(&pwl, g_wl);
    cudaGetSymbolAddress(&pqh, g_qh);
    cudaGetSymbolAddress(&pql, g_ql);
    cudaGetSymbolAddress(&pkh, g_kh);
    cudaGetSymbolAddress(&pkl, g_kl);
    cudaGetSymbolAddress(&pvh, g_vh);
    cudaGetSymbolAddress(&pvl, g_vl);
    cudaGetSymbolAddress(&pxth, g_xth);
    cudaGetSymbolAddress(&pxtl, g_xtl);

    const u16* ith = (const u16*)pih;
    const u16* itl = (const u16*)pil;
    const u16* wh  = (const u16*)pwh;
    const u16* wl  = (const u16*)pwl;
    const size_t IB = (size_t)BB * NN * DD;
    const size_t WB = (size_t)DD * DD;

    cudaFuncSetAttribute(scores_kernel,
                         cudaFuncAttributeMaxDynamicSharedMemorySize, SC_SMEM);

    init_kernel<<<1, 1>>>();
    mask_classify_kernel<<<256, 256>>>((const u32*)mask);
    mask_convert_kernel<<<256, 256>>>(mask);

    presplit_in_kernel<<<dim3(NN / 32, DD / 32, 3 * BB), dim3(32, 8)>>>(query, key, value);
    presplit_w_kernel<<<1024, 256>>>(Wq, Wk, Wv, Wm);

    dim3 gproj(NN / 128, DD / 64, BB);
    proj_kernel<1><<<gproj, 256>>>(ith + 0 * IB, itl + 0 * IB, wh + 0 * WB, wl + 0 * WB, bq, pqh, pql);
    proj_kernel<1><<<gproj, 256>>>(ith + 1 * IB, itl + 1 * IB, wh + 1 * WB, wl + 1 * WB, bk, pkh, pkl);
    proj_kernel<2><<<gproj, 256>>>(ith + 2 * IB, itl + 2 * IB, wh + 2 * WB, wl + 2 * WB, bv, pvh, pvl);

    scores_kernel<<<dim3(NN / 128, NN / 128, BB * HH), 512, SC_SMEM>>>();

    osmax_kernel<<<dim3(NN, BB), 256>>>(out2);

    pv_kernel<<<dim3(NN / 128, BB * HH), 256>>>();

    proj_kernel<0><<<gproj, 256>>>((const u16*)pxth, (const u16*)pxtl,
                                   wh + 3 * WB, wl + 3 * WB, bm, out, nullptr);
}

// round 10
// speedup vs baseline: 1.0464x; 1.0464x over previous
#include <cuda_runtime.h>
#include <cuda_bf16.h>
#include <cuda_fp16.h>
#include <cstdint>

#define BB 4
#define DD 512
#define NN 1536
#define HH 8
#define DH 64
#define PS 40   // smem row stride in halves (32 k + 8 pad -> conflict-free ldmatrix)

typedef unsigned short u16;
typedef unsigned int   u32;

// ---------------- scratch (device globals) -----------------------------------
__device__ __align__(16) u16 g_ith[(size_t)3 * BB * NN * DD];  // inputs^T hi [which][b][n][c]
__device__ __align__(16) u16 g_itl[(size_t)3 * BB * NN * DD];  // inputs^T lo
__device__ __align__(16) u16 g_wh[(size_t)4 * DD * DD];        // weights hi [which][o][c]
__device__ __align__(16) u16 g_wl[(size_t)4 * DD * DD];
__device__ __align__(16) u16 g_qh[(size_t)BB * HH * NN * DH];  // [b,h,n,d]
__device__ __align__(16) u16 g_ql[(size_t)BB * HH * NN * DH];
__device__ __align__(16) u16 g_kh[(size_t)BB * HH * NN * DH];  // [b,h,m,d]
__device__ __align__(16) u16 g_kl[(size_t)BB * HH * NN * DH];
__device__ __align__(16) u16 g_vh[(size_t)BB * HH * DH * NN];  // [b,h,d,m]
__device__ __align__(16) u16 g_vl[(size_t)BB * HH * DH * NN];
__device__ __align__(16) u16 g_s16[(size_t)BB * HH * NN * NN]; // fp16 scores [bh][n][m]
__device__ float g_mx[(size_t)BB * HH * NN];   // row max (with penalty semantics)
__device__ float g_iv[(size_t)BB * HH * NN];   // row 1/sum
__device__ __align__(16) u16 g_xth[(size_t)BB * NN * DD];      // PV out^T hi [b][n][c]
__device__ __align__(16) u16 g_xtl[(size_t)BB * NN * DD];
__device__ unsigned char g_mask[(size_t)NN * NN];
__device__ u32 g_minenc;
__device__ u32 g_maskflags;

// ---------------- helpers ----------------------------------------------------
__device__ __forceinline__ u32 enc_f(float x) {
    u32 b = __float_as_uint(x);
    return (b & 0x80000000u) ? ~b : (b | 0x80000000u);
}
__device__ __forceinline__ float dec_f(u32 e) {
    return (e & 0x80000000u) ? __uint_as_float(e ^ 0x80000000u)
                             : __uint_as_float(~e);
}
__device__ __forceinline__ u16 b16hi(float x) {
    return __bfloat16_as_ushort(__float2bfloat16(x));
}
__device__ __forceinline__ u16 b16lo(float x) {
    float hf = __bfloat162float(__float2bfloat16(x));
    return __bfloat16_as_ushort(__float2bfloat16(x - hf));
}
__device__ __forceinline__ void cp16(u32 dst, const void* src) {
    asm volatile("cp.async.ca.shared.global [%0], [%1], 16;" :: "r"(dst), "l"(src));
}
#define CP_COMMIT() asm volatile("cp.async.commit_group;" ::: "memory")
#define CP_WAIT0()  asm volatile("cp.async.wait_group 0;" ::: "memory")

__global__ void init_kernel() { g_minenc = 0xFFFFFFFFu; g_maskflags = 0u; }

// ---------------- mask dtype classification + normalization ------------------
__global__ void __launch_bounds__(256)
mask_classify_kernel(const u32* __restrict__ mw) {
    const int total = NN * NN / 4;
    u32 local = 0;
    for (int i = blockIdx.x * 256 + threadIdx.x; i < total; i += gridDim.x * 256) {
        u32 w = mw[i];
        if (w != 0u && w != 1u)          local |= 1u;
        if (w != 0u && w != 0x3f800000u) local |= 2u;
    }
#pragma unroll
    for (int o = 16; o > 0; o >>= 1) local |= __shfl_xor_sync(0xffffffffu, local, o);
    if ((threadIdx.x & 31) == 0 && local) atomicOr(&g_maskflags, local);
}

__global__ void __launch_bounds__(256)
mask_convert_kernel(const void* __restrict__ mraw) {
    const u32 f = g_maskflags;
    const int mode = ((f & 2u) == 0u) ? 2 : (((f & 1u) == 0u) ? 1 : 0);
    const int total = NN * NN;
    if (mode == 0) {
        const unsigned char* m8 = (const unsigned char*)mraw;
        for (int i = blockIdx.x * 256 + threadIdx.x; i < total; i += gridDim.x * 256)
            g_mask[i] = m8[i] ? 1 : 0;
    } else if (mode == 1) {
        const int* mi = (const int*)mraw;
        for (int i = blockIdx.x * 256 + threadIdx.x; i < total; i += gridDim.x * 256)
            g_mask[i] = mi[i] ? 1 : 0;
    } else {
        const float* mf = (const float*)mraw;
        for (int i = blockIdx.x * 256 + threadIdx.x; i < total; i += gridDim.x * 256)
            g_mask[i] = (mf[i] != 0.0f) ? 1 : 0;
    }
}

// ---------------- prepasses: split inputs/weights into bf16 planes -----------
__global__ void __launch_bounds__(256)
presplit_in_kernel(const float* __restrict__ q, const float* __restrict__ k,
                   const float* __restrict__ v) {
    __shared__ float tile[32][33];
    const int which = blockIdx.z >> 2, b = blockIdx.z & 3;
    const float* src = (which == 0 ? q : which == 1 ? k : v) + (size_t)b * DD * NN;
    const int n0 = blockIdx.x * 32, c0 = blockIdx.y * 32;
    const int tx = threadIdx.x, ty = threadIdx.y;  // 32 x 8
#pragma unroll
    for (int i = 0; i < 32; i += 8)
        tile[ty + i][tx] = src[(size_t)(c0 + ty + i) * NN + n0 + tx];
    __syncthreads();
    u16* dh = g_ith + (size_t)(which * BB + b) * NN * DD;
    u16* dl = g_itl + (size_t)(which * BB + b) * NN * DD;
#pragma unroll
    for (int i = 0; i < 32; i += 8) {
        float x = tile[tx][ty + i];
        size_t o = (size_t)(n0 + ty + i) * DD + c0 + tx;
        dh[o] = b16hi(x);
        dl[o] = b16lo(x);
    }
}

__global__ void __launch_bounds__(256)
presplit_w_kernel(const float* __restrict__ Wq, const float* __restrict__ Wk,
                  const float* __restrict__ Wv, const float* __restrict__ Wm) {
    const int total = 4 * DD * DD;
    for (int i = blockIdx.x * 256 + threadIdx.x; i < total; i += gridDim.x * 256) {
        int w = i >> 18;
        int r = i & (DD * DD - 1);
        const float* src = (w == 0 ? Wq : w == 1 ? Wk : w == 2 ? Wv : Wm);
        float x = src[r];
        g_wh[i] = b16hi(x);
        g_wl[i] = b16lo(x);
    }
}

// ---------------- mma.sync machinery -----------------------------------------
__device__ __forceinline__ void ldm4(u32& r0, u32& r1, u32& r2, u32& r3, u32 addr) {
    asm volatile("ldmatrix.sync.aligned.m8n8.x4.shared.b16 {%0,%1,%2,%3}, [%4];"
                 : "=r"(r0), "=r"(r1), "=r"(r2), "=r"(r3) : "r"(addr));
}
__device__ __forceinline__ void mma16816(float* c, u32 a0, u32 a1, u32 a2, u32 a3,
                                         u32 b0, u32 b1) {
    asm volatile("mma.sync.aligned.m16n8k16.row.col.f32.bf16.bf16.f32 "
                 "{%0,%1,%2,%3}, {%4,%5,%6,%7}, {%8,%9}, {%0,%1,%2,%3};"
                 : "+f"(c[0]), "+f"(c[1]), "+f"(c[2]), "+f"(c[3])
                 : "r"(a0), "r"(a1), "r"(a2), "r"(a3), "r"(b0), "r"(b1));
}
template <int SPS>
__device__ __forceinline__ u32 ldm_addr(u32 base, int lane, int row0, int col0) {
    int r = row0 + (lane & 7) + ((lane >> 3) & 1) * 8;
    int c = col0 + (lane >> 4) * 8;
    return base + (u32)(r * SPS + c) * 2u;
}
// One k16 step of split-bf16: acc += Ah*Bh + Ah*Bl + Al*Bh
template <int IM, int SPS>
__device__ __forceinline__ void mma_step(float (*acc)[4][4],
                                         u32 baAh, u32 baAl, u32 baBh, u32 baBl,
                                         int lane, int mBase, int nBase, int kk) {
    u32 A[IM][4], B[4][2], C[4][2];
    u32 x0, x1, x2, x3;
#pragma unroll
    for (int im = 0; im < IM; im++)
        ldm4(A[im][0], A[im][1], A[im][2], A[im][3],
             ldm_addr<SPS>(baAh, lane, mBase + im * 16, kk));
    ldm4(x0, x1, x2, x3, ldm_addr<SPS>(baBh, lane, nBase, kk));
    B[0][0] = x0; B[0][1] = x2; B[1][0] = x1; B[1][1] = x3;
    ldm4(x0, x1, x2, x3, ldm_addr<SPS>(baBh, lane, nBase + 16, kk));
    B[2][0] = x0; B[2][1] = x2; B[3][0] = x1; B[3][1] = x3;
#pragma unroll
    for (int im = 0; im < IM; im++)
#pragma unroll
        for (int jn = 0; jn < 4; jn++)
            mma16816(acc[im][jn], A[im][0], A[im][1], A[im][2], A[im][3], B[jn][0], B[jn][1]);
    ldm4(x0, x1, x2, x3, ldm_addr<SPS>(baBl, lane, nBase, kk));
    C[0][0] = x0; C[0][1] = x2; C[1][0] = x1; C[1][1] = x3;
    ldm4(x0, x1, x2, x3, ldm_addr<SPS>(baBl, lane, nBase + 16, kk));
    C[2][0] = x0; C[2][1] = x2; C[3][0] = x1; C[3][1] = x3;
#pragma unroll
    for (int im = 0; im < IM; im++)
#pragma unroll
        for (int jn = 0; jn < 4; jn++)
            mma16816(acc[im][jn], A[im][0], A[im][1], A[im][2], A[im][3], C[jn][0], C[jn][1]);
#pragma unroll
    for (int im = 0; im < IM; im++)
        ldm4(A[im][0], A[im][1], A[im][2], A[im][3],
             ldm_addr<SPS>(baAl, lane, mBase + im * 16, kk));
#pragma unroll
    for (int im = 0; im < IM; im++)
#pragma unroll
        for (int jn = 0; jn < 4; jn++)
            mma16816(acc[im][jn], A[im][0], A[im][1], A[im][2], A[im][3], B[jn][0], B[jn][1]);
}

// ---------------- projection: double-buffered, one sync per k-chunk ----------
// dyn smem per buffer: Wh 0 (5120B) | Wl 5120 | Xh 10240 (10240B) | Xl 20480
#define PJ_BUF 30720
#define PJ_SMEM (2 * PJ_BUF)
template <int MODE>
__global__ void __launch_bounds__(256)
proj_kernel(const u16* __restrict__ XTh, const u16* __restrict__ XTl,
            const u16* __restrict__ Wh, const u16* __restrict__ Wl,
            const float* __restrict__ bias, void* __restrict__ y0, void* __restrict__ y1) {
    extern __shared__ __align__(16) char pjs[];
    const int b = blockIdx.z, o0 = blockIdx.y * 64, n0 = blockIdx.x * 128;
    const int t = threadIdx.x, lane = t & 31, w = t >> 5;
    const int wm = w & 1, wn = w >> 1;
    const u16* Xh = XTh + (size_t)b * NN * DD;
    const u16* Xl = XTl + (size_t)b * NN * DD;
    const int ar = t >> 2, as = (t & 3) * 8;
    const u32 sb = (u32)__cvta_generic_to_shared(pjs);

    uint4 pa0, pa1, pbh[2], pbl[2];
    float acc[2][4][4];
#pragma unroll
    for (int i = 0; i < 2; i++)
#pragma unroll
        for (int j = 0; j < 4; j++)
#pragma unroll
            for (int k = 0; k < 4; k++) acc[i][j][k] = 0.f;

    auto load_regs = [&](int c0) {
        pa0    = *(const uint4*)&Wh[(size_t)(o0 + ar) * DD + c0 + as];
        pa1    = *(const uint4*)&Wl[(size_t)(o0 + ar) * DD + c0 + as];
        pbh[0] = *(const uint4*)&Xh[(size_t)(n0 + ar) * DD + c0 + as];
        pbl[0] = *(const uint4*)&Xl[(size_t)(n0 + ar) * DD + c0 + as];
        pbh[1] = *(const uint4*)&Xh[(size_t)(n0 + ar + 64) * DD + c0 + as];
        pbl[1] = *(const uint4*)&Xl[(size_t)(n0 + ar + 64) * DD + c0 + as];
    };
    auto store_smem = [&](int buf) {
        char* base = pjs + buf * PJ_BUF;
        const int ro = (ar * PS + as) * 2;
        const int r1 = ((ar + 64) * PS + as) * 2;
        *(uint4*)(base + ro)             = pa0;
        *(uint4*)(base + 5120 + ro)      = pa1;
        *(uint4*)(base + 10240 + ro)     = pbh[0];
        *(uint4*)(base + 20480 + ro)     = pbl[0];
        *(uint4*)(base + 10240 + r1)     = pbh[1];
        *(uint4*)(base + 20480 + r1)     = pbl[1];
    };

    load_regs(0); store_smem(0); load_regs(32);
    __syncthreads();
    const int NC = DD / 32;  // 16
    for (int c = 0; c < NC; c++) {
        const int cur = c & 1;
        if (c + 1 < NC) store_smem(cur ^ 1);
        if (c + 2 < NC) load_regs((c + 2) * 32);
        const u32 bb = sb + cur * PJ_BUF;
        mma_step<2, PS>(acc, bb, bb + 5120, bb + 10240, bb + 20480, lane, wm * 32, wn * 32, 0);
        mma_step<2, PS>(acc, bb, bb + 5120, bb + 10240, bb + 20480, lane, wm * 32, wn * 32, 16);
        __syncthreads();
    }

#pragma unroll
    for (int im = 0; im < 2; im++) {
        const int ob = o0 + wm * 32 + im * 16 + (lane >> 2);
        const float bs0 = bias[ob], bs1 = bias[ob + 8];
#pragma unroll
        for (int jn = 0; jn < 4; jn++) {
            float* cc = acc[im][jn];
            const int n = n0 + wn * 32 + jn * 8 + 2 * (lane & 3);
            const float v0 = cc[0] + bs0, v1 = cc[1] + bs0;
            const float v2 = cc[2] + bs1, v3 = cc[3] + bs1;
            if (MODE == 0) {
                float* Y = (float*)y0;
                *(float2*)&Y[((size_t)b * DD + ob) * NN + n]     = make_float2(v0, v1);
                *(float2*)&Y[((size_t)b * DD + ob + 8) * NN + n] = make_float2(v2, v3);
            } else if (MODE == 1) {
                u32* Yh = (u32*)y0;
                u32* Yl = (u32*)y1;
                const int h = ob & 7, d = ob >> 3;
                size_t i0 = (((size_t)(b * HH + h) * NN + n) * DH + d) >> 1;
                Yh[i0]      = (u32)b16hi(v0) | ((u32)b16hi(v2) << 16);
                Yl[i0]      = (u32)b16lo(v0) | ((u32)b16lo(v2) << 16);
                Yh[i0 + 32] = (u32)b16hi(v1) | ((u32)b16hi(v3) << 16);
                Yl[i0 + 32] = (u32)b16lo(v1) | ((u32)b16lo(v3) << 16);
            } else {
                u32* Yh = (u32*)y0;
                u32* Yl = (u32*)y1;
                const int h = ob & 7, d = ob >> 3;
                size_t i0 = (((size_t)(b * HH + h) * DH + d) * NN + n) >> 1;
                Yh[i0] = (u32)b16hi(v0) | ((u32)b16hi(v1) << 16);
                Yl[i0] = (u32)b16lo(v0) | ((u32)b16lo(v1) << 16);
                size_t i1 = i0 + (NN >> 1);
                Yh[i1] = (u32)b16hi(v2) | ((u32)b16hi(v3) << 16);
                Yl[i1] = (u32)b16lo(v2) | ((u32)b16lo(v3) << 16);
            }
        }
    }
}

// ---------------- scores: single k-chunk of 64, cp.async fill, fp16 out ------
#define PS2 72
#define SC_PLANE (128 * PS2 * 2)              // 18432 B
#define SC_SMEM  (4 * SC_PLANE)               // 73728 B
__global__ void __launch_bounds__(512)
scores_kernel() {
    extern __shared__ __align__(16) char dsm[];
    __shared__ float sred[16];
    const int bh = blockIdx.z, n0 = blockIdx.y * 128, m0 = blockIdx.x * 128;
    const int t = threadIdx.x, lane = t & 31, w = t >> 5;
    const int wm = w & 3, wn = w >> 2;   // warp tile 32(n) x 32(m)
    const u16* Qh = g_qh + (size_t)bh * NN * DH;
    const u16* Ql = g_ql + (size_t)bh * NN * DH;
    const u16* Kh = g_kh + (size_t)bh * NN * DH;
    const u16* Kl = g_kl + (size_t)bh * NN * DH;

    const u32 sbase = (u32)__cvta_generic_to_shared(dsm);
    const u32 baQh = sbase, baQl = sbase + SC_PLANE;
    const u32 baKh = sbase + 2 * SC_PLANE, baKl = sbase + 3 * SC_PLANE;

#pragma unroll
    for (int rep = 0; rep < 2; rep++) {
        const int idx = t + rep * 512;
        const int row = idx >> 3, c8 = (idx & 7) * 8;
        const u32 off = (u32)(row * PS2 + c8) * 2u;
        cp16(baQh + off, &Qh[(size_t)(n0 + row) * DH + c8]);
        cp16(baQl + off, &Ql[(size_t)(n0 + row) * DH + c8]);
        cp16(baKh + off, &Kh[(size_t)(m0 + row) * DH + c8]);
        cp16(baKl + off, &Kl[(size_t)(m0 + row) * DH + c8]);
    }
    CP_COMMIT();
    CP_WAIT0();
    __syncthreads();

    float acc[2][4][4];
#pragma unroll
    for (int i = 0; i < 2; i++)
#pragma unroll
        for (int j = 0; j < 4; j++)
#pragma unroll
            for (int k = 0; k < 4; k++) acc[i][j][k] = 0.f;

#pragma unroll
    for (int kk = 0; kk < 64; kk += 16)
        mma_step<2, PS2>(acc, baQh, baQl, baKh, baKl, lane, wm * 32, wn * 32, kk);

    float mn = __int_as_float(0x7f800000);
#pragma unroll
    for (int im = 0; im < 2; im++) {
        const int n = n0 + wm * 32 + im * 16 + (lane >> 2);
#pragma unroll
        for (int jn = 0; jn < 4; jn++) {
            float* cc = acc[im][jn];
            const int m = m0 + wn * 32 + jn * 8 + 2 * (lane & 3);
            float2 r0 = make_float2(cc[0] * 0.125f, cc[1] * 0.125f);
            float2 r1 = make_float2(cc[2] * 0.125f, cc[3] * 0.125f);
            mn = fminf(mn, fminf(fminf(r0.x, r0.y), fminf(r1.x, r1.y)));
            __half2 h0 = __floats2half2_rn(r0.x, r0.y);
            __half2 h1 = __floats2half2_rn(r1.x, r1.y);
            *(u32*)&g_s16[((size_t)bh * NN + n) * NN + m]     = *(u32*)&h0;
            *(u32*)&g_s16[((size_t)bh * NN + n + 8) * NN + m] = *(u32*)&h1;
        }
    }
#pragma unroll
    for (int o = 16; o > 0; o >>= 1) mn = fminf(mn, __shfl_xor_sync(0xffffffffu, mn, o));
    if (lane == 0) sred[w] = mn;
    __syncthreads();
    if (t == 0) {
        float v = sred[0];
#pragma unroll
        for (int i = 1; i < 16; i++) v = fminf(v, sred[i]);
        atomicMin(&g_minenc, enc_f(v));
    }
}

// ---------------- fused out2 + softmax stats ---------------------------------
__global__ void __launch_bounds__(256)
osmax_kernel(float* __restrict__ O2) {
    const int n = blockIdx.x, b = blockIdx.y;
    const int tid = threadIdx.x, lane = tid & 31, wid = tid >> 5;
    const float pen = dec_f(g_minenc) - 20.0f;
    const unsigned char* mrow = g_mask + (size_t)n * NN;

    __shared__ float sred[8][9];

    bool km[6];
#pragma unroll
    for (int i = 0; i < 6; i++) km[i] = mrow[tid + i * 256] != 0;

    float v[8][6];
#pragma unroll
    for (int h = 0; h < 8; h++) {
        const __half* S = (const __half*)(g_s16 + ((size_t)(b * HH + h) * NN + n) * NN);
#pragma unroll
        for (int i = 0; i < 6; i++) {
            float s = __half2float(S[tid + i * 256]);
            if (!km[i]) s += pen;
            v[h][i] = s;
        }
    }

    {
        float* o2 = &O2[((size_t)b * NN + n) * NN];
#pragma unroll
        for (int i = 0; i < 6; i++) {
            float s = v[0][i] + v[1][i] + v[2][i] + v[3][i]
                    + v[4][i] + v[5][i] + v[6][i] + v[7][i];
            o2[tid + i * 256] = s * 0.125f;
        }
    }

    float mx[8];
#pragma unroll
    for (int h = 0; h < 8; h++) {
        float m = v[h][0];
#pragma unroll
        for (int i = 1; i < 6; i++) m = fmaxf(m, v[h][i]);
#pragma unroll
        for (int o = 16; o > 0; o >>= 1) m = fmaxf(m, __shfl_xor_sync(0xffffffffu, m, o));
        mx[h] = m;
    }
    if (lane == 0)
#pragma unroll
        for (int h = 0; h < 8; h++) sred[h][wid] = mx[h];
    __syncthreads();
#pragma unroll
    for (int h = 0; h < 8; h++) {
        float m = sred[h][0];
#pragma unroll
        for (int w2 = 1; w2 < 8; w2++) m = fmaxf(m, sred[h][w2]);
        mx[h] = m;
    }
    __syncthreads();

    float iv[8];
#pragma unroll
    for (int h = 0; h < 8; h++) {
        float s = 0.f;
#pragma unroll
        for (int i = 0; i < 6; i++) s += __expf(v[h][i] - mx[h]);
#pragma unroll
        for (int o = 16; o > 0; o >>= 1) s += __shfl_xor_sync(0xffffffffu, s, o);
        iv[h] = s;
    }
    if (lane == 0)
#pragma unroll
        for (int h = 0; h < 8; h++) sred[h][wid] = iv[h];
    __syncthreads();
    if (tid == 0) {
#pragma unroll
        for (int h = 0; h < 8; h++) {
            float s = sred[h][0];
#pragma unroll
            for (int w2 = 1; w2 < 8; w2++) s += sred[h][w2];
            g_mx[(size_t)(b * HH + h) * NN + n] = mx[h];
            g_iv[(size_t)(b * HH + h) * NN + n] = 1.0f / s;
        }
    }
}

// ---------------- PV: double-buffered; p computed on the fly -----------------
// dyn smem per buffer: Ph 0 (10240B) | Pl 10240 | Vh 20480 (5120B) | Vl 25600
#define PV_BUF 30720
#define PV_SMEM (2 * PV_BUF)
__global__ void __launch_bounds__(256)
pv_kernel() {
    extern __shared__ __align__(16) char pvs[];
    const int bh = blockIdx.y, n0 = blockIdx.x * 128;
    const int t = threadIdx.x, lane = t & 31, w = t >> 5;
    const int wm = w >> 1, wn = w & 1;
    const u16* Vh = g_vh + (size_t)bh * DH * NN;
    const u16* Vl = g_vl + (size_t)bh * DH * NN;
    const u32 sb = (u32)__cvta_generic_to_shared(pvs);

    const int pr = t >> 2, psv = (t & 3) * 8;
    const int rowA = n0 + pr, rowB = rowA + 64;
    const u16* SA = g_s16 + ((size_t)bh * NN + rowA) * NN;
    const u16* SB = g_s16 + ((size_t)bh * NN + rowB) * NN;
    const unsigned char* mA = g_mask + (size_t)rowA * NN;
    const unsigned char* mB = g_mask + (size_t)rowB * NN;
    const float mxA = g_mx[(size_t)bh * NN + rowA], ivA = g_iv[(size_t)bh * NN + rowA];
    const float mxB = g_mx[(size_t)bh * NN + rowB], ivB = g_iv[(size_t)bh * NN + rowB];

    uint4 psA, psB, pvh, pvl;
    uint2 pmA, pmB;
    float acc[2][4][4];
#pragma unroll
    for (int i = 0; i < 2; i++)
#pragma unroll
        for (int j = 0; j < 4; j++)
#pragma unroll
            for (int k = 0; k < 4; k++) acc[i][j][k] = 0.f;

    auto load_regs = [&](int m0c) {
        psA = *(const uint4*)&SA[m0c + psv];
        psB = *(const uint4*)&SB[m0c + psv];
        pmA = *(const uint2*)&mA[m0c + psv];
        pmB = *(const uint2*)&mB[m0c + psv];
        pvh = *(const uint4*)&Vh[(size_t)pr * NN + m0c + psv];
        pvl = *(const uint4*)&Vl[(size_t)pr * NN + m0c + psv];
    };
    auto store_smem = [&](int buf) {
        char* base = pvs + buf * PV_BUF;
        const int roA = (pr * PS + psv) * 2;
        const int roB = ((pr + 64) * PS + psv) * 2;
        const unsigned char* mba = (const unsigned char*)&pmA;
        const unsigned char* mbb = (const unsigned char*)&pmB;
#pragma unroll
        for (int j = 0; j < 4; j++) {
            __half2 hA = ((const __half2*)&psA)[j];
            float2 fA = __half22float2(hA);
            float p0 = mba[2 * j]     ? __expf(fA.x - mxA) * ivA : 0.f;
            float p1 = mba[2 * j + 1] ? __expf(fA.y - mxA) * ivA : 0.f;
            ((u32*)(base + roA))[j]          = (u32)b16hi(p0) | ((u32)b16hi(p1) << 16);
            ((u32*)(base + 10240 + roA))[j]  = (u32)b16lo(p0) | ((u32)b16lo(p1) << 16);
            __half2 hB = ((const __half2*)&psB)[j];
            float2 fB = __half22float2(hB);
            float q0 = mbb[2 * j]     ? __expf(fB.x - mxB) * ivB : 0.f;
            float q1 = mbb[2 * j + 1] ? __expf(fB.y - mxB) * ivB : 0.f;
            ((u32*)(base + roB))[j]          = (u32)b16hi(q0) | ((u32)b16hi(q1) << 16);
            ((u32*)(base + 10240 + roB))[j]  = (u32)b16lo(q0) | ((u32)b16lo(q1) << 16);
        }
        const int roV = (pr * PS + psv) * 2;
        *(uint4*)(base + 20480 + roV) = pvh;
        *(uint4*)(base + 25600 + roV) = pvl;
    };

    load_regs(0); store_smem(0); load_regs(32);
    __syncthreads();
    const int NC = NN / 32;  // 48
    for (int c = 0; c < NC; c++) {
        const int cur = c & 1;
        if (c + 1 < NC) store_smem(cur ^ 1);
        if (c + 2 < NC) load_regs((c + 2) * 32);
        const u32 bb = sb + cur * PV_BUF;
        mma_step<2, PS>(acc, bb, bb + 10240, bb + 20480, bb + 25600, lane, wm * 32, wn * 32, 0);
        mma_step<2, PS>(acc, bb, bb + 10240, bb + 20480, bb + 25600, lane, wm * 32, wn * 32, 16);
        __syncthreads();
    }

    const int b = bh >> 3, h = bh & 7;
#pragma unroll
    for (int im = 0; im < 2; im++) {
        const int n = n0 + wm * 32 + im * 16 + (lane >> 2);
#pragma unroll
        for (int jn = 0; jn < 4; jn++) {
            float* cc = acc[im][jn];
            const int d  = wn * 32 + jn * 8 + 2 * (lane & 3);
            const int c0i = d * 8 + h, c1i = (d + 1) * 8 + h;
            size_t base0 = ((size_t)b * NN + n) * DD;
            size_t base1 = base0 + (size_t)8 * DD;
            g_xth[base0 + c0i] = b16hi(cc[0]);  g_xtl[base0 + c0i] = b16lo(cc[0]);
            g_xth[base0 + c1i] = b16hi(cc[1]);  g_xtl[base0 + c1i] = b16lo(cc[1]);
            g_xth[base1 + c0i] = b16hi(cc[2]);  g_xtl[base1 + c0i] = b16lo(cc[2]);
            g_xth[base1 + c1i] = b16hi(cc[3]);  g_xtl[base1 + c1i] = b16lo(cc[3]);
        }
    }
}

// ---------------- launch ------------------------------------------------------
extern "C" void kernel_launch(void* const* d_in, const int* in_sizes, int n_in,
                              void* d_out, int out_size) {
    const float* query = (const float*)d_in[0];
    const float* key   = (const float*)d_in[1];
    const float* value = (const float*)d_in[2];
    // d_in[3] = dist (unused)
    const void* mask   = d_in[4];
    const float* Wq = (const float*)d_in[5];
    const float* bq = (const float*)d_in[6];
    const float* Wk = (const float*)d_in[7];
    const float* bk = (const float*)d_in[8];
    const float* Wv = (const float*)d_in[9];
    const float* bv = (const float*)d_in[10];
    const float* Wm = (const float*)d_in[11];
    const float* bm = (const float*)d_in[12];

    float* out  = (float*)d_out;                 // [B, D, N]
    float* out2 = out + (size_t)BB * DD * NN;    // [B, N, N]

    void *pih, *pil, *pwh, *pwl, *pqh, *pql, *pkh, *pkl, *pvh, *pvl, *pxth, *pxtl;
    cudaGetSymbolAddress(&pih, g_ith);
    cudaGetSymbolAddress(&pil, g_itl);
    cudaGetSymbolAddress(&pwh, g_wh);
    cudaGetSymbolAddress(&pwl, g_wl);
    cudaGetSymbolAddress(&pqh, g_qh);
    cudaGetSymbolAddress(&pql, g_ql);
    cudaGetSymbolAddress(&pkh, g_kh);
    cudaGetSymbolAddress(&pkl, g_kl);
    cudaGetSymbolAddress(&pvh, g_vh);
    cudaGetSymbolAddress(&pvl, g_vl);
    cudaGetSymbolAddress(&pxth, g_xth);
    cudaGetSymbolAddress(&pxtl, g_xtl);

    const u16* ith = (const u16*)pih;
    const u16* itl = (const u16*)pil;
    const u16* wh  = (const u16*)pwh;
    const u16* wl  = (const u16*)pwl;
    const size_t IB = (size_t)BB * NN * DD;
    const size_t WB = (size_t)DD * DD;

    cudaFuncSetAttribute(scores_kernel,
                         cudaFuncAttributeMaxDynamicSharedMemorySize, SC_SMEM);
    cudaFuncSetAttribute(proj_kernel<0>,
                         cudaFuncAttributeMaxDynamicSharedMemorySize, PJ_SMEM);
    cudaFuncSetAttribute(proj_kernel<1>,
                         cudaFuncAttributeMaxDynamicSharedMemorySize, PJ_SMEM);
    cudaFuncSetAttribute(proj_kernel<2>,
                         cudaFuncAttributeMaxDynamicSharedMemorySize, PJ_SMEM);
    cudaFuncSetAttribute(pv_kernel,
                         cudaFuncAttributeMaxDynamicSharedMemorySize, PV_SMEM);

    init_kernel<<<1, 1>>>();
    mask_classify_kernel<<<256, 256>>>((const u32*)mask);
    mask_convert_kernel<<<256, 256>>>(mask);

    presplit_in_kernel<<<dim3(NN / 32, DD / 32, 3 * BB), dim3(32, 8)>>>(query, key, value);
    presplit_w_kernel<<<1024, 256>>>(Wq, Wk, Wv, Wm);

    dim3 gproj(NN / 128, DD / 64, BB);
    proj_kernel<1><<<gproj, 256, PJ_SMEM>>>(ith + 0 * IB, itl + 0 * IB, wh + 0 * WB, wl + 0 * WB, bq, pqh, pql);
    proj_kernel<1><<<gproj, 256, PJ_SMEM>>>(ith + 1 * IB, itl + 1 * IB, wh + 1 * WB, wl + 1 * WB, bk, pkh, pkl);
    proj_kernel<2><<<gproj, 256, PJ_SMEM>>>(ith + 2 * IB, itl + 2 * IB, wh + 2 * WB, wl + 2 * WB, bv, pvh, pvl);

    scores_kernel<<<dim3(NN / 128, NN / 128, BB * HH), 512, SC_SMEM>>>();

    osmax_kernel<<<dim3(NN, BB), 256>>>(out2);

    pv_kernel<<<dim3(NN / 128, BB * HH), 256, PV_SMEM>>>();

    proj_kernel<0><<<gproj, 256, PJ_SMEM>>>((const u16*)pxth, (const u16*)pxtl,
                                            wh + 3 * WB, wl + 3 * WB, bm, out, nullptr);
}

// round 11
// speedup vs baseline: 1.0938x; 1.0453x over previous
#include <cuda_runtime.h>
#include <cuda_bf16.h>
#include <cuda_fp16.h>
#include <cstdint>

#define BB 4
#define DD 512
#define NN 1536
#define HH 8
#define DH 64
#define PS 40   // smem row stride in halves (32 k + 8 pad -> conflict-free ldmatrix)

typedef unsigned short u16;
typedef unsigned int   u32;

// ---------------- scratch (device globals) -----------------------------------
__device__ __align__(16) u16 g_ith[(size_t)3 * BB * NN * DD];  // inputs^T hi [which][b][n][c]
__device__ __align__(16) u16 g_itl[(size_t)3 * BB * NN * DD];  // inputs^T lo
__device__ __align__(16) u16 g_wh[(size_t)4 * DD * DD];        // weights hi [which][o][c]
__device__ __align__(16) u16 g_wl[(size_t)4 * DD * DD];
__device__ __align__(16) u16 g_qh[(size_t)BB * HH * NN * DH];  // [b,h,n,d]
__device__ __align__(16) u16 g_ql[(size_t)BB * HH * NN * DH];
__device__ __align__(16) u16 g_kh[(size_t)BB * HH * NN * DH];  // [b,h,m,d]
__device__ __align__(16) u16 g_kl[(size_t)BB * HH * NN * DH];
__device__ __align__(16) u16 g_vh[(size_t)BB * HH * DH * NN];  // [b,h,d,m]
__device__ __align__(16) u16 g_vl[(size_t)BB * HH * DH * NN];
__device__ __align__(16) u16 g_s16[(size_t)BB * HH * NN * NN]; // fp16 scores [bh][n][m]
__device__ float g_mx[(size_t)BB * HH * NN];   // row max (unmasked)
__device__ float g_iv[(size_t)BB * HH * NN];   // row 1/sum
__device__ __align__(16) u16 g_xth[(size_t)BB * NN * DD];      // PV out^T hi [b][n][c]
__device__ __align__(16) u16 g_xtl[(size_t)BB * NN * DD];
__device__ __align__(16) unsigned char g_mask[(size_t)NN * NN];
__device__ u32 g_minenc;
__device__ u32 g_maskflags;

// ---------------- helpers ----------------------------------------------------
__device__ __forceinline__ u32 enc_f(float x) {
    u32 b = __float_as_uint(x);
    return (b & 0x80000000u) ? ~b : (b | 0x80000000u);
}
__device__ __forceinline__ float dec_f(u32 e) {
    return (e & 0x80000000u) ? __uint_as_float(e ^ 0x80000000u)
                             : __uint_as_float(~e);
}
__device__ __forceinline__ u16 b16hi(float x) {
    return __bfloat16_as_ushort(__float2bfloat16(x));
}
__device__ __forceinline__ u16 b16lo(float x) {
    float hf = __bfloat162float(__float2bfloat16(x));
    return __bfloat16_as_ushort(__float2bfloat16(x - hf));
}
__device__ __forceinline__ void cp16(u32 dst, const void* src) {
    asm volatile("cp.async.ca.shared.global [%0], [%1], 16;" :: "r"(dst), "l"(src));
}
#define CP_COMMIT() asm volatile("cp.async.commit_group;" ::: "memory")
#define CP_WAIT0()  asm volatile("cp.async.wait_group 0;" ::: "memory")

__global__ void init_kernel() { g_minenc = 0xFFFFFFFFu; g_maskflags = 0u; }

// ---------------- mask dtype classification + normalization ------------------
__global__ void __launch_bounds__(256)
mask_classify_kernel(const u32* __restrict__ mw) {
    const int total = NN * NN / 4;
    u32 local = 0;
    for (int i = blockIdx.x * 256 + threadIdx.x; i < total; i += gridDim.x * 256) {
        u32 w = mw[i];
        if (w != 0u && w != 1u)          local |= 1u;
        if (w != 0u && w != 0x3f800000u) local |= 2u;
    }
#pragma unroll
    for (int o = 16; o > 0; o >>= 1) local |= __shfl_xor_sync(0xffffffffu, local, o);
    if ((threadIdx.x & 31) == 0 && local) atomicOr(&g_maskflags, local);
}

__global__ void __launch_bounds__(256)
mask_convert_kernel(const void* __restrict__ mraw) {
    const u32 f = g_maskflags;
    const int mode = ((f & 2u) == 0u) ? 2 : (((f & 1u) == 0u) ? 1 : 0);
    const int total = NN * NN;
    if (mode == 0) {
        const unsigned char* m8 = (const unsigned char*)mraw;
        for (int i = blockIdx.x * 256 + threadIdx.x; i < total; i += gridDim.x * 256)
            g_mask[i] = m8[i] ? 1 : 0;
    } else if (mode == 1) {
        const int* mi = (const int*)mraw;
        for (int i = blockIdx.x * 256 + threadIdx.x; i < total; i += gridDim.x * 256)
            g_mask[i] = mi[i] ? 1 : 0;
    } else {
        const float* mf = (const float*)mraw;
        for (int i = blockIdx.x * 256 + threadIdx.x; i < total; i += gridDim.x * 256)
            g_mask[i] = (mf[i] != 0.0f) ? 1 : 0;
    }
}

// ---------------- prepasses: split inputs/weights into bf16 planes -----------
__global__ void __launch_bounds__(256)
presplit_in_kernel(const float* __restrict__ q, const float* __restrict__ k,
                   const float* __restrict__ v) {
    __shared__ float tile[32][33];
    const int which = blockIdx.z >> 2, b = blockIdx.z & 3;
    const float* src = (which == 0 ? q : which == 1 ? k : v) + (size_t)b * DD * NN;
    const int n0 = blockIdx.x * 32, c0 = blockIdx.y * 32;
    const int tx = threadIdx.x, ty = threadIdx.y;  // 32 x 8
#pragma unroll
    for (int i = 0; i < 32; i += 8)
        tile[ty + i][tx] = src[(size_t)(c0 + ty + i) * NN + n0 + tx];
    __syncthreads();
    u16* dh = g_ith + (size_t)(which * BB + b) * NN * DD;
    u16* dl = g_itl + (size_t)(which * BB + b) * NN * DD;
#pragma unroll
    for (int i = 0; i < 32; i += 8) {
        float x = tile[tx][ty + i];
        size_t o = (size_t)(n0 + ty + i) * DD + c0 + tx;
        dh[o] = b16hi(x);
        dl[o] = b16lo(x);
    }
}

__global__ void __launch_bounds__(256)
presplit_w_kernel(const float* __restrict__ Wq, const float* __restrict__ Wk,
                  const float* __restrict__ Wv, const float* __restrict__ Wm) {
    const int total = 4 * DD * DD;
    for (int i = blockIdx.x * 256 + threadIdx.x; i < total; i += gridDim.x * 256) {
        int w = i >> 18;
        int r = i & (DD * DD - 1);
        const float* src = (w == 0 ? Wq : w == 1 ? Wk : w == 2 ? Wv : Wm);
        float x = src[r];
        g_wh[i] = b16hi(x);
        g_wl[i] = b16lo(x);
    }
}

// ---------------- mma.sync machinery -----------------------------------------
__device__ __forceinline__ void ldm4(u32& r0, u32& r1, u32& r2, u32& r3, u32 addr) {
    asm volatile("ldmatrix.sync.aligned.m8n8.x4.shared.b16 {%0,%1,%2,%3}, [%4];"
                 : "=r"(r0), "=r"(r1), "=r"(r2), "=r"(r3) : "r"(addr));
}
__device__ __forceinline__ void mma16816(float* c, u32 a0, u32 a1, u32 a2, u32 a3,
                                         u32 b0, u32 b1) {
    asm volatile("mma.sync.aligned.m16n8k16.row.col.f32.bf16.bf16.f32 "
                 "{%0,%1,%2,%3}, {%4,%5,%6,%7}, {%8,%9}, {%0,%1,%2,%3};"
                 : "+f"(c[0]), "+f"(c[1]), "+f"(c[2]), "+f"(c[3])
                 : "r"(a0), "r"(a1), "r"(a2), "r"(a3), "r"(b0), "r"(b1));
}
template <int SPS>
__device__ __forceinline__ u32 ldm_addr(u32 base, int lane, int row0, int col0) {
    int r = row0 + (lane & 7) + ((lane >> 3) & 1) * 8;
    int c = col0 + (lane >> 4) * 8;
    return base + (u32)(r * SPS + c) * 2u;
}
// One k16 step of split-bf16: acc += Ah*Bh + Ah*Bl + Al*Bh
template <int IM, int SPS>
__device__ __forceinline__ void mma_step(float (*acc)[4][4],
                                         u32 baAh, u32 baAl, u32 baBh, u32 baBl,
                                         int lane, int mBase, int nBase, int kk) {
    u32 A[IM][4], B[4][2], C[4][2];
    u32 x0, x1, x2, x3;
#pragma unroll
    for (int im = 0; im < IM; im++)
        ldm4(A[im][0], A[im][1], A[im][2], A[im][3],
             ldm_addr<SPS>(baAh, lane, mBase + im * 16, kk));
    ldm4(x0, x1, x2, x3, ldm_addr<SPS>(baBh, lane, nBase, kk));
    B[0][0] = x0; B[0][1] = x2; B[1][0] = x1; B[1][1] = x3;
    ldm4(x0, x1, x2, x3, ldm_addr<SPS>(baBh, lane, nBase + 16, kk));
    B[2][0] = x0; B[2][1] = x2; B[3][0] = x1; B[3][1] = x3;
#pragma unroll
    for (int im = 0; im < IM; im++)
#pragma unroll
        for (int jn = 0; jn < 4; jn++)
            mma16816(acc[im][jn], A[im][0], A[im][1], A[im][2], A[im][3], B[jn][0], B[jn][1]);
    ldm4(x0, x1, x2, x3, ldm_addr<SPS>(baBl, lane, nBase, kk));
    C[0][0] = x0; C[0][1] = x2; C[1][0] = x1; C[1][1] = x3;
    ldm4(x0, x1, x2, x3, ldm_addr<SPS>(baBl, lane, nBase + 16, kk));
    C[2][0] = x0; C[2][1] = x2; C[3][0] = x1; C[3][1] = x3;
#pragma unroll
    for (int im = 0; im < IM; im++)
#pragma unroll
        for (int jn = 0; jn < 4; jn++)
            mma16816(acc[im][jn], A[im][0], A[im][1], A[im][2], A[im][3], C[jn][0], C[jn][1]);
#pragma unroll
    for (int im = 0; im < IM; im++)
        ldm4(A[im][0], A[im][1], A[im][2], A[im][3],
             ldm_addr<SPS>(baAl, lane, mBase + im * 16, kk));
#pragma unroll
    for (int im = 0; im < IM; im++)
#pragma unroll
        for (int jn = 0; jn < 4; jn++)
            mma16816(acc[im][jn], A[im][0], A[im][1], A[im][2], A[im][3], B[jn][0], B[jn][1]);
}

// ---------------- merged QKV projection (one launch, which = z>>2) -----------
// dyn smem per buffer: Wh 0 (5120B) | Wl 5120 | Xh 10240 (10240B) | Xl 20480
#define PJ_BUF 30720
#define PJ_SMEM (2 * PJ_BUF)
__global__ void __launch_bounds__(256)
projqkv_kernel(const u16* __restrict__ ITh, const u16* __restrict__ ITl,
               const u16* __restrict__ WHp, const u16* __restrict__ WLp,
               const float* __restrict__ bq, const float* __restrict__ bk,
               const float* __restrict__ bv,
               u32* __restrict__ qh, u32* __restrict__ ql,
               u32* __restrict__ kh, u32* __restrict__ kl,
               u32* __restrict__ vh, u32* __restrict__ vl) {
    extern __shared__ __align__(16) char pjs[];
    const int z = blockIdx.z, which = z >> 2, b = z & 3;
    const int o0 = blockIdx.y * 64, n0 = blockIdx.x * 128;
    const int t = threadIdx.x, lane = t & 31, w = t >> 5;
    const int wm = w & 1, wn = w >> 1;
    const u16* Xh = ITh + (size_t)(which * BB + b) * NN * DD;
    const u16* Xl = ITl + (size_t)(which * BB + b) * NN * DD;
    const u16* Wh = WHp + (size_t)which * DD * DD;
    const u16* Wl = WLp + (size_t)which * DD * DD;
    const float* bias = (which == 0) ? bq : (which == 1) ? bk : bv;
    const int ar = t >> 2, as = (t & 3) * 8;
    const u32 sb = (u32)__cvta_generic_to_shared(pjs);

    uint4 pa0, pa1, pbh[2], pbl[2];
    float acc[2][4][4];
#pragma unroll
    for (int i = 0; i < 2; i++)
#pragma unroll
        for (int j = 0; j < 4; j++)
#pragma unroll
            for (int k = 0; k < 4; k++) acc[i][j][k] = 0.f;

    auto load_regs = [&](int c0) {
        pa0    = *(const uint4*)&Wh[(size_t)(o0 + ar) * DD + c0 + as];
        pa1    = *(const uint4*)&Wl[(size_t)(o0 + ar) * DD + c0 + as];
        pbh[0] = *(const uint4*)&Xh[(size_t)(n0 + ar) * DD + c0 + as];
        pbl[0] = *(const uint4*)&Xl[(size_t)(n0 + ar) * DD + c0 + as];
        pbh[1] = *(const uint4*)&Xh[(size_t)(n0 + ar + 64) * DD + c0 + as];
        pbl[1] = *(const uint4*)&Xl[(size_t)(n0 + ar + 64) * DD + c0 + as];
    };
    auto store_smem = [&](int buf) {
        char* base = pjs + buf * PJ_BUF;
        const int ro = (ar * PS + as) * 2;
        const int r1 = ((ar + 64) * PS + as) * 2;
        *(uint4*)(base + ro)             = pa0;
        *(uint4*)(base + 5120 + ro)      = pa1;
        *(uint4*)(base + 10240 + ro)     = pbh[0];
        *(uint4*)(base + 20480 + ro)     = pbl[0];
        *(uint4*)(base + 10240 + r1)     = pbh[1];
        *(uint4*)(base + 20480 + r1)     = pbl[1];
    };

    load_regs(0); store_smem(0); load_regs(32);
    __syncthreads();
    const int NC = DD / 32;  // 16
    for (int c = 0; c < NC; c++) {
        const int cur = c & 1;
        if (c + 1 < NC) store_smem(cur ^ 1);
        if (c + 2 < NC) load_regs((c + 2) * 32);
        const u32 bb = sb + cur * PJ_BUF;
        mma_step<2, PS>(acc, bb, bb + 5120, bb + 10240, bb + 20480, lane, wm * 32, wn * 32, 0);
        mma_step<2, PS>(acc, bb, bb + 5120, bb + 10240, bb + 20480, lane, wm * 32, wn * 32, 16);
        __syncthreads();
    }

    u32* Yh = (which == 0) ? qh : (which == 1) ? kh : vh;
    u32* Yl = (which == 0) ? ql : (which == 1) ? kl : vl;
#pragma unroll
    for (int im = 0; im < 2; im++) {
        const int ob = o0 + wm * 32 + im * 16 + (lane >> 2);
        const float bs0 = bias[ob], bs1 = bias[ob + 8];
#pragma unroll
        for (int jn = 0; jn < 4; jn++) {
            float* cc = acc[im][jn];
            const int n = n0 + wn * 32 + jn * 8 + 2 * (lane & 3);
            const float v0 = cc[0] + bs0, v1 = cc[1] + bs0;
            const float v2 = cc[2] + bs1, v3 = cc[3] + bs1;
            if (which < 2) {
                // Q/K planes [b,h,n,d]; ob -> (h,d), ob+8 -> (h,d+1); d even.
                const int h = ob & 7, d = ob >> 3;
                size_t i0 = (((size_t)(b * HH + h) * NN + n) * DH + d) >> 1;
                Yh[i0]      = (u32)b16hi(v0) | ((u32)b16hi(v2) << 16);
                Yl[i0]      = (u32)b16lo(v0) | ((u32)b16lo(v2) << 16);
                Yh[i0 + 32] = (u32)b16hi(v1) | ((u32)b16hi(v3) << 16);
                Yl[i0 + 32] = (u32)b16lo(v1) | ((u32)b16lo(v3) << 16);
            } else {
                // V planes [b,h,d,m]; rows d, d+1, m = n (even).
                const int h = ob & 7, d = ob >> 3;
                size_t i0 = (((size_t)(b * HH + h) * DH + d) * NN + n) >> 1;
                Yh[i0] = (u32)b16hi(v0) | ((u32)b16hi(v1) << 16);
                Yl[i0] = (u32)b16lo(v0) | ((u32)b16lo(v1) << 16);
                size_t i1 = i0 + (NN >> 1);
                Yh[i1] = (u32)b16hi(v2) | ((u32)b16hi(v3) << 16);
                Yl[i1] = (u32)b16lo(v2) | ((u32)b16lo(v3) << 16);
            }
        }
    }
}

// ---------------- final projection (MODE 0, fp32 out) ------------------------
__global__ void __launch_bounds__(256)
proj0_kernel(const u16* __restrict__ XTh, const u16* __restrict__ XTl,
             const u16* __restrict__ Wh, const u16* __restrict__ Wl,
             const float* __restrict__ bias, float* __restrict__ Y) {
    extern __shared__ __align__(16) char pjs[];
    const int b = blockIdx.z, o0 = blockIdx.y * 64, n0 = blockIdx.x * 128;
    const int t = threadIdx.x, lane = t & 31, w = t >> 5;
    const int wm = w & 1, wn = w >> 1;
    const u16* Xh = XTh + (size_t)b * NN * DD;
    const u16* Xl = XTl + (size_t)b * NN * DD;
    const int ar = t >> 2, as = (t & 3) * 8;
    const u32 sb = (u32)__cvta_generic_to_shared(pjs);

    uint4 pa0, pa1, pbh[2], pbl[2];
    float acc[2][4][4];
#pragma unroll
    for (int i = 0; i < 2; i++)
#pragma unroll
        for (int j = 0; j < 4; j++)
#pragma unroll
            for (int k = 0; k < 4; k++) acc[i][j][k] = 0.f;

    auto load_regs = [&](int c0) {
        pa0    = *(const uint4*)&Wh[(size_t)(o0 + ar) * DD + c0 + as];
        pa1    = *(const uint4*)&Wl[(size_t)(o0 + ar) * DD + c0 + as];
        pbh[0] = *(const uint4*)&Xh[(size_t)(n0 + ar) * DD + c0 + as];
        pbl[0] = *(const uint4*)&Xl[(size_t)(n0 + ar) * DD + c0 + as];
        pbh[1] = *(const uint4*)&Xh[(size_t)(n0 + ar + 64) * DD + c0 + as];
        pbl[1] = *(const uint4*)&Xl[(size_t)(n0 + ar + 64) * DD + c0 + as];
    };
    auto store_smem = [&](int buf) {
        char* base = pjs + buf * PJ_BUF;
        const int ro = (ar * PS + as) * 2;
        const int r1 = ((ar + 64) * PS + as) * 2;
        *(uint4*)(base + ro)             = pa0;
        *(uint4*)(base + 5120 + ro)      = pa1;
        *(uint4*)(base + 10240 + ro)     = pbh[0];
        *(uint4*)(base + 20480 + ro)     = pbl[0];
        *(uint4*)(base + 10240 + r1)     = pbh[1];
        *(uint4*)(base + 20480 + r1)     = pbl[1];
    };

    load_regs(0); store_smem(0); load_regs(32);
    __syncthreads();
    const int NC = DD / 32;
    for (int c = 0; c < NC; c++) {
        const int cur = c & 1;
        if (c + 1 < NC) store_smem(cur ^ 1);
        if (c + 2 < NC) load_regs((c + 2) * 32);
        const u32 bb = sb + cur * PJ_BUF;
        mma_step<2, PS>(acc, bb, bb + 5120, bb + 10240, bb + 20480, lane, wm * 32, wn * 32, 0);
        mma_step<2, PS>(acc, bb, bb + 5120, bb + 10240, bb + 20480, lane, wm * 32, wn * 32, 16);
        __syncthreads();
    }

#pragma unroll
    for (int im = 0; im < 2; im++) {
        const int ob = o0 + wm * 32 + im * 16 + (lane >> 2);
        const float bs0 = bias[ob], bs1 = bias[ob + 8];
#pragma unroll
        for (int jn = 0; jn < 4; jn++) {
            float* cc = acc[im][jn];
            const int n = n0 + wn * 32 + jn * 8 + 2 * (lane & 3);
            *(float2*)&Y[((size_t)b * DD + ob) * NN + n]     = make_float2(cc[0] + bs0, cc[1] + bs0);
            *(float2*)&Y[((size_t)b * DD + ob + 8) * NN + n] = make_float2(cc[2] + bs1, cc[3] + bs1);
        }
    }
}

// ---------------- scores: single k-chunk of 64, cp.async fill, fp16 out ------
#define PS2 72
#define SC_PLANE (128 * PS2 * 2)              // 18432 B
#define SC_SMEM  (4 * SC_PLANE)               // 73728 B
__global__ void __launch_bounds__(512)
scores_kernel() {
    extern __shared__ __align__(16) char dsm[];
    __shared__ float sred[16];
    const int bh = blockIdx.z, n0 = blockIdx.y * 128, m0 = blockIdx.x * 128;
    const int t = threadIdx.x, lane = t & 31, w = t >> 5;
    const int wm = w & 3, wn = w >> 2;   // warp tile 32(n) x 32(m)
    const u16* Qh = g_qh + (size_t)bh * NN * DH;
    const u16* Ql = g_ql + (size_t)bh * NN * DH;
    const u16* Kh = g_kh + (size_t)bh * NN * DH;
    const u16* Kl = g_kl + (size_t)bh * NN * DH;

    const u32 sbase = (u32)__cvta_generic_to_shared(dsm);
    const u32 baQh = sbase, baQl = sbase + SC_PLANE;
    const u32 baKh = sbase + 2 * SC_PLANE, baKl = sbase + 3 * SC_PLANE;

#pragma unroll
    for (int rep = 0; rep < 2; rep++) {
        const int idx = t + rep * 512;
        const int row = idx >> 3, c8 = (idx & 7) * 8;
        const u32 off = (u32)(row * PS2 + c8) * 2u;
        cp16(baQh + off, &Qh[(size_t)(n0 + row) * DH + c8]);
        cp16(baQl + off, &Ql[(size_t)(n0 + row) * DH + c8]);
        cp16(baKh + off, &Kh[(size_t)(m0 + row) * DH + c8]);
        cp16(baKl + off, &Kl[(size_t)(m0 + row) * DH + c8]);
    }
    CP_COMMIT();
    CP_WAIT0();
    __syncthreads();

    float acc[2][4][4];
#pragma unroll
    for (int i = 0; i < 2; i++)
#pragma unroll
        for (int j = 0; j < 4; j++)
#pragma unroll
            for (int k = 0; k < 4; k++) acc[i][j][k] = 0.f;

#pragma unroll
    for (int kk = 0; kk < 64; kk += 16)
        mma_step<2, PS2>(acc, baQh, baQl, baKh, baKl, lane, wm * 32, wn * 32, kk);

    float mn = __int_as_float(0x7f800000);
#pragma unroll
    for (int im = 0; im < 2; im++) {
        const int n = n0 + wm * 32 + im * 16 + (lane >> 2);
#pragma unroll
        for (int jn = 0; jn < 4; jn++) {
            float* cc = acc[im][jn];
            const int m = m0 + wn * 32 + jn * 8 + 2 * (lane & 3);
            float2 r0 = make_float2(cc[0] * 0.125f, cc[1] * 0.125f);
            float2 r1 = make_float2(cc[2] * 0.125f, cc[3] * 0.125f);
            mn = fminf(mn, fminf(fminf(r0.x, r0.y), fminf(r1.x, r1.y)));
            __half2 h0 = __floats2half2_rn(r0.x, r0.y);
            __half2 h1 = __floats2half2_rn(r1.x, r1.y);
            *(u32*)&g_s16[((size_t)bh * NN + n) * NN + m]     = *(u32*)&h0;
            *(u32*)&g_s16[((size_t)bh * NN + n + 8) * NN + m] = *(u32*)&h1;
        }
    }
#pragma unroll
    for (int o = 16; o > 0; o >>= 1) mn = fminf(mn, __shfl_xor_sync(0xffffffffu, mn, o));
    if (lane == 0) sred[w] = mn;
    __syncthreads();
    if (t == 0) {
        float v = sred[0];
#pragma unroll
        for (int i = 1; i < 16; i++) v = fminf(v, sred[i]);
        atomicMin(&g_minenc, enc_f(v));
    }
}

// ---------------- fused out2 + softmax stats (smem-staged) -------------------
// dyn smem: s16 rows [8][1536] halves (24576B) + mask row (1536B)
#define OS_SMEM (8 * NN * 2 + NN)
__global__ void __launch_bounds__(256)
osmax_kernel(float* __restrict__ O2) {
    extern __shared__ __align__(16) char osm[];
    const __half* ss = (const __half*)osm;
    const unsigned char* sm = (const unsigned char*)(osm + 8 * NN * 2);
    __shared__ float sred[8][9];
    const int n = blockIdx.x, b = blockIdx.y;
    const int tid = threadIdx.x, lane = tid & 31, wid = tid >> 5;
    const u32 sb = (u32)__cvta_generic_to_shared(osm);

    // stage 8 score rows + mask row via cp.async (16B granules, deep MLP)
    for (int i = tid; i < 8 * (NN / 8); i += 256) {         // 1536 granules
        const int h = i / (NN / 8), c = i % (NN / 8);
        cp16(sb + (h * NN + c * 8) * 2,
             g_s16 + ((size_t)(b * HH + h) * NN + n) * NN + c * 8);
    }
    for (int i = tid; i < NN / 16; i += 256)                // 96 granules
        cp16(sb + 8 * NN * 2 + i * 16, g_mask + (size_t)n * NN + i * 16);
    CP_COMMIT();
    CP_WAIT0();
    __syncthreads();

    const float pen = dec_f(g_minenc) - 20.0f;

    // P1: out2 row = mean over heads + penalty (exact)
    {
        float* o2 = &O2[((size_t)b * NN + n) * NN];
#pragma unroll
        for (int i = 0; i < 6; i++) {
            const int m = tid + i * 256;
            float s = 0.f;
#pragma unroll
            for (int h = 0; h < 8; h++) s += __half2float(ss[h * NN + m]);
            s *= 0.125f;
            if (!sm[m]) s += pen;
            o2[m] = s;
        }
    }

    // P2: per-head max over unmasked (masked never wins: pen ~ -21)
    float mx[8];
#pragma unroll
    for (int h = 0; h < 8; h++) {
        float m_ = -1e30f;
#pragma unroll
        for (int i = 0; i < 6; i++) {
            const int m = tid + i * 256;
            if (sm[m]) m_ = fmaxf(m_, __half2float(ss[h * NN + m]));
        }
#pragma unroll
        for (int o = 16; o > 0; o >>= 1) m_ = fmaxf(m_, __shfl_xor_sync(0xffffffffu, m_, o));
        mx[h] = m_;
    }
    if (lane == 0)
#pragma unroll
        for (int h = 0; h < 8; h++) sred[h][wid] = mx[h];
    __syncthreads();
#pragma unroll
    for (int h = 0; h < 8; h++) {
        float m_ = sred[h][0];
#pragma unroll
        for (int w2 = 1; w2 < 8; w2++) m_ = fmaxf(m_, sred[h][w2]);
        mx[h] = m_;
    }
    __syncthreads();

    // P3: per-head sum of exp over unmasked (masked terms ~e^-21 -> dropped)
    float iv[8];
#pragma unroll
    for (int h = 0; h < 8; h++) {
        float s = 0.f;
#pragma unroll
        for (int i = 0; i < 6; i++) {
            const int m = tid + i * 256;
            if (sm[m]) s += __expf(__half2float(ss[h * NN + m]) - mx[h]);
        }
#pragma unroll
        for (int o = 16; o > 0; o >>= 1) s += __shfl_xor_sync(0xffffffffu, s, o);
        iv[h] = s;
    }
    if (lane == 0)
#pragma unroll
        for (int h = 0; h < 8; h++) sred[h][wid] = iv[h];
    __syncthreads();
    if (tid == 0) {
#pragma unroll
        for (int h = 0; h < 8; h++) {
            float s = sred[h][0];
#pragma unroll
            for (int w2 = 1; w2 < 8; w2++) s += sred[h][w2];
            g_mx[(size_t)(b * HH + h) * NN + n] = mx[h];
            g_iv[(size_t)(b * HH + h) * NN + n] = 1.0f / s;
        }
    }
}

// ---------------- PV: double-buffered; p computed on the fly -----------------
// dyn smem per buffer: Ph 0 (10240B) | Pl 10240 | Vh 20480 (5120B) | Vl 25600
#define PV_BUF 30720
#define PV_SMEM (2 * PV_BUF)
__global__ void __launch_bounds__(256)
pv_kernel() {
    extern __shared__ __align__(16) char pvs[];
    const int bh = blockIdx.y, n0 = blockIdx.x * 128;
    const int t = threadIdx.x, lane = t & 31, w = t >> 5;
    const int wm = w >> 1, wn = w & 1;
    const u16* Vh = g_vh + (size_t)bh * DH * NN;
    const u16* Vl = g_vl + (size_t)bh * DH * NN;
    const u32 sb = (u32)__cvta_generic_to_shared(pvs);

    const int pr = t >> 2, psv = (t & 3) * 8;
    const int rowA = n0 + pr, rowB = rowA + 64;
    const u16* SA = g_s16 + ((size_t)bh * NN + rowA) * NN;
    const u16* SB = g_s16 + ((size_t)bh * NN + rowB) * NN;
    const unsigned char* mA = g_mask + (size_t)rowA * NN;
    const unsigned char* mB = g_mask + (size_t)rowB * NN;
    const float mxA = g_mx[(size_t)bh * NN + rowA], ivA = g_iv[(size_t)bh * NN + rowA];
    const float mxB = g_mx[(size_t)bh * NN + rowB], ivB = g_iv[(size_t)bh * NN + rowB];

    uint4 psA, psB, pvh, pvl;
    uint2 pmA, pmB;
    float acc[2][4][4];
#pragma unroll
    for (int i = 0; i < 2; i++)
#pragma unroll
        for (int j = 0; j < 4; j++)
#pragma unroll
            for (int k = 0; k < 4; k++) acc[i][j][k] = 0.f;

    auto load_regs = [&](int m0c) {
        psA = *(const uint4*)&SA[m0c + psv];
        psB = *(const uint4*)&SB[m0c + psv];
        pmA = *(const uint2*)&mA[m0c + psv];
        pmB = *(const uint2*)&mB[m0c + psv];
        pvh = *(const uint4*)&Vh[(size_t)pr * NN + m0c + psv];
        pvl = *(const uint4*)&Vl[(size_t)pr * NN + m0c + psv];
    };
    auto store_smem = [&](int buf) {
        char* base = pvs + buf * PV_BUF;
        const int roA = (pr * PS + psv) * 2;
        const int roB = ((pr + 64) * PS + psv) * 2;
        const unsigned char* mba = (const unsigned char*)&pmA;
        const unsigned char* mbb = (const unsigned char*)&pmB;
#pragma unroll
        for (int j = 0; j < 4; j++) {
            __half2 hA = ((const __half2*)&psA)[j];
            float2 fA = __half22float2(hA);
            float p0 = mba[2 * j]     ? __expf(fA.x - mxA) * ivA : 0.f;
            float p1 = mba[2 * j + 1] ? __expf(fA.y - mxA) * ivA : 0.f;
            ((u32*)(base + roA))[j]          = (u32)b16hi(p0) | ((u32)b16hi(p1) << 16);
            ((u32*)(base + 10240 + roA))[j]  = (u32)b16lo(p0) | ((u32)b16lo(p1) << 16);
            __half2 hB = ((const __half2*)&psB)[j];
            float2 fB = __half22float2(hB);
            float q0 = mbb[2 * j]     ? __expf(fB.x - mxB) * ivB : 0.f;
            float q1 = mbb[2 * j + 1] ? __expf(fB.y - mxB) * ivB : 0.f;
            ((u32*)(base + roB))[j]          = (u32)b16hi(q0) | ((u32)b16hi(q1) << 16);
            ((u32*)(base + 10240 + roB))[j]  = (u32)b16lo(q0) | ((u32)b16lo(q1) << 16);
        }
        const int roV = (pr * PS + psv) * 2;
        *(uint4*)(base + 20480 + roV) = pvh;
        *(uint4*)(base + 25600 + roV) = pvl;
    };

    load_regs(0); store_smem(0); load_regs(32);
    __syncthreads();
    const int NC = NN / 32;  // 48
    for (int c = 0; c < NC; c++) {
        const int cur = c & 1;
        if (c + 1 < NC) store_smem(cur ^ 1);
        if (c + 2 < NC) load_regs((c + 2) * 32);
        const u32 bb = sb + cur * PV_BUF;
        mma_step<2, PS>(acc, bb, bb + 10240, bb + 20480, bb + 25600, lane, wm * 32, wn * 32, 0);
        mma_step<2, PS>(acc, bb, bb + 10240, bb + 20480, bb + 25600, lane, wm * 32, wn * 32, 16);
        __syncthreads();
    }

    const int b = bh >> 3, h = bh & 7;
#pragma unroll
    for (int im = 0; im < 2; im++) {
        const int n = n0 + wm * 32 + im * 16 + (lane >> 2);
#pragma unroll
        for (int jn = 0; jn < 4; jn++) {
            float* cc = acc[im][jn];
            const int d  = wn * 32 + jn * 8 + 2 * (lane & 3);
            const int c0i = d * 8 + h, c1i = (d + 1) * 8 + h;
            size_t base0 = ((size_t)b * NN + n) * DD;
            size_t base1 = base0 + (size_t)8 * DD;
            g_xth[base0 + c0i] = b16hi(cc[0]);  g_xtl[base0 + c0i] = b16lo(cc[0]);
            g_xth[base0 + c1i] = b16hi(cc[1]);  g_xtl[base0 + c1i] = b16lo(cc[1]);
            g_xth[base1 + c0i] = b16hi(cc[2]);  g_xtl[base1 + c0i] = b16lo(cc[2]);
            g_xth[base1 + c1i] = b16hi(cc[3]);  g_xtl[base1 + c1i] = b16lo(cc[3]);
        }
    }
}

// ---------------- launch ------------------------------------------------------
extern "C" void kernel_launch(void* const* d_in, const int* in_sizes, int n_in,
                              void* d_out, int out_size) {
    const float* query = (const float*)d_in[0];
    const float* key   = (const float*)d_in[1];
    const float* value = (const float*)d_in[2];
    // d_in[3] = dist (unused)
    const void* mask   = d_in[4];
    const float* Wq = (const float*)d_in[5];
    const float* bq = (const float*)d_in[6];
    const float* Wk = (const float*)d_in[7];
    const float* bk = (const float*)d_in[8];
    const float* Wv = (const float*)d_in[9];
    const float* bv = (const float*)d_in[10];
    const float* Wm = (const float*)d_in[11];
    const float* bm = (const float*)d_in[12];

    float* out  = (float*)d_out;                 // [B, D, N]
    float* out2 = out + (size_t)BB * DD * NN;    // [B, N, N]

    void *pih, *pil, *pwh, *pwl, *pqh, *pql, *pkh, *pkl, *pvh, *pvl, *pxth, *pxtl;
    cudaGetSymbolAddress(&pih, g_ith);
    cudaGetSymbolAddress(&pil, g_itl);
    cudaGetSymbolAddress(&pwh, g_wh);
    cudaGetSymbolAddress(&pwl, g_wl);
    cudaGetSymbolAddress(&pqh, g_qh);
    cudaGetSymbolAddress(&pql, g_ql);
    cudaGetSymbolAddress(&pkh, g_kh);
    cudaGetSymbolAddress(&pkl, g_kl);
    cudaGetSymbolAddress(&pvh, g_vh);
    cudaGetSymbolAddress(&pvl, g_vl);
    cudaGetSymbolAddress(&pxth, g_xth);
    cudaGetSymbolAddress(&pxtl, g_xtl);

    const u16* ith = (const u16*)pih;
    const u16* itl = (const u16*)pil;
    const u16* wh  = (const u16*)pwh;
    const u16* wl  = (const u16*)pwl;
    const size_t WB = (size_t)DD * DD;

    cudaFuncSetAttribute(scores_kernel,
                         cudaFuncAttributeMaxDynamicSharedMemorySize, SC_SMEM);
    cudaFuncSetAttribute(projqkv_kernel,
                         cudaFuncAttributeMaxDynamicSharedMemorySize, PJ_SMEM);
    cudaFuncSetAttribute(proj0_kernel,
                         cudaFuncAttributeMaxDynamicSharedMemorySize, PJ_SMEM);
    cudaFuncSetAttribute(pv_kernel,
                         cudaFuncAttributeMaxDynamicSharedMemorySize, PV_SMEM);
    cudaFuncSetAttribute(osmax_kernel,
                         cudaFuncAttributeMaxDynamicSharedMemorySize, OS_SMEM);

    init_kernel<<<1, 1>>>();
    mask_classify_kernel<<<256, 256>>>((const u32*)mask);
    mask_convert_kernel<<<256, 256>>>(mask);

    presplit_in_kernel<<<dim3(NN / 32, DD / 32, 3 * BB), dim3(32, 8)>>>(query, key, value);
    presplit_w_kernel<<<1024, 256>>>(Wq, Wk, Wv, Wm);

    projqkv_kernel<<<dim3(NN / 128, DD / 64, 3 * BB), 256, PJ_SMEM>>>(
        ith, itl, wh, wl, bq, bk, bv,
        (u32*)pqh, (u32*)pql, (u32*)pkh, (u32*)pkl, (u32*)pvh, (u32*)pvl);

    scores_kernel<<<dim3(NN / 128, NN / 128, BB * HH), 512, SC_SMEM>>>();

    osmax_kernel<<<dim3(NN, BB), 256, OS_SMEM>>>(out2);

    pv_kernel<<<dim3(NN / 128, BB * HH), 256, PV_SMEM>>>();

    proj0_kernel<<<dim3(NN / 128, DD / 64, BB), 256, PJ_SMEM>>>(
        (const u16*)pxth, (const u16*)pxtl, wh + 3 * WB, wl + 3 * WB, bm, out);
}

// round 12
// speedup vs baseline: 1.1936x; 1.0913x over previous
#include <cuda_runtime.h>
#include <cuda_bf16.h>
#include <cuda_fp16.h>
#include <cstdint>

#define BB 4
#define DD 512
#define NN 1536
#define HH 8
#define DH 64
#define PS 40   // smem row stride in halves (32 k + 8 pad -> conflict-free ldmatrix)

typedef unsigned short u16;
typedef unsigned int   u32;

// ---------------- scratch (device globals) -----------------------------------
__device__ __align__(16) u16 g_ith[(size_t)3 * BB * NN * DD];  // inputs^T hi [which][b][n][c]
__device__ __align__(16) u16 g_itl[(size_t)3 * BB * NN * DD];  // inputs^T lo
__device__ __align__(16) u16 g_wh[(size_t)4 * DD * DD];        // weights hi [which][o][c] (Wm col-permuted)
__device__ __align__(16) u16 g_wl[(size_t)4 * DD * DD];
__device__ __align__(16) u16 g_qh[(size_t)BB * HH * NN * DH];  // [b,h,n,d]
__device__ __align__(16) u16 g_ql[(size_t)BB * HH * NN * DH];
__device__ __align__(16) u16 g_kh[(size_t)BB * HH * NN * DH];  // [b,h,m,d]
__device__ __align__(16) u16 g_kl[(size_t)BB * HH * NN * DH];
__device__ __align__(16) u16 g_vh[(size_t)BB * HH * DH * NN];  // [b,h,d,m]
__device__ __align__(16) u16 g_vl[(size_t)BB * HH * DH * NN];
__device__ __align__(16) u16 g_s16[(size_t)BB * HH * NN * NN]; // fp16 scores [bh][n][m]
__device__ float g_iv[(size_t)BB * HH * NN];   // row 1/sum(exp(s)) over unmasked
__device__ __align__(16) u16 g_xth[(size_t)BB * HH * NN * DH]; // PV out hi [b,h,n,d]
__device__ __align__(16) u16 g_xtl[(size_t)BB * HH * NN * DH];
__device__ __align__(16) unsigned char g_mask[(size_t)NN * NN];
__device__ u32 g_minenc;
__device__ u32 g_maskflags;

// ---------------- helpers ----------------------------------------------------
__device__ __forceinline__ u32 enc_f(float x) {
    u32 b = __float_as_uint(x);
    return (b & 0x80000000u) ? ~b : (b | 0x80000000u);
}
__device__ __forceinline__ float dec_f(u32 e) {
    return (e & 0x80000000u) ? __uint_as_float(e ^ 0x80000000u)
                             : __uint_as_float(~e);
}
__device__ __forceinline__ u16 b16hi(float x) {
    return __bfloat16_as_ushort(__float2bfloat16(x));
}
__device__ __forceinline__ u16 b16lo(float x) {
    float hf = __bfloat162float(__float2bfloat16(x));
    return __bfloat16_as_ushort(__float2bfloat16(x - hf));
}
__device__ __forceinline__ void cp16(u32 dst, const void* src) {
    asm volatile("cp.async.ca.shared.global [%0], [%1], 16;" :: "r"(dst), "l"(src));
}
#define CP_COMMIT() asm volatile("cp.async.commit_group;" ::: "memory")
#define CP_WAIT0()  asm volatile("cp.async.wait_group 0;" ::: "memory")

__global__ void init_kernel() { g_minenc = 0xFFFFFFFFu; g_maskflags = 0u; }

// ---------------- mask dtype classification + normalization ------------------
__global__ void __launch_bounds__(256)
mask_classify_kernel(const u32* __restrict__ mw) {
    const int total = NN * NN / 4;
    u32 local = 0;
    for (int i = blockIdx.x * 256 + threadIdx.x; i < total; i += gridDim.x * 256) {
        u32 w = mw[i];
        if (w != 0u && w != 1u)          local |= 1u;
        if (w != 0u && w != 0x3f800000u) local |= 2u;
    }
#pragma unroll
    for (int o = 16; o > 0; o >>= 1) local |= __shfl_xor_sync(0xffffffffu, local, o);
    if ((threadIdx.x & 31) == 0 && local) atomicOr(&g_maskflags, local);
}

__global__ void __launch_bounds__(256)
mask_convert_kernel(const void* __restrict__ mraw) {
    const u32 f = g_maskflags;
    const int mode = ((f & 2u) == 0u) ? 2 : (((f & 1u) == 0u) ? 1 : 0);
    const int total = NN * NN;
    if (mode == 0) {
        const unsigned char* m8 = (const unsigned char*)mraw;
        for (int i = blockIdx.x * 256 + threadIdx.x; i < total; i += gridDim.x * 256)
            g_mask[i] = m8[i] ? 1 : 0;
    } else if (mode == 1) {
        const int* mi = (const int*)mraw;
        for (int i = blockIdx.x * 256 + threadIdx.x; i < total; i += gridDim.x * 256)
            g_mask[i] = mi[i] ? 1 : 0;
    } else {
        const float* mf = (const float*)mraw;
        for (int i = blockIdx.x * 256 + threadIdx.x; i < total; i += gridDim.x * 256)
            g_mask[i] = (mf[i] != 0.0f) ? 1 : 0;
    }
}

// ---------------- prepasses: split inputs/weights into bf16 planes -----------
__global__ void __launch_bounds__(256)
presplit_in_kernel(const float* __restrict__ q, const float* __restrict__ k,
                   const float* __restrict__ v) {
    __shared__ float tile[32][33];
    const int which = blockIdx.z >> 2, b = blockIdx.z & 3;
    const float* src = (which == 0 ? q : which == 1 ? k : v) + (size_t)b * DD * NN;
    const int n0 = blockIdx.x * 32, c0 = blockIdx.y * 32;
    const int tx = threadIdx.x, ty = threadIdx.y;  // 32 x 8
#pragma unroll
    for (int i = 0; i < 32; i += 8)
        tile[ty + i][tx] = src[(size_t)(c0 + ty + i) * NN + n0 + tx];
    __syncthreads();
    u16* dh = g_ith + (size_t)(which * BB + b) * NN * DD;
    u16* dl = g_itl + (size_t)(which * BB + b) * NN * DD;
#pragma unroll
    for (int i = 0; i < 32; i += 8) {
        float x = tile[tx][ty + i];
        size_t o = (size_t)(n0 + ty + i) * DD + c0 + tx;
        dh[o] = b16hi(x);
        dl[o] = b16lo(x);
    }
}

// Wm (w==3) columns permuted: c = d*8+h stored at c' = h*64+d (matches pv's
// [b,h,n,d] output layout in proj0's k dimension).
__global__ void __launch_bounds__(256)
presplit_w_kernel(const float* __restrict__ Wq, const float* __restrict__ Wk,
                  const float* __restrict__ Wv, const float* __restrict__ Wm) {
    const int total = 4 * DD * DD;
    for (int i = blockIdx.x * 256 + threadIdx.x; i < total; i += gridDim.x * 256) {
        int w = i >> 18;
        int r = i & (DD * DD - 1);
        const float* src = (w == 0 ? Wq : w == 1 ? Wk : w == 2 ? Wv : Wm);
        float x = src[r];
        int dst = i;
        if (w == 3) {
            int o = r >> 9, c = r & 511;
            int d = c >> 3, h = c & 7;
            dst = (3 << 18) | (o << 9) | (h * 64 + d);
        }
        g_wh[dst] = b16hi(x);
        g_wl[dst] = b16lo(x);
    }
}

// ---------------- mma.sync machinery -----------------------------------------
__device__ __forceinline__ void ldm4(u32& r0, u32& r1, u32& r2, u32& r3, u32 addr) {
    asm volatile("ldmatrix.sync.aligned.m8n8.x4.shared.b16 {%0,%1,%2,%3}, [%4];"
                 : "=r"(r0), "=r"(r1), "=r"(r2), "=r"(r3) : "r"(addr));
}
__device__ __forceinline__ void mma16816(float* c, u32 a0, u32 a1, u32 a2, u32 a3,
                                         u32 b0, u32 b1) {
    asm volatile("mma.sync.aligned.m16n8k16.row.col.f32.bf16.bf16.f32 "
                 "{%0,%1,%2,%3}, {%4,%5,%6,%7}, {%8,%9}, {%0,%1,%2,%3};"
                 : "+f"(c[0]), "+f"(c[1]), "+f"(c[2]), "+f"(c[3])
                 : "r"(a0), "r"(a1), "r"(a2), "r"(a3), "r"(b0), "r"(b1));
}
template <int SPS>
__device__ __forceinline__ u32 ldm_addr(u32 base, int lane, int row0, int col0) {
    int r = row0 + (lane & 7) + ((lane >> 3) & 1) * 8;
    int c = col0 + (lane >> 4) * 8;
    return base + (u32)(r * SPS + c) * 2u;
}
// One k16 step of split-bf16: acc += Ah*Bh + Ah*Bl + Al*Bh
template <int IM, int SPS>
__device__ __forceinline__ void mma_step(float (*acc)[4][4],
                                         u32 baAh, u32 baAl, u32 baBh, u32 baBl,
                                         int lane, int mBase, int nBase, int kk) {
    u32 A[IM][4], B[4][2], C[4][2];
    u32 x0, x1, x2, x3;
#pragma unroll
    for (int im = 0; im < IM; im++)
        ldm4(A[im][0], A[im][1], A[im][2], A[im][3],
             ldm_addr<SPS>(baAh, lane, mBase + im * 16, kk));
    ldm4(x0, x1, x2, x3, ldm_addr<SPS>(baBh, lane, nBase, kk));
    B[0][0] = x0; B[0][1] = x2; B[1][0] = x1; B[1][1] = x3;
    ldm4(x0, x1, x2, x3, ldm_addr<SPS>(baBh, lane, nBase + 16, kk));
    B[2][0] = x0; B[2][1] = x2; B[3][0] = x1; B[3][1] = x3;
#pragma unroll
    for (int im = 0; im < IM; im++)
#pragma unroll
        for (int jn = 0; jn < 4; jn++)
            mma16816(acc[im][jn], A[im][0], A[im][1], A[im][2], A[im][3], B[jn][0], B[jn][1]);
    ldm4(x0, x1, x2, x3, ldm_addr<SPS>(baBl, lane, nBase, kk));
    C[0][0] = x0; C[0][1] = x2; C[1][0] = x1; C[1][1] = x3;
    ldm4(x0, x1, x2, x3, ldm_addr<SPS>(baBl, lane, nBase + 16, kk));
    C[2][0] = x0; C[2][1] = x2; C[3][0] = x1; C[3][1] = x3;
#pragma unroll
    for (int im = 0; im < IM; im++)
#pragma unroll
        for (int jn = 0; jn < 4; jn++)
            mma16816(acc[im][jn], A[im][0], A[im][1], A[im][2], A[im][3], C[jn][0], C[jn][1]);
#pragma unroll
    for (int im = 0; im < IM; im++)
        ldm4(A[im][0], A[im][1], A[im][2], A[im][3],
             ldm_addr<SPS>(baAl, lane, mBase + im * 16, kk));
#pragma unroll
    for (int im = 0; im < IM; im++)
#pragma unroll
        for (int jn = 0; jn < 4; jn++)
            mma16816(acc[im][jn], A[im][0], A[im][1], A[im][2], A[im][3], B[jn][0], B[jn][1]);
}

// ---------------- merged QKV projection (one launch, which = z>>2) -----------
// dyn smem per buffer: Wh 0 (5120B) | Wl 5120 | Xh 10240 (10240B) | Xl 20480
#define PJ_BUF 30720
#define PJ_SMEM (2 * PJ_BUF)
__global__ void __launch_bounds__(256)
projqkv_kernel(const u16* __restrict__ ITh, const u16* __restrict__ ITl,
               const u16* __restrict__ WHp, const u16* __restrict__ WLp,
               const float* __restrict__ bq, const float* __restrict__ bk,
               const float* __restrict__ bv,
               u32* __restrict__ qh, u32* __restrict__ ql,
               u32* __restrict__ kh, u32* __restrict__ kl,
               u32* __restrict__ vh, u32* __restrict__ vl) {
    extern __shared__ __align__(16) char pjs[];
    const int z = blockIdx.z, which = z >> 2, b = z & 3;
    const int o0 = blockIdx.y * 64, n0 = blockIdx.x * 128;
    const int t = threadIdx.x, lane = t & 31, w = t >> 5;
    const int wm = w & 1, wn = w >> 1;
    const u16* Xh = ITh + (size_t)(which * BB + b) * NN * DD;
    const u16* Xl = ITl + (size_t)(which * BB + b) * NN * DD;
    const u16* Wh = WHp + (size_t)which * DD * DD;
    const u16* Wl = WLp + (size_t)which * DD * DD;
    const float* bias = (which == 0) ? bq : (which == 1) ? bk : bv;
    const int ar = t >> 2, as = (t & 3) * 8;
    const u32 sb = (u32)__cvta_generic_to_shared(pjs);

    uint4 pa0, pa1, pbh[2], pbl[2];
    float acc[2][4][4];
#pragma unroll
    for (int i = 0; i < 2; i++)
#pragma unroll
        for (int j = 0; j < 4; j++)
#pragma unroll
            for (int k = 0; k < 4; k++) acc[i][j][k] = 0.f;

    auto load_regs = [&](int c0) {
        pa0    = *(const uint4*)&Wh[(size_t)(o0 + ar) * DD + c0 + as];
        pa1    = *(const uint4*)&Wl[(size_t)(o0 + ar) * DD + c0 + as];
        pbh[0] = *(const uint4*)&Xh[(size_t)(n0 + ar) * DD + c0 + as];
        pbl[0] = *(const uint4*)&Xl[(size_t)(n0 + ar) * DD + c0 + as];
        pbh[1] = *(const uint4*)&Xh[(size_t)(n0 + ar + 64) * DD + c0 + as];
        pbl[1] = *(const uint4*)&Xl[(size_t)(n0 + ar + 64) * DD + c0 + as];
    };
    auto store_smem = [&](int buf) {
        char* base = pjs + buf * PJ_BUF;
        const int ro = (ar * PS + as) * 2;
        const int r1 = ((ar + 64) * PS + as) * 2;
        *(uint4*)(base + ro)             = pa0;
        *(uint4*)(base + 5120 + ro)      = pa1;
        *(uint4*)(base + 10240 + ro)     = pbh[0];
        *(uint4*)(base + 20480 + ro)     = pbl[0];
        *(uint4*)(base + 10240 + r1)     = pbh[1];
        *(uint4*)(base + 20480 + r1)     = pbl[1];
    };

    load_regs(0); store_smem(0); load_regs(32);
    __syncthreads();
    const int NC = DD / 32;  // 16
    for (int c = 0; c < NC; c++) {
        const int cur = c & 1;
        if (c + 1 < NC) store_smem(cur ^ 1);
        if (c + 2 < NC) load_regs((c + 2) * 32);
        const u32 bb = sb + cur * PJ_BUF;
        mma_step<2, PS>(acc, bb, bb + 5120, bb + 10240, bb + 20480, lane, wm * 32, wn * 32, 0);
        mma_step<2, PS>(acc, bb, bb + 5120, bb + 10240, bb + 20480, lane, wm * 32, wn * 32, 16);
        __syncthreads();
    }

    u32* Yh = (which == 0) ? qh : (which == 1) ? kh : vh;
    u32* Yl = (which == 0) ? ql : (which == 1) ? kl : vl;
#pragma unroll
    for (int im = 0; im < 2; im++) {
        const int ob = o0 + wm * 32 + im * 16 + (lane >> 2);
        const float bs0 = bias[ob], bs1 = bias[ob + 8];
#pragma unroll
        for (int jn = 0; jn < 4; jn++) {
            float* cc = acc[im][jn];
            const int n = n0 + wn * 32 + jn * 8 + 2 * (lane & 3);
            const float v0 = cc[0] + bs0, v1 = cc[1] + bs0;
            const float v2 = cc[2] + bs1, v3 = cc[3] + bs1;
            if (which < 2) {
                const int h = ob & 7, d = ob >> 3;
                size_t i0 = (((size_t)(b * HH + h) * NN + n) * DH + d) >> 1;
                Yh[i0]      = (u32)b16hi(v0) | ((u32)b16hi(v2) << 16);
                Yl[i0]      = (u32)b16lo(v0) | ((u32)b16lo(v2) << 16);
                Yh[i0 + 32] = (u32)b16hi(v1) | ((u32)b16hi(v3) << 16);
                Yl[i0 + 32] = (u32)b16lo(v1) | ((u32)b16lo(v3) << 16);
            } else {
                const int h = ob & 7, d = ob >> 3;
                size_t i0 = (((size_t)(b * HH + h) * DH + d) * NN + n) >> 1;
                Yh[i0] = (u32)b16hi(v0) | ((u32)b16hi(v1) << 16);
                Yl[i0] = (u32)b16lo(v0) | ((u32)b16lo(v1) << 16);
                size_t i1 = i0 + (NN >> 1);
                Yh[i1] = (u32)b16hi(v2) | ((u32)b16hi(v3) << 16);
                Yl[i1] = (u32)b16lo(v2) | ((u32)b16lo(v3) << 16);
            }
        }
    }
}

// ---------------- final projection: X from [b,h,n,d] planes, Wm permuted -----
__global__ void __launch_bounds__(256)
proj0_kernel(const u16* __restrict__ XTh, const u16* __restrict__ XTl,
             const u16* __restrict__ Wh, const u16* __restrict__ Wl,
             const float* __restrict__ bias, float* __restrict__ Y) {
    extern __shared__ __align__(16) char pjs[];
    const int b = blockIdx.z, o0 = blockIdx.y * 64, n0 = blockIdx.x * 128;
    const int t = threadIdx.x, lane = t & 31, w = t >> 5;
    const int wm = w & 1, wn = w >> 1;
    const int ar = t >> 2, as = (t & 3) * 8;
    const u32 sb = (u32)__cvta_generic_to_shared(pjs);

    uint4 pa0, pa1, pbh[2], pbl[2];
    float acc[2][4][4];
#pragma unroll
    for (int i = 0; i < 2; i++)
#pragma unroll
        for (int j = 0; j < 4; j++)
#pragma unroll
            for (int k = 0; k < 4; k++) acc[i][j][k] = 0.f;

    auto load_regs = [&](int c0) {
        pa0 = *(const uint4*)&Wh[(size_t)(o0 + ar) * DD + c0 + as];
        pa1 = *(const uint4*)&Wl[(size_t)(o0 + ar) * DD + c0 + as];
        // X k-dim is permuted order c' = h*64 + d; chunk c0 (32 wide) lives in
        // head h = c0>>6 at offset (c0&63)+as (as<32 so no head crossing).
        const int h = c0 >> 6, off = (c0 & 63) + as;
        const size_t hb = (size_t)(b * HH + h) * NN * DH;
        pbh[0] = *(const uint4*)&XTh[hb + (size_t)(n0 + ar) * DH + off];
        pbl[0] = *(const uint4*)&XTl[hb + (size_t)(n0 + ar) * DH + off];
        pbh[1] = *(const uint4*)&XTh[hb + (size_t)(n0 + ar + 64) * DH + off];
        pbl[1] = *(const uint4*)&XTl[hb + (size_t)(n0 + ar + 64) * DH + off];
    };
    auto store_smem = [&](int buf) {
        char* base = pjs + buf * PJ_BUF;
        const int ro = (ar * PS + as) * 2;
        const int r1 = ((ar + 64) * PS + as) * 2;
        *(uint4*)(base + ro)             = pa0;
        *(uint4*)(base + 5120 + ro)      = pa1;
        *(uint4*)(base + 10240 + ro)     = pbh[0];
        *(uint4*)(base + 20480 + ro)     = pbl[0];
        *(uint4*)(base + 10240 + r1)     = pbh[1];
        *(uint4*)(base + 20480 + r1)     = pbl[1];
    };

    load_regs(0); store_smem(0); load_regs(32);
    __syncthreads();
    const int NC = DD / 32;
    for (int c = 0; c < NC; c++) {
        const int cur = c & 1;
        if (c + 1 < NC) store_smem(cur ^ 1);
        if (c + 2 < NC) load_regs((c + 2) * 32);
        const u32 bb = sb + cur * PJ_BUF;
        mma_step<2, PS>(acc, bb, bb + 5120, bb + 10240, bb + 20480, lane, wm * 32, wn * 32, 0);
        mma_step<2, PS>(acc, bb, bb + 5120, bb + 10240, bb + 20480, lane, wm * 32, wn * 32, 16);
        __syncthreads();
    }

#pragma unroll
    for (int im = 0; im < 2; im++) {
        const int ob = o0 + wm * 32 + im * 16 + (lane >> 2);
        const float bs0 = bias[ob], bs1 = bias[ob + 8];
#pragma unroll
        for (int jn = 0; jn < 4; jn++) {
            float* cc = acc[im][jn];
            const int n = n0 + wn * 32 + jn * 8 + 2 * (lane & 3);
            *(float2*)&Y[((size_t)b * DD + ob) * NN + n]     = make_float2(cc[0] + bs0, cc[1] + bs0);
            *(float2*)&Y[((size_t)b * DD + ob + 8) * NN + n] = make_float2(cc[2] + bs1, cc[3] + bs1);
        }
    }
}

// ---------------- scores: single k-chunk of 64, cp.async fill, fp16 out ------
#define PS2 72
#define SC_PLANE (128 * PS2 * 2)              // 18432 B
#define SC_SMEM  (4 * SC_PLANE)               // 73728 B
__global__ void __launch_bounds__(512)
scores_kernel() {
    extern __shared__ __align__(16) char dsm[];
    __shared__ float sred[16];
    const int bh = blockIdx.z, n0 = blockIdx.y * 128, m0 = blockIdx.x * 128;
    const int t = threadIdx.x, lane = t & 31, w = t >> 5;
    const int wm = w & 3, wn = w >> 2;   // warp tile 32(n) x 32(m)
    const u16* Qh = g_qh + (size_t)bh * NN * DH;
    const u16* Ql = g_ql + (size_t)bh * NN * DH;
    const u16* Kh = g_kh + (size_t)bh * NN * DH;
    const u16* Kl = g_kl + (size_t)bh * NN * DH;

    const u32 sbase = (u32)__cvta_generic_to_shared(dsm);
    const u32 baQh = sbase, baQl = sbase + SC_PLANE;
    const u32 baKh = sbase + 2 * SC_PLANE, baKl = sbase + 3 * SC_PLANE;

#pragma unroll
    for (int rep = 0; rep < 2; rep++) {
        const int idx = t + rep * 512;
        const int row = idx >> 3, c8 = (idx & 7) * 8;
        const u32 off = (u32)(row * PS2 + c8) * 2u;
        cp16(baQh + off, &Qh[(size_t)(n0 + row) * DH + c8]);
        cp16(baQl + off, &Ql[(size_t)(n0 + row) * DH + c8]);
        cp16(baKh + off, &Kh[(size_t)(m0 + row) * DH + c8]);
        cp16(baKl + off, &Kl[(size_t)(m0 + row) * DH + c8]);
    }
    CP_COMMIT();
    CP_WAIT0();
    __syncthreads();

    float acc[2][4][4];
#pragma unroll
    for (int i = 0; i < 2; i++)
#pragma unroll
        for (int j = 0; j < 4; j++)
#pragma unroll
            for (int k = 0; k < 4; k++) acc[i][j][k] = 0.f;

#pragma unroll
    for (int kk = 0; kk < 64; kk += 16)
        mma_step<2, PS2>(acc, baQh, baQl, baKh, baKl, lane, wm * 32, wn * 32, kk);

    float mn = __int_as_float(0x7f800000);
#pragma unroll
    for (int im = 0; im < 2; im++) {
        const int n = n0 + wm * 32 + im * 16 + (lane >> 2);
#pragma unroll
        for (int jn = 0; jn < 4; jn++) {
            float* cc = acc[im][jn];
            const int m = m0 + wn * 32 + jn * 8 + 2 * (lane & 3);
            float2 r0 = make_float2(cc[0] * 0.125f, cc[1] * 0.125f);
            float2 r1 = make_float2(cc[2] * 0.125f, cc[3] * 0.125f);
            mn = fminf(mn, fminf(fminf(r0.x, r0.y), fminf(r1.x, r1.y)));
            __half2 h0 = __floats2half2_rn(r0.x, r0.y);
            __half2 h1 = __floats2half2_rn(r1.x, r1.y);
            *(u32*)&g_s16[((size_t)bh * NN + n) * NN + m]     = *(u32*)&h0;
            *(u32*)&g_s16[((size_t)bh * NN + n + 8) * NN + m] = *(u32*)&h1;
        }
    }
#pragma unroll
    for (int o = 16; o > 0; o >>= 1) mn = fminf(mn, __shfl_xor_sync(0xffffffffu, mn, o));
    if (lane == 0) sred[w] = mn;
    __syncthreads();
    if (t == 0) {
        float v = sred[0];
#pragma unroll
        for (int i = 1; i < 16; i++) v = fminf(v, sred[i]);
        atomicMin(&g_minenc, enc_f(v));
    }
}

// ---------------- fused out2 + softmax sums (single sweep, no max) -----------
// dyn smem: s16 rows [8][1536] halves (24576B) + mask row (1536B)
#define OS_SMEM (8 * NN * 2 + NN)
__global__ void __launch_bounds__(256)
osmax_kernel(float* __restrict__ O2) {
    extern __shared__ __align__(16) char osm[];
    const __half* ss = (const __half*)osm;
    const unsigned char* sm = (const unsigned char*)(osm + 8 * NN * 2);
    __shared__ float sred[8][9];
    const int n = blockIdx.x, b = blockIdx.y;
    const int tid = threadIdx.x, lane = tid & 31, wid = tid >> 5;
    const u32 sb = (u32)__cvta_generic_to_shared(osm);

    for (int i = tid; i < 8 * (NN / 8); i += 256) {
        const int h = i / (NN / 8), c = i % (NN / 8);
        cp16(sb + (h * NN + c * 8) * 2,
             g_s16 + ((size_t)(b * HH + h) * NN + n) * NN + c * 8);
    }
    for (int i = tid; i < NN / 16; i += 256)
        cp16(sb + 8 * NN * 2 + i * 16, g_mask + (size_t)n * NN + i * 16);
    CP_COMMIT();
    CP_WAIT0();
    __syncthreads();

    const float pen = dec_f(g_minenc) - 20.0f;
    float* o2 = &O2[((size_t)b * NN + n) * NN];

    // single sweep: out2 element + per-head exp(s) accumulation (unmasked only;
    // masked terms are e^-21 relative -> numerically invisible in the sum)
    float iv[8] = {};
#pragma unroll
    for (int i = 0; i < 6; i++) {
        const int m = tid + i * 256;
        const bool msk = sm[m] != 0;
        float s8 = 0.f;
#pragma unroll
        for (int h = 0; h < 8; h++) {
            float s = __half2float(ss[h * NN + m]);
            s8 += s;
            if (msk) iv[h] += __expf(s);
        }
        o2[m] = s8 * 0.125f + (msk ? 0.f : pen);
    }

#pragma unroll
    for (int h = 0; h < 8; h++) {
        float s = iv[h];
#pragma unroll
        for (int o = 16; o > 0; o >>= 1) s += __shfl_xor_sync(0xffffffffu, s, o);
        iv[h] = s;
    }
    if (lane == 0)
#pragma unroll
        for (int h = 0; h < 8; h++) sred[h][wid] = iv[h];
    __syncthreads();
    if (tid == 0) {
#pragma unroll
        for (int h = 0; h < 8; h++) {
            float s = sred[h][0];
#pragma unroll
            for (int w2 = 1; w2 < 8; w2++) s += sred[h][w2];
            g_iv[(size_t)(b * HH + h) * NN + n] = 1.0f / s;
        }
    }
}

// ---------------- PV: double-buffered; p = exp(s)*iv on the fly --------------
// dyn smem per buffer: Ph 0 (10240B) | Pl 10240 | Vh 20480 (5120B) | Vl 25600
#define PV_BUF 30720
#define PV_SMEM (2 * PV_BUF)
__global__ void __launch_bounds__(256)
pv_kernel() {
    extern __shared__ __align__(16) char pvs[];
    const int bh = blockIdx.y, n0 = blockIdx.x * 128;
    const int t = threadIdx.x, lane = t & 31, w = t >> 5;
    const int wm = w >> 1, wn = w & 1;
    const u16* Vh = g_vh + (size_t)bh * DH * NN;
    const u16* Vl = g_vl + (size_t)bh * DH * NN;
    const u32 sb = (u32)__cvta_generic_to_shared(pvs);

    const int pr = t >> 2, psv = (t & 3) * 8;
    const int rowA = n0 + pr, rowB = rowA + 64;
    const u16* SA = g_s16 + ((size_t)bh * NN + rowA) * NN;
    const u16* SB = g_s16 + ((size_t)bh * NN + rowB) * NN;
    const unsigned char* mA = g_mask + (size_t)rowA * NN;
    const unsigned char* mB = g_mask + (size_t)rowB * NN;
    const float ivA = g_iv[(size_t)bh * NN + rowA];
    const float ivB = g_iv[(size_t)bh * NN + rowB];

    uint4 psA, psB, pvh, pvl;
    uint2 pmA, pmB;
    float acc[2][4][4];
#pragma unroll
    for (int i = 0; i < 2; i++)
#pragma unroll
        for (int j = 0; j < 4; j++)
#pragma unroll
            for (int k = 0; k < 4; k++) acc[i][j][k] = 0.f;

    auto load_regs = [&](int m0c) {
        psA = *(const uint4*)&SA[m0c + psv];
        psB = *(const uint4*)&SB[m0c + psv];
        pmA = *(const uint2*)&mA[m0c + psv];
        pmB = *(const uint2*)&mB[m0c + psv];
        pvh = *(const uint4*)&Vh[(size_t)pr * NN + m0c + psv];
        pvl = *(const uint4*)&Vl[(size_t)pr * NN + m0c + psv];
    };
    auto store_smem = [&](int buf) {
        char* base = pvs + buf * PV_BUF;
        const int roA = (pr * PS + psv) * 2;
        const int roB = ((pr + 64) * PS + psv) * 2;
        const unsigned char* mba = (const unsigned char*)&pmA;
        const unsigned char* mbb = (const unsigned char*)&pmB;
#pragma unroll
        for (int j = 0; j < 4; j++) {
            __half2 hA = ((const __half2*)&psA)[j];
            float2 fA = __half22float2(hA);
            float p0 = mba[2 * j]     ? __expf(fA.x) * ivA : 0.f;
            float p1 = mba[2 * j + 1] ? __expf(fA.y) * ivA : 0.f;
            ((u32*)(base + roA))[j]          = (u32)b16hi(p0) | ((u32)b16hi(p1) << 16);
            ((u32*)(base + 10240 + roA))[j]  = (u32)b16lo(p0) | ((u32)b16lo(p1) << 16);
            __half2 hB = ((const __half2*)&psB)[j];
            float2 fB = __half22float2(hB);
            float q0 = mbb[2 * j]     ? __expf(fB.x) * ivB : 0.f;
            float q1 = mbb[2 * j + 1] ? __expf(fB.y) * ivB : 0.f;
            ((u32*)(base + roB))[j]          = (u32)b16hi(q0) | ((u32)b16hi(q1) << 16);
            ((u32*)(base + 10240 + roB))[j]  = (u32)b16lo(q0) | ((u32)b16lo(q1) << 16);
        }
        const int roV = (pr * PS + psv) * 2;
        *(uint4*)(base + 20480 + roV) = pvh;
        *(uint4*)(base + 25600 + roV) = pvl;
    };

    load_regs(0); store_smem(0); load_regs(32);
    __syncthreads();
    const int NC = NN / 32;  // 48
    for (int c = 0; c < NC; c++) {
        const int cur = c & 1;
        if (c + 1 < NC) store_smem(cur ^ 1);
        if (c + 2 < NC) load_regs((c + 2) * 32);
        const u32 bb = sb + cur * PV_BUF;
        mma_step<2, PS>(acc, bb, bb + 10240, bb + 20480, bb + 25600, lane, wm * 32, wn * 32, 0);
        mma_step<2, PS>(acc, bb, bb + 10240, bb + 20480, bb + 25600, lane, wm * 32, wn * 32, 16);
        __syncthreads();
    }

    // epilogue: packed u32 writes to [b,h,n,d] hi/lo planes (d,d+1 pairs)
    const int b = bh >> 3, h = bh & 7;
    u32* Xh32 = (u32*)g_xth;
    u32* Xl32 = (u32*)g_xtl;
    const size_t hb = (size_t)(b * HH + h) * NN * (DH / 2);
#pragma unroll
    for (int im = 0; im < 2; im++) {
        const int n = n0 + wm * 32 + im * 16 + (lane >> 2);
#pragma unroll
        for (int jn = 0; jn < 4; jn++) {
            float* cc = acc[im][jn];
            const int d = wn * 32 + jn * 8 + 2 * (lane & 3);
            size_t r0 = hb + (size_t)n * (DH / 2) + (d >> 1);
            size_t r1 = r0 + (size_t)8 * (DH / 2);
            Xh32[r0] = (u32)b16hi(cc[0]) | ((u32)b16hi(cc[1]) << 16);
            Xl32[r0] = (u32)b16lo(cc[0]) | ((u32)b16lo(cc[1]) << 16);
            Xh32[r1] = (u32)b16hi(cc[2]) | ((u32)b16hi(cc[3]) << 16);
            Xl32[r1] = (u32)b16lo(cc[2]) | ((u32)b16lo(cc[3]) << 16);
        }
    }
}

// ---------------- launch ------------------------------------------------------
extern "C" void kernel_launch(void* const* d_in, const int* in_sizes, int n_in,
                              void* d_out, int out_size) {
    const float* query = (const float*)d_in[0];
    const float* key   = (const float*)d_in[1];
    const float* value = (const float*)d_in[2];
    // d_in[3] = dist (unused)
    const void* mask   = d_in[4];
    const float* Wq = (const float*)d_in[5];
    const float* bq = (const float*)d_in[6];
    const float* Wk = (const float*)d_in[7];
    const float* bk = (const float*)d_in[8];
    const float* Wv = (const float*)d_in[9];
    const float* bv = (const float*)d_in[10];
    const float* Wm = (const float*)d_in[11];
    const float* bm = (const float*)d_in[12];

    float* out  = (float*)d_out;                 // [B, D, N]
    float* out2 = out + (size_t)BB * DD * NN;    // [B, N, N]

    void *pih, *pil, *pwh, *pwl, *pqh, *pql, *pkh, *pkl, *pvh, *pvl, *pxth, *pxtl;
    cudaGetSymbolAddress(&pih, g_ith);
    cudaGetSymbolAddress(&pil, g_itl);
    cudaGetSymbolAddress(&pwh, g_wh);
    cudaGetSymbolAddress(&pwl, g_wl);
    cudaGetSymbolAddress(&pqh, g_qh);
    cudaGetSymbolAddress(&pql, g_ql);
    cudaGetSymbolAddress(&pkh, g_kh);
    cudaGetSymbolAddress(&pkl, g_kl);
    cudaGetSymbolAddress(&pvh, g_vh);
    cudaGetSymbolAddress(&pvl, g_vl);
    cudaGetSymbolAddress(&pxth, g_xth);
    cudaGetSymbolAddress(&pxtl, g_xtl);

    const u16* ith = (const u16*)pih;
    const u16* itl = (const u16*)pil;
    const u16* wh  = (const u16*)pwh;
    const u16* wl  = (const u16*)pwl;
    const size_t WB = (size_t)DD * DD;

    cudaFuncSetAttribute(scores_kernel,
                         cudaFuncAttributeMaxDynamicSharedMemorySize, SC_SMEM);
    cudaFuncSetAttribute(projqkv_kernel,
                         cudaFuncAttributeMaxDynamicSharedMemorySize, PJ_SMEM);
    cudaFuncSetAttribute(proj0_kernel,
                         cudaFuncAttributeMaxDynamicSharedMemorySize, PJ_SMEM);
    cudaFuncSetAttribute(pv_kernel,
                         cudaFuncAttributeMaxDynamicSharedMemorySize, PV_SMEM);
    cudaFuncSetAttribute(osmax_kernel,
                         cudaFuncAttributeMaxDynamicSharedMemorySize, OS_SMEM);

    init_kernel<<<1, 1>>>();
    mask_classify_kernel<<<256, 256>>>((const u32*)mask);
    mask_convert_kernel<<<256, 256>>>(mask);

    presplit_in_kernel<<<dim3(NN / 32, DD / 32, 3 * BB), dim3(32, 8)>>>(query, key, value);
    presplit_w_kernel<<<1024, 256>>>(Wq, Wk, Wv, Wm);

    projqkv_kernel<<<dim3(NN / 128, DD / 64, 3 * BB), 256, PJ_SMEM>>>(
        ith, itl, wh, wl, bq, bk, bv,
        (u32*)pqh, (u32*)pql, (u32*)pkh, (u32*)pkl, (u32*)pvh, (u32*)pvl);

    scores_kernel<<<dim3(NN / 128, NN / 128, BB * HH), 512, SC_SMEM>>>();

    osmax_kernel<<<dim3(NN, BB), 256, OS_SMEM>>>(out2);

    pv_kernel<<<dim3(NN / 128, BB * HH), 256, PV_SMEM>>>();

    proj0_kernel<<<dim3(NN / 128, DD / 64, BB), 256, PJ_SMEM>>>(
        (const u16*)pxth, (const u16*)pxtl, wh + 3 * WB, wl + 3 * WB, bm, out);
}

// round 13
// speedup vs baseline: 1.2071x; 1.0113x over previous
#include <cuda_runtime.h>
#include <cuda_bf16.h>
#include <cuda_fp16.h>
#include <cstdint>

#define BB 4
#define DD 512
#define NN 1536
#define HH 8
#define DH 64
#define PS 40   // smem row stride in halves (32 k + 8 pad -> conflict-free ldmatrix)

typedef unsigned short u16;
typedef unsigned int   u32;

// ---------------- scratch (device globals) -----------------------------------
__device__ __align__(16) u16 g_ith[(size_t)3 * BB * NN * DD];  // inputs^T hi [which][b][n][c]
__device__ __align__(16) u16 g_itl[(size_t)3 * BB * NN * DD];  // inputs^T lo
__device__ __align__(16) u16 g_wh[(size_t)4 * DD * DD];        // weights hi [which][o][c] (Wm col-permuted)
__device__ __align__(16) u16 g_wl[(size_t)4 * DD * DD];
__device__ __align__(16) u16 g_qh[(size_t)BB * HH * NN * DH];  // [b,h,n,d]
__device__ __align__(16) u16 g_ql[(size_t)BB * HH * NN * DH];
__device__ __align__(16) u16 g_kh[(size_t)BB * HH * NN * DH];  // [b,h,m,d]
__device__ __align__(16) u16 g_kl[(size_t)BB * HH * NN * DH];
__device__ __align__(16) u16 g_vh[(size_t)BB * HH * DH * NN];  // [b,h,d,m]
__device__ __align__(16) u16 g_vl[(size_t)BB * HH * DH * NN];
__device__ __align__(16) u16 g_s16[(size_t)BB * HH * NN * NN]; // fp16 scores [bh][n][m]
__device__ __align__(16) u16 g_xth[(size_t)BB * HH * NN * DH]; // PV out hi [b,h,n,d]
__device__ __align__(16) u16 g_xtl[(size_t)BB * HH * NN * DH];
__device__ __align__(16) unsigned char g_mask[(size_t)NN * NN];
__device__ u32 g_minenc;
__device__ u32 g_maskflags;

// ---------------- helpers ----------------------------------------------------
__device__ __forceinline__ u32 enc_f(float x) {
    u32 b = __float_as_uint(x);
    return (b & 0x80000000u) ? ~b : (b | 0x80000000u);
}
__device__ __forceinline__ float dec_f(u32 e) {
    return (e & 0x80000000u) ? __uint_as_float(e ^ 0x80000000u)
                             : __uint_as_float(~e);
}
__device__ __forceinline__ u16 b16hi(float x) {
    return __bfloat16_as_ushort(__float2bfloat16(x));
}
__device__ __forceinline__ u16 b16lo(float x) {
    float hf = __bfloat162float(__float2bfloat16(x));
    return __bfloat16_as_ushort(__float2bfloat16(x - hf));
}
__device__ __forceinline__ void cp16(u32 dst, const void* src) {
    asm volatile("cp.async.ca.shared.global [%0], [%1], 16;" :: "r"(dst), "l"(src));
}
#define CP_COMMIT() asm volatile("cp.async.commit_group;" ::: "memory")
#define CP_WAIT0()  asm volatile("cp.async.wait_group 0;" ::: "memory")
#define CP_WAIT1()  asm volatile("cp.async.wait_group 1;" ::: "memory")

__global__ void init_kernel() { g_minenc = 0xFFFFFFFFu; g_maskflags = 0u; }

// ---------------- mask dtype classification + normalization ------------------
__global__ void __launch_bounds__(256)
mask_classify_kernel(const u32* __restrict__ mw) {
    const int total = NN * NN / 4;
    u32 local = 0;
    for (int i = blockIdx.x * 256 + threadIdx.x; i < total; i += gridDim.x * 256) {
        u32 w = mw[i];
        if (w != 0u && w != 1u)          local |= 1u;
        if (w != 0u && w != 0x3f800000u) local |= 2u;
    }
#pragma unroll
    for (int o = 16; o > 0; o >>= 1) local |= __shfl_xor_sync(0xffffffffu, local, o);
    if ((threadIdx.x & 31) == 0 && local) atomicOr(&g_maskflags, local);
}

__global__ void __launch_bounds__(256)
mask_convert_kernel(const void* __restrict__ mraw) {
    const u32 f = g_maskflags;
    const int mode = ((f & 2u) == 0u) ? 2 : (((f & 1u) == 0u) ? 1 : 0);
    const int total = NN * NN;
    if (mode == 0) {
        const unsigned char* m8 = (const unsigned char*)mraw;
        for (int i = blockIdx.x * 256 + threadIdx.x; i < total; i += gridDim.x * 256)
            g_mask[i] = m8[i] ? 1 : 0;
    } else if (mode == 1) {
        const int* mi = (const int*)mraw;
        for (int i = blockIdx.x * 256 + threadIdx.x; i < total; i += gridDim.x * 256)
            g_mask[i] = mi[i] ? 1 : 0;
    } else {
        const float* mf = (const float*)mraw;
        for (int i = blockIdx.x * 256 + threadIdx.x; i < total; i += gridDim.x * 256)
            g_mask[i] = (mf[i] != 0.0f) ? 1 : 0;
    }
}

// ---------------- prepasses: split inputs/weights into bf16 planes -----------
__global__ void __launch_bounds__(256)
presplit_in_kernel(const float* __restrict__ q, const float* __restrict__ k,
                   const float* __restrict__ v) {
    __shared__ float tile[32][33];
    const int which = blockIdx.z >> 2, b = blockIdx.z & 3;
    const float* src = (which == 0 ? q : which == 1 ? k : v) + (size_t)b * DD * NN;
    const int n0 = blockIdx.x * 32, c0 = blockIdx.y * 32;
    const int tx = threadIdx.x, ty = threadIdx.y;  // 32 x 8
#pragma unroll
    for (int i = 0; i < 32; i += 8)
        tile[ty + i][tx] = src[(size_t)(c0 + ty + i) * NN + n0 + tx];
    __syncthreads();
    u16* dh = g_ith + (size_t)(which * BB + b) * NN * DD;
    u16* dl = g_itl + (size_t)(which * BB + b) * NN * DD;
#pragma unroll
    for (int i = 0; i < 32; i += 8) {
        float x = tile[tx][ty + i];
        size_t o = (size_t)(n0 + ty + i) * DD + c0 + tx;
        dh[o] = b16hi(x);
        dl[o] = b16lo(x);
    }
}

// Wm (w==3) columns permuted: c = d*8+h stored at c' = h*64+d.
__global__ void __launch_bounds__(256)
presplit_w_kernel(const float* __restrict__ Wq, const float* __restrict__ Wk,
                  const float* __restrict__ Wv, const float* __restrict__ Wm) {
    const int total = 4 * DD * DD;
    for (int i = blockIdx.x * 256 + threadIdx.x; i < total; i += gridDim.x * 256) {
        int w = i >> 18;
        int r = i & (DD * DD - 1);
        const float* src = (w == 0 ? Wq : w == 1 ? Wk : w == 2 ? Wv : Wm);
        float x = src[r];
        int dst = i;
        if (w == 3) {
            int o = r >> 9, c = r & 511;
            int d = c >> 3, h = c & 7;
            dst = (3 << 18) | (o << 9) | (h * 64 + d);
        }
        g_wh[dst] = b16hi(x);
        g_wl[dst] = b16lo(x);
    }
}

// ---------------- mma.sync machinery -----------------------------------------
__device__ __forceinline__ void ldm4(u32& r0, u32& r1, u32& r2, u32& r3, u32 addr) {
    asm volatile("ldmatrix.sync.aligned.m8n8.x4.shared.b16 {%0,%1,%2,%3}, [%4];"
                 : "=r"(r0), "=r"(r1), "=r"(r2), "=r"(r3) : "r"(addr));
}
__device__ __forceinline__ void mma16816(float* c, u32 a0, u32 a1, u32 a2, u32 a3,
                                         u32 b0, u32 b1) {
    asm volatile("mma.sync.aligned.m16n8k16.row.col.f32.bf16.bf16.f32 "
                 "{%0,%1,%2,%3}, {%4,%5,%6,%7}, {%8,%9}, {%0,%1,%2,%3};"
                 : "+f"(c[0]), "+f"(c[1]), "+f"(c[2]), "+f"(c[3])
                 : "r"(a0), "r"(a1), "r"(a2), "r"(a3), "r"(b0), "r"(b1));
}
template <int SPS>
__device__ __forceinline__ u32 ldm_addr(u32 base, int lane, int row0, int col0) {
    int r = row0 + (lane & 7) + ((lane >> 3) & 1) * 8;
    int c = col0 + (lane >> 4) * 8;
    return base + (u32)(r * SPS + c) * 2u;
}
// One k16 step of split-bf16: acc += Ah*Bh + Ah*Bl + Al*Bh
template <int IM, int SPS>
__device__ __forceinline__ void mma_step(float (*acc)[4][4],
                                         u32 baAh, u32 baAl, u32 baBh, u32 baBl,
                                         int lane, int mBase, int nBase, int kk) {
    u32 A[IM][4], B[4][2], C[4][2];
    u32 x0, x1, x2, x3;
#pragma unroll
    for (int im = 0; im < IM; im++)
        ldm4(A[im][0], A[im][1], A[im][2], A[im][3],
             ldm_addr<SPS>(baAh, lane, mBase + im * 16, kk));
    ldm4(x0, x1, x2, x3, ldm_addr<SPS>(baBh, lane, nBase, kk));
    B[0][0] = x0; B[0][1] = x2; B[1][0] = x1; B[1][1] = x3;
    ldm4(x0, x1, x2, x3, ldm_addr<SPS>(baBh, lane, nBase + 16, kk));
    B[2][0] = x0; B[2][1] = x2; B[3][0] = x1; B[3][1] = x3;
#pragma unroll
    for (int im = 0; im < IM; im++)
#pragma unroll
        for (int jn = 0; jn < 4; jn++)
            mma16816(acc[im][jn], A[im][0], A[im][1], A[im][2], A[im][3], B[jn][0], B[jn][1]);
    ldm4(x0, x1, x2, x3, ldm_addr<SPS>(baBl, lane, nBase, kk));
    C[0][0] = x0; C[0][1] = x2; C[1][0] = x1; C[1][1] = x3;
    ldm4(x0, x1, x2, x3, ldm_addr<SPS>(baBl, lane, nBase + 16, kk));
    C[2][0] = x0; C[2][1] = x2; C[3][0] = x1; C[3][1] = x3;
#pragma unroll
    for (int im = 0; im < IM; im++)
#pragma unroll
        for (int jn = 0; jn < 4; jn++)
            mma16816(acc[im][jn], A[im][0], A[im][1], A[im][2], A[im][3], C[jn][0], C[jn][1]);
#pragma unroll
    for (int im = 0; im < IM; im++)
        ldm4(A[im][0], A[im][1], A[im][2], A[im][3],
             ldm_addr<SPS>(baAl, lane, mBase + im * 16, kk));
#pragma unroll
    for (int im = 0; im < IM; im++)
#pragma unroll
        for (int jn = 0; jn < 4; jn++)
            mma16816(acc[im][jn], A[im][0], A[im][1], A[im][2], A[im][3], B[jn][0], B[jn][1]);
}

// ---------------- merged QKV projection (one launch, which = z>>2) -----------
#define PJ_BUF 30720
#define PJ_SMEM (2 * PJ_BUF)
__global__ void __launch_bounds__(256)
projqkv_kernel(const u16* __restrict__ ITh, const u16* __restrict__ ITl,
               const u16* __restrict__ WHp, const u16* __restrict__ WLp,
               const float* __restrict__ bq, const float* __restrict__ bk,
               const float* __restrict__ bv,
               u32* __restrict__ qh, u32* __restrict__ ql,
               u32* __restrict__ kh, u32* __restrict__ kl,
               u32* __restrict__ vh, u32* __restrict__ vl) {
    extern __shared__ __align__(16) char pjs[];
    const int z = blockIdx.z, which = z >> 2, b = z & 3;
    const int o0 = blockIdx.y * 64, n0 = blockIdx.x * 128;
    const int t = threadIdx.x, lane = t & 31, w = t >> 5;
    const int wm = w & 1, wn = w >> 1;
    const u16* Xh = ITh + (size_t)(which * BB + b) * NN * DD;
    const u16* Xl = ITl + (size_t)(which * BB + b) * NN * DD;
    const u16* Wh = WHp + (size_t)which * DD * DD;
    const u16* Wl = WLp + (size_t)which * DD * DD;
    const float* bias = (which == 0) ? bq : (which == 1) ? bk : bv;
    const int ar = t >> 2, as = (t & 3) * 8;
    const u32 sb = (u32)__cvta_generic_to_shared(pjs);

    uint4 pa0, pa1, pbh[2], pbl[2];
    float acc[2][4][4];
#pragma unroll
    for (int i = 0; i < 2; i++)
#pragma unroll
        for (int j = 0; j < 4; j++)
#pragma unroll
            for (int k = 0; k < 4; k++) acc[i][j][k] = 0.f;

    auto load_regs = [&](int c0) {
        pa0    = *(const uint4*)&Wh[(size_t)(o0 + ar) * DD + c0 + as];
        pa1    = *(const uint4*)&Wl[(size_t)(o0 + ar) * DD + c0 + as];
        pbh[0] = *(const uint4*)&Xh[(size_t)(n0 + ar) * DD + c0 + as];
        pbl[0] = *(const uint4*)&Xl[(size_t)(n0 + ar) * DD + c0 + as];
        pbh[1] = *(const uint4*)&Xh[(size_t)(n0 + ar + 64) * DD + c0 + as];
        pbl[1] = *(const uint4*)&Xl[(size_t)(n0 + ar + 64) * DD + c0 + as];
    };
    auto store_smem = [&](int buf) {
        char* base = pjs + buf * PJ_BUF;
        const int ro = (ar * PS + as) * 2;
        const int r1 = ((ar + 64) * PS + as) * 2;
        *(uint4*)(base + ro)             = pa0;
        *(uint4*)(base + 5120 + ro)      = pa1;
        *(uint4*)(base + 10240 + ro)     = pbh[0];
        *(uint4*)(base + 20480 + ro)     = pbl[0];
        *(uint4*)(base + 10240 + r1)     = pbh[1];
        *(uint4*)(base + 20480 + r1)     = pbl[1];
    };

    load_regs(0); store_smem(0); load_regs(32);
    __syncthreads();
    const int NC = DD / 32;  // 16
    for (int c = 0; c < NC; c++) {
        const int cur = c & 1;
        if (c + 1 < NC) store_smem(cur ^ 1);
        if (c + 2 < NC) load_regs((c + 2) * 32);
        const u32 bb = sb + cur * PJ_BUF;
        mma_step<2, PS>(acc, bb, bb + 5120, bb + 10240, bb + 20480, lane, wm * 32, wn * 32, 0);
        mma_step<2, PS>(acc, bb, bb + 5120, bb + 10240, bb + 20480, lane, wm * 32, wn * 32, 16);
        __syncthreads();
    }

    u32* Yh = (which == 0) ? qh : (which == 1) ? kh : vh;
    u32* Yl = (which == 0) ? ql : (which == 1) ? kl : vl;
#pragma unroll
    for (int im = 0; im < 2; im++) {
        const int ob = o0 + wm * 32 + im * 16 + (lane >> 2);
        const float bs0 = bias[ob], bs1 = bias[ob + 8];
#pragma unroll
        for (int jn = 0; jn < 4; jn++) {
            float* cc = acc[im][jn];
            const int n = n0 + wn * 32 + jn * 8 + 2 * (lane & 3);
            const float v0 = cc[0] + bs0, v1 = cc[1] + bs0;
            const float v2 = cc[2] + bs1, v3 = cc[3] + bs1;
            if (which < 2) {
                const int h = ob & 7, d = ob >> 3;
                size_t i0 = (((size_t)(b * HH + h) * NN + n) * DH + d) >> 1;
                Yh[i0]      = (u32)b16hi(v0) | ((u32)b16hi(v2) << 16);
                Yl[i0]      = (u32)b16lo(v0) | ((u32)b16lo(v2) << 16);
                Yh[i0 + 32] = (u32)b16hi(v1) | ((u32)b16hi(v3) << 16);
                Yl[i0 + 32] = (u32)b16lo(v1) | ((u32)b16lo(v3) << 16);
            } else {
                const int h = ob & 7, d = ob >> 3;
                size_t i0 = (((size_t)(b * HH + h) * DH + d) * NN + n) >> 1;
                Yh[i0] = (u32)b16hi(v0) | ((u32)b16hi(v1) << 16);
                Yl[i0] = (u32)b16lo(v0) | ((u32)b16lo(v1) << 16);
                size_t i1 = i0 + (NN >> 1);
                Yh[i1] = (u32)b16hi(v2) | ((u32)b16hi(v3) << 16);
                Yl[i1] = (u32)b16lo(v2) | ((u32)b16lo(v3) << 16);
            }
        }
    }
}

// ---------------- final projection: X from [b,h,n,d] planes, Wm permuted -----
__global__ void __launch_bounds__(256)
proj0_kernel(const u16* __restrict__ XTh, const u16* __restrict__ XTl,
             const u16* __restrict__ Wh, const u16* __restrict__ Wl,
             const float* __restrict__ bias, float* __restrict__ Y) {
    extern __shared__ __align__(16) char pjs[];
    const int b = blockIdx.z, o0 = blockIdx.y * 64, n0 = blockIdx.x * 128;
    const int t = threadIdx.x, lane = t & 31, w = t >> 5;
    const int wm = w & 1, wn = w >> 1;
    const int ar = t >> 2, as = (t & 3) * 8;
    const u32 sb = (u32)__cvta_generic_to_shared(pjs);

    uint4 pa0, pa1, pbh[2], pbl[2];
    float acc[2][4][4];
#pragma unroll
    for (int i = 0; i < 2; i++)
#pragma unroll
        for (int j = 0; j < 4; j++)
#pragma unroll
            for (int k = 0; k < 4; k++) acc[i][j][k] = 0.f;

    auto load_regs = [&](int c0) {
        pa0 = *(const uint4*)&Wh[(size_t)(o0 + ar) * DD + c0 + as];
        pa1 = *(const uint4*)&Wl[(size_t)(o0 + ar) * DD + c0 + as];
        const int h = c0 >> 6, off = (c0 & 63) + as;
        const size_t hb = (size_t)(b * HH + h) * NN * DH;
        pbh[0] = *(const uint4*)&XTh[hb + (size_t)(n0 + ar) * DH + off];
        pbl[0] = *(const uint4*)&XTl[hb + (size_t)(n0 + ar) * DH + off];
        pbh[1] = *(const uint4*)&XTh[hb + (size_t)(n0 + ar + 64) * DH + off];
        pbl[1] = *(const uint4*)&XTl[hb + (size_t)(n0 + ar + 64) * DH + off];
    };
    auto store_smem = [&](int buf) {
        char* base = pjs + buf * PJ_BUF;
        const int ro = (ar * PS + as) * 2;
        const int r1 = ((ar + 64) * PS + as) * 2;
        *(uint4*)(base + ro)             = pa0;
        *(uint4*)(base + 5120 + ro)      = pa1;
        *(uint4*)(base + 10240 + ro)     = pbh[0];
        *(uint4*)(base + 20480 + ro)     = pbl[0];
        *(uint4*)(base + 10240 + r1)     = pbh[1];
        *(uint4*)(base + 20480 + r1)     = pbl[1];
    };

    load_regs(0); store_smem(0); load_regs(32);
    __syncthreads();
    const int NC = DD / 32;
    for (int c = 0; c < NC; c++) {
        const int cur = c & 1;
        if (c + 1 < NC) store_smem(cur ^ 1);
        if (c + 2 < NC) load_regs((c + 2) * 32);
        const u32 bb = sb + cur * PJ_BUF;
        mma_step<2, PS>(acc, bb, bb + 5120, bb + 10240, bb + 20480, lane, wm * 32, wn * 32, 0);
        mma_step<2, PS>(acc, bb, bb + 5120, bb + 10240, bb + 20480, lane, wm * 32, wn * 32, 16);
        __syncthreads();
    }

#pragma unroll
    for (int im = 0; im < 2; im++) {
        const int ob = o0 + wm * 32 + im * 16 + (lane >> 2);
        const float bs0 = bias[ob], bs1 = bias[ob + 8];
#pragma unroll
        for (int jn = 0; jn < 4; jn++) {
            float* cc = acc[im][jn];
            const int n = n0 + wn * 32 + jn * 8 + 2 * (lane & 3);
            *(float2*)&Y[((size_t)b * DD + ob) * NN + n]     = make_float2(cc[0] + bs0, cc[1] + bs0);
            *(float2*)&Y[((size_t)b * DD + ob + 8) * NN + n] = make_float2(cc[2] + bs1, cc[3] + bs1);
        }
    }
}

// ---------------- scores v2: head loop, fused out2 head-sum ------------------
// grid (12 m, 12 n, 4 b); double-buffered per-head tile planes.
#define PS2 72
#define SC_PLANE (128 * PS2 * 2)              // 18432 B
#define SC_BUF   (4 * SC_PLANE)               // 73728 B
#define SC_SMEM  (2 * SC_BUF)                 // 147456 B
__global__ void __launch_bounds__(512)
scores_kernel(float* __restrict__ O2) {
    extern __shared__ __align__(16) char dsm[];
    __shared__ float sred[16];
    const int b = blockIdx.z, n0 = blockIdx.y * 128, m0 = blockIdx.x * 128;
    const int t = threadIdx.x, lane = t & 31, w = t >> 5;
    const int wm = w & 3, wn = w >> 2;   // warp tile 32(n) x 32(m)
    const u32 sbase = (u32)__cvta_generic_to_shared(dsm);

    auto fill = [&](int buf, int h) {
        const size_t bh = (size_t)(b * HH + h);
        const u16* Qh = g_qh + bh * NN * DH;
        const u16* Ql = g_ql + bh * NN * DH;
        const u16* Kh = g_kh + bh * NN * DH;
        const u16* Kl = g_kl + bh * NN * DH;
        const u32 base = sbase + buf * SC_BUF;
#pragma unroll
        for (int rep = 0; rep < 2; rep++) {
            const int idx = t + rep * 512;
            const int row = idx >> 3, c8 = (idx & 7) * 8;
            const u32 off = (u32)(row * PS2 + c8) * 2u;
            cp16(base + off,                &Qh[(size_t)(n0 + row) * DH + c8]);
            cp16(base + SC_PLANE + off,     &Ql[(size_t)(n0 + row) * DH + c8]);
            cp16(base + 2 * SC_PLANE + off, &Kh[(size_t)(m0 + row) * DH + c8]);
            cp16(base + 3 * SC_PLANE + off, &Kl[(size_t)(m0 + row) * DH + c8]);
        }
        CP_COMMIT();
    };

    fill(0, 0);
    float s8[2][4][4];
#pragma unroll
    for (int i = 0; i < 2; i++)
#pragma unroll
        for (int j = 0; j < 4; j++)
#pragma unroll
            for (int k = 0; k < 4; k++) s8[i][j][k] = 0.f;
    float mn = __int_as_float(0x7f800000);

    for (int h = 0; h < HH; h++) {
        if (h > 0) __syncthreads();           // all reads of buf (h+1)&1 done
        if (h + 1 < HH) fill((h + 1) & 1, h + 1);
        if (h + 1 < HH) { CP_WAIT1(); } else { CP_WAIT0(); }
        __syncthreads();

        float acc[2][4][4];
#pragma unroll
        for (int i = 0; i < 2; i++)
#pragma unroll
            for (int j = 0; j < 4; j++)
#pragma unroll
                for (int k = 0; k < 4; k++) acc[i][j][k] = 0.f;

        const u32 bb = sbase + (h & 1) * SC_BUF;
#pragma unroll
        for (int kk = 0; kk < 64; kk += 16)
            mma_step<2, PS2>(acc, bb, bb + SC_PLANE, bb + 2 * SC_PLANE,
                             bb + 3 * SC_PLANE, lane, wm * 32, wn * 32, kk);

        const size_t bh = (size_t)(b * HH + h);
#pragma unroll
        for (int im = 0; im < 2; im++) {
            const int n = n0 + wm * 32 + im * 16 + (lane >> 2);
#pragma unroll
            for (int jn = 0; jn < 4; jn++) {
                float* cc = acc[im][jn];
                const int m = m0 + wn * 32 + jn * 8 + 2 * (lane & 3);
                float2 r0 = make_float2(cc[0] * 0.125f, cc[1] * 0.125f);
                float2 r1 = make_float2(cc[2] * 0.125f, cc[3] * 0.125f);
                mn = fminf(mn, fminf(fminf(r0.x, r0.y), fminf(r1.x, r1.y)));
                s8[im][jn][0] += r0.x; s8[im][jn][1] += r0.y;
                s8[im][jn][2] += r1.x; s8[im][jn][3] += r1.y;
                __half2 h0 = __floats2half2_rn(r0.x, r0.y);
                __half2 h1 = __floats2half2_rn(r1.x, r1.y);
                *(u32*)&g_s16[(bh * NN + n) * NN + m]     = *(u32*)&h0;
                *(u32*)&g_s16[(bh * NN + n + 8) * NN + m] = *(u32*)&h1;
            }
        }
    }

    // out2 head-mean (pen added by fixup kernel after global min is final)
#pragma unroll
    for (int im = 0; im < 2; im++) {
        const int n = n0 + wm * 32 + im * 16 + (lane >> 2);
#pragma unroll
        for (int jn = 0; jn < 4; jn++) {
            float* ss = s8[im][jn];
            const int m = m0 + wn * 32 + jn * 8 + 2 * (lane & 3);
            *(float2*)&O2[((size_t)b * NN + n) * NN + m] =
                make_float2(ss[0] * 0.125f, ss[1] * 0.125f);
            *(float2*)&O2[((size_t)b * NN + n + 8) * NN + m] =
                make_float2(ss[2] * 0.125f, ss[3] * 0.125f);
        }
    }

#pragma unroll
    for (int o = 16; o > 0; o >>= 1) mn = fminf(mn, __shfl_xor_sync(0xffffffffu, mn, o));
    if (lane == 0) sred[w] = mn;
    __syncthreads();
    if (t == 0) {
        float v = sred[0];
#pragma unroll
        for (int i = 1; i < 16; i++) v = fminf(v, sred[i]);
        atomicMin(&g_minenc, enc_f(v));
    }
}

// ---------------- out2 pen fixup: O2 += pen * (~mask) ------------------------
__global__ void __launch_bounds__(256)
pen_fixup_kernel(float* __restrict__ O2) {
    const int idx = blockIdx.x * 256 + threadIdx.x;   // float4 index over [n][m]
    const int total = NN * NN / 4;
    if (idx >= total) return;
    const float pen = dec_f(g_minenc) - 20.0f;
    uchar4 mk = ((const uchar4*)g_mask)[idx];
    if (mk.x && mk.y && mk.z && mk.w) return;         // common case: no change
    float4 ad = make_float4(mk.x ? 0.f : pen, mk.y ? 0.f : pen,
                            mk.z ? 0.f : pen, mk.w ? 0.f : pen);
#pragma unroll
    for (int b = 0; b < BB; b++) {
        float4* p = (float4*)&O2[(size_t)b * NN * NN + idx * 4];
        float4 v = *p;
        v.x += ad.x; v.y += ad.y; v.z += ad.z; v.w += ad.w;
        *p = v;
    }
}

// ---------------- PV: self-normalizing; p = exp(s), scaled by 1/rowsum -------
#define PV_BUF 30720
#define PV_SMEM (2 * PV_BUF)
__global__ void __launch_bounds__(256)
pv_kernel() {
    extern __shared__ __align__(16) char pvs[];
    __shared__ float sSum[128];
    const int bh = blockIdx.y, n0 = blockIdx.x * 128;
    const int t = threadIdx.x, lane = t & 31, w = t >> 5;
    const int wm = w >> 1, wn = w & 1;
    const u16* Vh = g_vh + (size_t)bh * DH * NN;
    const u16* Vl = g_vl + (size_t)bh * DH * NN;
    const u32 sb = (u32)__cvta_generic_to_shared(pvs);

    const int pr = t >> 2, psv = (t & 3) * 8;
    const int rowA = n0 + pr, rowB = rowA + 64;
    const u16* SA = g_s16 + ((size_t)bh * NN + rowA) * NN;
    const u16* SB = g_s16 + ((size_t)bh * NN + rowB) * NN;
    const unsigned char* mA = g_mask + (size_t)rowA * NN;
    const unsigned char* mB = g_mask + (size_t)rowB * NN;

    uint4 psA, psB, pvh, pvl;
    uint2 pmA, pmB;
    float sumA = 0.f, sumB = 0.f;
    float acc[2][4][4];
#pragma unroll
    for (int i = 0; i < 2; i++)
#pragma unroll
        for (int j = 0; j < 4; j++)
#pragma unroll
            for (int k = 0; k < 4; k++) acc[i][j][k] = 0.f;

    auto load_regs = [&](int m0c) {
        psA = *(const uint4*)&SA[m0c + psv];
        psB = *(const uint4*)&SB[m0c + psv];
        pmA = *(const uint2*)&mA[m0c + psv];
        pmB = *(const uint2*)&mB[m0c + psv];
        pvh = *(const uint4*)&Vh[(size_t)pr * NN + m0c + psv];
        pvl = *(const uint4*)&Vl[(size_t)pr * NN + m0c + psv];
    };
    auto store_smem = [&](int buf) {
        char* base = pvs + buf * PV_BUF;
        const int roA = (pr * PS + psv) * 2;
        const int roB = ((pr + 64) * PS + psv) * 2;
        const unsigned char* mba = (const unsigned char*)&pmA;
        const unsigned char* mbb = (const unsigned char*)&pmB;
#pragma unroll
        for (int j = 0; j < 4; j++) {
            __half2 hA = ((const __half2*)&psA)[j];
            float2 fA = __half22float2(hA);
            float p0 = mba[2 * j]     ? __expf(fA.x) : 0.f;
            float p1 = mba[2 * j + 1] ? __expf(fA.y) : 0.f;
            sumA += p0 + p1;
            ((u32*)(base + roA))[j]          = (u32)b16hi(p0) | ((u32)b16hi(p1) << 16);
            ((u32*)(base + 10240 + roA))[j]  = (u32)b16lo(p0) | ((u32)b16lo(p1) << 16);
            __half2 hB = ((const __half2*)&psB)[j];
            float2 fB = __half22float2(hB);
            float q0 = mbb[2 * j]     ? __expf(fB.x) : 0.f;
            float q1 = mbb[2 * j + 1] ? __expf(fB.y) : 0.f;
            sumB += q0 + q1;
            ((u32*)(base + roB))[j]          = (u32)b16hi(q0) | ((u32)b16hi(q1) << 16);
            ((u32*)(base + 10240 + roB))[j]  = (u32)b16lo(q0) | ((u32)b16lo(q1) << 16);
        }
        const int roV = (pr * PS + psv) * 2;
        *(uint4*)(base + 20480 + roV) = pvh;
        *(uint4*)(base + 25600 + roV) = pvl;
    };

    load_regs(0); store_smem(0); load_regs(32);
    __syncthreads();
    const int NC = NN / 32;  // 48
    for (int c = 0; c < NC; c++) {
        const int cur = c & 1;
        if (c + 1 < NC) store_smem(cur ^ 1);
        if (c + 2 < NC) load_regs((c + 2) * 32);
        const u32 bb = sb + cur * PV_BUF;
        mma_step<2, PS>(acc, bb, bb + 10240, bb + 20480, bb + 25600, lane, wm * 32, wn * 32, 0);
        mma_step<2, PS>(acc, bb, bb + 10240, bb + 20480, bb + 25600, lane, wm * 32, wn * 32, 16);
        __syncthreads();
    }

    // row-sum reduce over the 4 threads sharing a row (lanes xor 1, 2)
    sumA += __shfl_xor_sync(0xffffffffu, sumA, 1);
    sumA += __shfl_xor_sync(0xffffffffu, sumA, 2);
    sumB += __shfl_xor_sync(0xffffffffu, sumB, 1);
    sumB += __shfl_xor_sync(0xffffffffu, sumB, 2);
    if ((t & 3) == 0) { sSum[pr] = sumA; sSum[pr + 64] = sumB; }
    __syncthreads();

    // epilogue: scale by 1/rowsum, packed u32 writes to [b,h,n,d] planes
    const int b = bh >> 3, h = bh & 7;
    u32* Xh32 = (u32*)g_xth;
    u32* Xl32 = (u32*)g_xtl;
    const size_t hb = (size_t)(b * HH + h) * NN * (DH / 2);
#pragma unroll
    for (int im = 0; im < 2; im++) {
        const int rl = wm * 32 + im * 16 + (lane >> 2);
        const int n = n0 + rl;
        const float iv0 = 1.0f / sSum[rl];
        const float iv1 = 1.0f / sSum[rl + 8];
#pragma unroll
        for (int jn = 0; jn < 4; jn++) {
            float* cc = acc[im][jn];
            const int d = wn * 32 + jn * 8 + 2 * (lane & 3);
            size_t r0 = hb + (size_t)n * (DH / 2) + (d >> 1);
            size_t r1 = r0 + (size_t)8 * (DH / 2);
            float a0 = cc[0] * iv0, a1 = cc[1] * iv0;
            float a2 = cc[2] * iv1, a3 = cc[3] * iv1;
            Xh32[r0] = (u32)b16hi(a0) | ((u32)b16hi(a1) << 16);
            Xl32[r0] = (u32)b16lo(a0) | ((u32)b16lo(a1) << 16);
            Xh32[r1] = (u32)b16hi(a2) | ((u32)b16hi(a3) << 16);
            Xl32[r1] = (u32)b16lo(a2) | ((u32)b16lo(a3) << 16);
        }
    }
}

// ---------------- launch ------------------------------------------------------
extern "C" void kernel_launch(void* const* d_in, const int* in_sizes, int n_in,
                              void* d_out, int out_size) {
    const float* query = (const float*)d_in[0];
    const float* key   = (const float*)d_in[1];
    const float* value = (const float*)d_in[2];
    // d_in[3] = dist (unused)
    const void* mask   = d_in[4];
    const float* Wq = (const float*)d_in[5];
    const float* bq = (const float*)d_in[6];
    const float* Wk = (const float*)d_in[7];
    const float* bk = (const float*)d_in[8];
    const float* Wv = (const float*)d_in[9];
    const float* bv = (const float*)d_in[10];
    const float* Wm = (const float*)d_in[11];
    const float* bm = (const float*)d_in[12];

    float* out  = (float*)d_out;                 // [B, D, N]
    float* out2 = out + (size_t)BB * DD * NN;    // [B, N, N]

    void *pih, *pil, *pwh, *pwl, *pqh, *pql, *pkh, *pkl, *pvh, *pvl, *pxth, *pxtl;
    cudaGetSymbolAddress(&pih, g_ith);
    cudaGetSymbolAddress(&pil, g_itl);
    cudaGetSymbolAddress(&pwh, g_wh);
    cudaGetSymbolAddress(&pwl, g_wl);
    cudaGetSymbolAddress(&pqh, g_qh);
    cudaGetSymbolAddress(&pql, g_ql);
    cudaGetSymbolAddress(&pkh, g_kh);
    cudaGetSymbolAddress(&pkl, g_kl);
    cudaGetSymbolAddress(&pvh, g_vh);
    cudaGetSymbolAddress(&pvl, g_vl);
    cudaGetSymbolAddress(&pxth, g_xth);
    cudaGetSymbolAddress(&pxtl, g_xtl);

    const u16* ith = (const u16*)pih;
    const u16* itl = (const u16*)pil;
    const u16* wh  = (const u16*)pwh;
    const u16* wl  = (const u16*)pwl;
    const size_t WB = (size_t)DD * DD;

    cudaFuncSetAttribute(scores_kernel,
                         cudaFuncAttributeMaxDynamicSharedMemorySize, SC_SMEM);
    cudaFuncSetAttribute(projqkv_kernel,
                         cudaFuncAttributeMaxDynamicSharedMemorySize, PJ_SMEM);
    cudaFuncSetAttribute(proj0_kernel,
                         cudaFuncAttributeMaxDynamicSharedMemorySize, PJ_SMEM);
    cudaFuncSetAttribute(pv_kernel,
                         cudaFuncAttributeMaxDynamicSharedMemorySize, PV_SMEM);

    init_kernel<<<1, 1>>>();
    mask_classify_kernel<<<256, 256>>>((const u32*)mask);
    mask_convert_kernel<<<256, 256>>>(mask);

    presplit_in_kernel<<<dim3(NN / 32, DD / 32, 3 * BB), dim3(32, 8)>>>(query, key, value);
    presplit_w_kernel<<<1024, 256>>>(Wq, Wk, Wv, Wm);

    projqkv_kernel<<<dim3(NN / 128, DD / 64, 3 * BB), 256, PJ_SMEM>>>(
        ith, itl, wh, wl, bq, bk, bv,
        (u32*)pqh, (u32*)pql, (u32*)pkh, (u32*)pkl, (u32*)pvh, (u32*)pvl);

    scores_kernel<<<dim3(NN / 128, NN / 128, BB), 512, SC_SMEM>>>(out2);

    pv_kernel<<<dim3(NN / 128, BB * HH), 256, PV_SMEM>>>();

    pen_fixup_kernel<<<(NN * NN / 4 + 255) / 256, 256>>>(out2);

    proj0_kernel<<<dim3(NN / 128, DD / 64, BB), 256, PJ_SMEM>>>(
        (const u16*)pxth, (const u16*)pxtl, wh + 3 * WB, wl + 3 * WB, bm, out);
}

// round 14
// speedup vs baseline: 1.2565x; 1.0409x over previous
#include <cuda_runtime.h>
#include <cuda_bf16.h>
#include <cuda_fp16.h>
#include <cstdint>

#define BB 4
#define DD 512
#define NN 1536
#define HH 8
#define DH 64
#define PS 40   // smem row stride in halves (32 k + 8 pad -> conflict-free ldmatrix)

typedef unsigned short u16;
typedef unsigned int   u32;

// ---------------- scratch (device globals) -----------------------------------
__device__ __align__(16) u16 g_ith[(size_t)3 * BB * NN * DD];  // inputs^T hi [which][b][n][c]
__device__ __align__(16) u16 g_itl[(size_t)3 * BB * NN * DD];  // inputs^T lo
__device__ __align__(16) u16 g_wh[(size_t)4 * DD * DD];        // weights hi [which][o][c] (Wm col-permuted)
__device__ __align__(16) u16 g_wl[(size_t)4 * DD * DD];
__device__ __align__(16) u16 g_qh[(size_t)BB * HH * NN * DH];  // [b,h,n,d]
__device__ __align__(16) u16 g_ql[(size_t)BB * HH * NN * DH];
__device__ __align__(16) u16 g_kh[(size_t)BB * HH * NN * DH];  // [b,h,m,d]
__device__ __align__(16) u16 g_kl[(size_t)BB * HH * NN * DH];
__device__ __align__(16) u16 g_vh[(size_t)BB * HH * DH * NN];  // [b,h,d,m]
__device__ __align__(16) u16 g_vl[(size_t)BB * HH * DH * NN];
__device__ __align__(16) u16 g_s16[(size_t)BB * HH * NN * NN]; // fp16 MASKED exp(s) [bh][n][m]
__device__ __align__(16) u16 g_xth[(size_t)BB * HH * NN * DH]; // PV out hi [b,h,n,d]
__device__ __align__(16) u16 g_xtl[(size_t)BB * HH * NN * DH];
__device__ __align__(16) unsigned char g_mask[(size_t)NN * NN];
__device__ u32 g_minenc;
__device__ u32 g_maskflags;

// ---------------- helpers ----------------------------------------------------
__device__ __forceinline__ u32 enc_f(float x) {
    u32 b = __float_as_uint(x);
    return (b & 0x80000000u) ? ~b : (b | 0x80000000u);
}
__device__ __forceinline__ float dec_f(u32 e) {
    return (e & 0x80000000u) ? __uint_as_float(e ^ 0x80000000u)
                             : __uint_as_float(~e);
}
__device__ __forceinline__ u16 b16hi(float x) {
    return __bfloat16_as_ushort(__float2bfloat16(x));
}
__device__ __forceinline__ u16 b16lo(float x) {
    float hf = __bfloat162float(__float2bfloat16(x));
    return __bfloat16_as_ushort(__float2bfloat16(x - hf));
}
__device__ __forceinline__ void cp16(u32 dst, const void* src) {
    asm volatile("cp.async.ca.shared.global [%0], [%1], 16;" :: "r"(dst), "l"(src));
}
#define CP_COMMIT() asm volatile("cp.async.commit_group;" ::: "memory")
#define CP_WAIT0()  asm volatile("cp.async.wait_group 0;" ::: "memory")
#define CP_WAIT1()  asm volatile("cp.async.wait_group 1;" ::: "memory")

__global__ void init_kernel() { g_minenc = 0xFFFFFFFFu; g_maskflags = 0u; }

// ---------------- mask dtype classification + normalization ------------------
__global__ void __launch_bounds__(256)
mask_classify_kernel(const u32* __restrict__ mw) {
    const int total = NN * NN / 4;
    u32 local = 0;
    for (int i = blockIdx.x * 256 + threadIdx.x; i < total; i += gridDim.x * 256) {
        u32 w = mw[i];
        if (w != 0u && w != 1u)          local |= 1u;
        if (w != 0u && w != 0x3f800000u) local |= 2u;
    }
#pragma unroll
    for (int o = 16; o > 0; o >>= 1) local |= __shfl_xor_sync(0xffffffffu, local, o);
    if ((threadIdx.x & 31) == 0 && local) atomicOr(&g_maskflags, local);
}

__global__ void __launch_bounds__(256)
mask_convert_kernel(const void* __restrict__ mraw) {
    const u32 f = g_maskflags;
    const int mode = ((f & 2u) == 0u) ? 2 : (((f & 1u) == 0u) ? 1 : 0);
    const int total = NN * NN;
    if (mode == 0) {
        const unsigned char* m8 = (const unsigned char*)mraw;
        for (int i = blockIdx.x * 256 + threadIdx.x; i < total; i += gridDim.x * 256)
            g_mask[i] = m8[i] ? 1 : 0;
    } else if (mode == 1) {
        const int* mi = (const int*)mraw;
        for (int i = blockIdx.x * 256 + threadIdx.x; i < total; i += gridDim.x * 256)
            g_mask[i] = mi[i] ? 1 : 0;
    } else {
        const float* mf = (const float*)mraw;
        for (int i = blockIdx.x * 256 + threadIdx.x; i < total; i += gridDim.x * 256)
            g_mask[i] = (mf[i] != 0.0f) ? 1 : 0;
    }
}

// ---------------- prepasses: split inputs/weights into bf16 planes -----------
__global__ void __launch_bounds__(256)
presplit_in_kernel(const float* __restrict__ q, const float* __restrict__ k,
                   const float* __restrict__ v) {
    __shared__ float tile[32][33];
    const int which = blockIdx.z >> 2, b = blockIdx.z & 3;
    const float* src = (which == 0 ? q : which == 1 ? k : v) + (size_t)b * DD * NN;
    const int n0 = blockIdx.x * 32, c0 = blockIdx.y * 32;
    const int tx = threadIdx.x, ty = threadIdx.y;  // 32 x 8
#pragma unroll
    for (int i = 0; i < 32; i += 8)
        tile[ty + i][tx] = src[(size_t)(c0 + ty + i) * NN + n0 + tx];
    __syncthreads();
    u16* dh = g_ith + (size_t)(which * BB + b) * NN * DD;
    u16* dl = g_itl + (size_t)(which * BB + b) * NN * DD;
#pragma unroll
    for (int i = 0; i < 32; i += 8) {
        float x = tile[tx][ty + i];
        size_t o = (size_t)(n0 + ty + i) * DD + c0 + tx;
        dh[o] = b16hi(x);
        dl[o] = b16lo(x);
    }
}

// Wm (w==3) columns permuted: c = d*8+h stored at c' = h*64+d.
__global__ void __launch_bounds__(256)
presplit_w_kernel(const float* __restrict__ Wq, const float* __restrict__ Wk,
                  const float* __restrict__ Wv, const float* __restrict__ Wm) {
    const int total = 4 * DD * DD;
    for (int i = blockIdx.x * 256 + threadIdx.x; i < total; i += gridDim.x * 256) {
        int w = i >> 18;
        int r = i & (DD * DD - 1);
        const float* src = (w == 0 ? Wq : w == 1 ? Wk : w == 2 ? Wv : Wm);
        float x = src[r];
        int dst = i;
        if (w == 3) {
            int o = r >> 9, c = r & 511;
            int d = c >> 3, h = c & 7;
            dst = (3 << 18) | (o << 9) | (h * 64 + d);
        }
        g_wh[dst] = b16hi(x);
        g_wl[dst] = b16lo(x);
    }
}

// ---------------- mma.sync machinery -----------------------------------------
__device__ __forceinline__ void ldm4(u32& r0, u32& r1, u32& r2, u32& r3, u32 addr) {
    asm volatile("ldmatrix.sync.aligned.m8n8.x4.shared.b16 {%0,%1,%2,%3}, [%4];"
                 : "=r"(r0), "=r"(r1), "=r"(r2), "=r"(r3) : "r"(addr));
}
__device__ __forceinline__ void mma16816(float* c, u32 a0, u32 a1, u32 a2, u32 a3,
                                         u32 b0, u32 b1) {
    asm volatile("mma.sync.aligned.m16n8k16.row.col.f32.bf16.bf16.f32 "
                 "{%0,%1,%2,%3}, {%4,%5,%6,%7}, {%8,%9}, {%0,%1,%2,%3};"
                 : "+f"(c[0]), "+f"(c[1]), "+f"(c[2]), "+f"(c[3])
                 : "r"(a0), "r"(a1), "r"(a2), "r"(a3), "r"(b0), "r"(b1));
}
template <int SPS>
__device__ __forceinline__ u32 ldm_addr(u32 base, int lane, int row0, int col0) {
    int r = row0 + (lane & 7) + ((lane >> 3) & 1) * 8;
    int c = col0 + (lane >> 4) * 8;
    return base + (u32)(r * SPS + c) * 2u;
}
// One k16 step of split-bf16: acc += Ah*Bh + Ah*Bl + Al*Bh
template <int IM, int SPS>
__device__ __forceinline__ void mma_step(float (*acc)[4][4],
                                         u32 baAh, u32 baAl, u32 baBh, u32 baBl,
                                         int lane, int mBase, int nBase, int kk) {
    u32 A[IM][4], B[4][2], C[4][2];
    u32 x0, x1, x2, x3;
#pragma unroll
    for (int im = 0; im < IM; im++)
        ldm4(A[im][0], A[im][1], A[im][2], A[im][3],
             ldm_addr<SPS>(baAh, lane, mBase + im * 16, kk));
    ldm4(x0, x1, x2, x3, ldm_addr<SPS>(baBh, lane, nBase, kk));
    B[0][0] = x0; B[0][1] = x2; B[1][0] = x1; B[1][1] = x3;
    ldm4(x0, x1, x2, x3, ldm_addr<SPS>(baBh, lane, nBase + 16, kk));
    B[2][0] = x0; B[2][1] = x2; B[3][0] = x1; B[3][1] = x3;
#pragma unroll
    for (int im = 0; im < IM; im++)
#pragma unroll
        for (int jn = 0; jn < 4; jn++)
            mma16816(acc[im][jn], A[im][0], A[im][1], A[im][2], A[im][3], B[jn][0], B[jn][1]);
    ldm4(x0, x1, x2, x3, ldm_addr<SPS>(baBl, lane, nBase, kk));
    C[0][0] = x0; C[0][1] = x2; C[1][0] = x1; C[1][1] = x3;
    ldm4(x0, x1, x2, x3, ldm_addr<SPS>(baBl, lane, nBase + 16, kk));
    C[2][0] = x0; C[2][1] = x2; C[3][0] = x1; C[3][1] = x3;
#pragma unroll
    for (int im = 0; im < IM; im++)
#pragma unroll
        for (int jn = 0; jn < 4; jn++)
            mma16816(acc[im][jn], A[im][0], A[im][1], A[im][2], A[im][3], C[jn][0], C[jn][1]);
#pragma unroll
    for (int im = 0; im < IM; im++)
        ldm4(A[im][0], A[im][1], A[im][2], A[im][3],
             ldm_addr<SPS>(baAl, lane, mBase + im * 16, kk));
#pragma unroll
    for (int im = 0; im < IM; im++)
#pragma unroll
        for (int jn = 0; jn < 4; jn++)
            mma16816(acc[im][jn], A[im][0], A[im][1], A[im][2], A[im][3], B[jn][0], B[jn][1]);
}

// ---------------- merged QKV projection (one launch, which = z>>2) -----------
#define PJ_BUF 30720
#define PJ_SMEM (2 * PJ_BUF)
__global__ void __launch_bounds__(256)
projqkv_kernel(const u16* __restrict__ ITh, const u16* __restrict__ ITl,
               const u16* __restrict__ WHp, const u16* __restrict__ WLp,
               const float* __restrict__ bq, const float* __restrict__ bk,
               const float* __restrict__ bv,
               u32* __restrict__ qh, u32* __restrict__ ql,
               u32* __restrict__ kh, u32* __restrict__ kl,
               u32* __restrict__ vh, u32* __restrict__ vl) {
    extern __shared__ __align__(16) char pjs[];
    const int z = blockIdx.z, which = z >> 2, b = z & 3;
    const int o0 = blockIdx.y * 64, n0 = blockIdx.x * 128;
    const int t = threadIdx.x, lane = t & 31, w = t >> 5;
    const int wm = w & 1, wn = w >> 1;
    const u16* Xh = ITh + (size_t)(which * BB + b) * NN * DD;
    const u16* Xl = ITl + (size_t)(which * BB + b) * NN * DD;
    const u16* Wh = WHp + (size_t)which * DD * DD;
    const u16* Wl = WLp + (size_t)which * DD * DD;
    const float* bias = (which == 0) ? bq : (which == 1) ? bk : bv;
    const int ar = t >> 2, as = (t & 3) * 8;
    const u32 sb = (u32)__cvta_generic_to_shared(pjs);

    uint4 pa0, pa1, pbh[2], pbl[2];
    float acc[2][4][4];
#pragma unroll
    for (int i = 0; i < 2; i++)
#pragma unroll
        for (int j = 0; j < 4; j++)
#pragma unroll
            for (int k = 0; k < 4; k++) acc[i][j][k] = 0.f;

    auto load_regs = [&](int c0) {
        pa0    = *(const uint4*)&Wh[(size_t)(o0 + ar) * DD + c0 + as];
        pa1    = *(const uint4*)&Wl[(size_t)(o0 + ar) * DD + c0 + as];
        pbh[0] = *(const uint4*)&Xh[(size_t)(n0 + ar) * DD + c0 + as];
        pbl[0] = *(const uint4*)&Xl[(size_t)(n0 + ar) * DD + c0 + as];
        pbh[1] = *(const uint4*)&Xh[(size_t)(n0 + ar + 64) * DD + c0 + as];
        pbl[1] = *(const uint4*)&Xl[(size_t)(n0 + ar + 64) * DD + c0 + as];
    };
    auto store_smem = [&](int buf) {
        char* base = pjs + buf * PJ_BUF;
        const int ro = (ar * PS + as) * 2;
        const int r1 = ((ar + 64) * PS + as) * 2;
        *(uint4*)(base + ro)             = pa0;
        *(uint4*)(base + 5120 + ro)      = pa1;
        *(uint4*)(base + 10240 + ro)     = pbh[0];
        *(uint4*)(base + 20480 + ro)     = pbl[0];
        *(uint4*)(base + 10240 + r1)     = pbh[1];
        *(uint4*)(base + 20480 + r1)     = pbl[1];
    };

    load_regs(0); store_smem(0); load_regs(32);
    __syncthreads();
    const int NC = DD / 32;  // 16
    for (int c = 0; c < NC; c++) {
        const int cur = c & 1;
        if (c + 1 < NC) store_smem(cur ^ 1);
        if (c + 2 < NC) load_regs((c + 2) * 32);
        const u32 bb = sb + cur * PJ_BUF;
        mma_step<2, PS>(acc, bb, bb + 5120, bb + 10240, bb + 20480, lane, wm * 32, wn * 32, 0);
        mma_step<2, PS>(acc, bb, bb + 5120, bb + 10240, bb + 20480, lane, wm * 32, wn * 32, 16);
        __syncthreads();
    }

    u32* Yh = (which == 0) ? qh : (which == 1) ? kh : vh;
    u32* Yl = (which == 0) ? ql : (which == 1) ? kl : vl;
#pragma unroll
    for (int im = 0; im < 2; im++) {
        const int ob = o0 + wm * 32 + im * 16 + (lane >> 2);
        const float bs0 = bias[ob], bs1 = bias[ob + 8];
#pragma unroll
        for (int jn = 0; jn < 4; jn++) {
            float* cc = acc[im][jn];
            const int n = n0 + wn * 32 + jn * 8 + 2 * (lane & 3);
            const float v0 = cc[0] + bs0, v1 = cc[1] + bs0;
            const float v2 = cc[2] + bs1, v3 = cc[3] + bs1;
            if (which < 2) {
                const int h = ob & 7, d = ob >> 3;
                size_t i0 = (((size_t)(b * HH + h) * NN + n) * DH + d) >> 1;
                Yh[i0]      = (u32)b16hi(v0) | ((u32)b16hi(v2) << 16);
                Yl[i0]      = (u32)b16lo(v0) | ((u32)b16lo(v2) << 16);
                Yh[i0 + 32] = (u32)b16hi(v1) | ((u32)b16hi(v3) << 16);
                Yl[i0 + 32] = (u32)b16lo(v1) | ((u32)b16lo(v3) << 16);
            } else {
                const int h = ob & 7, d = ob >> 3;
                size_t i0 = (((size_t)(b * HH + h) * DH + d) * NN + n) >> 1;
                Yh[i0] = (u32)b16hi(v0) | ((u32)b16hi(v1) << 16);
                Yl[i0] = (u32)b16lo(v0) | ((u32)b16lo(v1) << 16);
                size_t i1 = i0 + (NN >> 1);
                Yh[i1] = (u32)b16hi(v2) | ((u32)b16hi(v3) << 16);
                Yl[i1] = (u32)b16lo(v2) | ((u32)b16lo(v3) << 16);
            }
        }
    }
}

// ---------------- final projection: X from [b,h,n,d] planes, Wm permuted -----
__global__ void __launch_bounds__(256)
proj0_kernel(const u16* __restrict__ XTh, const u16* __restrict__ XTl,
             const u16* __restrict__ Wh, const u16* __restrict__ Wl,
             const float* __restrict__ bias, float* __restrict__ Y) {
    extern __shared__ __align__(16) char pjs[];
    const int b = blockIdx.z, o0 = blockIdx.y * 64, n0 = blockIdx.x * 128;
    const int t = threadIdx.x, lane = t & 31, w = t >> 5;
    const int wm = w & 1, wn = w >> 1;
    const int ar = t >> 2, as = (t & 3) * 8;
    const u32 sb = (u32)__cvta_generic_to_shared(pjs);

    uint4 pa0, pa1, pbh[2], pbl[2];
    float acc[2][4][4];
#pragma unroll
    for (int i = 0; i < 2; i++)
#pragma unroll
        for (int j = 0; j < 4; j++)
#pragma unroll
            for (int k = 0; k < 4; k++) acc[i][j][k] = 0.f;

    auto load_regs = [&](int c0) {
        pa0 = *(const uint4*)&Wh[(size_t)(o0 + ar) * DD + c0 + as];
        pa1 = *(const uint4*)&Wl[(size_t)(o0 + ar) * DD + c0 + as];
        const int h = c0 >> 6, off = (c0 & 63) + as;
        const size_t hb = (size_t)(b * HH + h) * NN * DH;
        pbh[0] = *(const uint4*)&XTh[hb + (size_t)(n0 + ar) * DH + off];
        pbl[0] = *(const uint4*)&XTl[hb + (size_t)(n0 + ar) * DH + off];
        pbh[1] = *(const uint4*)&XTh[hb + (size_t)(n0 + ar + 64) * DH + off];
        pbl[1] = *(const uint4*)&XTl[hb + (size_t)(n0 + ar + 64) * DH + off];
    };
    auto store_smem = [&](int buf) {
        char* base = pjs + buf * PJ_BUF;
        const int ro = (ar * PS + as) * 2;
        const int r1 = ((ar + 64) * PS + as) * 2;
        *(uint4*)(base + ro)             = pa0;
        *(uint4*)(base + 5120 + ro)      = pa1;
        *(uint4*)(base + 10240 + ro)     = pbh[0];
        *(uint4*)(base + 20480 + ro)     = pbl[0];
        *(uint4*)(base + 10240 + r1)     = pbh[1];
        *(uint4*)(base + 20480 + r1)     = pbl[1];
    };

    load_regs(0); store_smem(0); load_regs(32);
    __syncthreads();
    const int NC = DD / 32;
    for (int c = 0; c < NC; c++) {
        const int cur = c & 1;
        if (c + 1 < NC) store_smem(cur ^ 1);
        if (c + 2 < NC) load_regs((c + 2) * 32);
        const u32 bb = sb + cur * PJ_BUF;
        mma_step<2, PS>(acc, bb, bb + 5120, bb + 10240, bb + 20480, lane, wm * 32, wn * 32, 0);
        mma_step<2, PS>(acc, bb, bb + 5120, bb + 10240, bb + 20480, lane, wm * 32, wn * 32, 16);
        __syncthreads();
    }

#pragma unroll
    for (int im = 0; im < 2; im++) {
        const int ob = o0 + wm * 32 + im * 16 + (lane >> 2);
        const float bs0 = bias[ob], bs1 = bias[ob + 8];
#pragma unroll
        for (int jn = 0; jn < 4; jn++) {
            float* cc = acc[im][jn];
            const int n = n0 + wn * 32 + jn * 8 + 2 * (lane & 3);
            *(float2*)&Y[((size_t)b * DD + ob) * NN + n]     = make_float2(cc[0] + bs0, cc[1] + bs0);
            *(float2*)&Y[((size_t)b * DD + ob + 8) * NN + n] = make_float2(cc[2] + bs1, cc[3] + bs1);
        }
    }
}

// ---------------- scores: head loop, fused out2, writes MASKED exp(s) --------
#define PS2 72
#define SC_PLANE (128 * PS2 * 2)              // 18432 B
#define SC_BUF   (4 * SC_PLANE)               // 73728 B
#define SC_MASK  (2 * SC_BUF)                 // mask tile offset
#define SC_SMEM  (2 * SC_BUF + 128 * 128)     // + 16KB mask tile = 163840 B
__global__ void __launch_bounds__(512)
scores_kernel(float* __restrict__ O2) {
    extern __shared__ __align__(16) char dsm[];
    __shared__ float sred[16];
    const int b = blockIdx.z, n0 = blockIdx.y * 128, m0 = blockIdx.x * 128;
    const int t = threadIdx.x, lane = t & 31, w = t >> 5;
    const int wm = w & 3, wn = w >> 2;   // warp tile 32(n) x 32(m)
    const u32 sbase = (u32)__cvta_generic_to_shared(dsm);
    const u16* smask = (const u16*)(dsm + SC_MASK);  // [128 n][128 m] bytes

    auto fill = [&](int buf, int h) {
        const size_t bh = (size_t)(b * HH + h);
        const u16* Qh = g_qh + bh * NN * DH;
        const u16* Ql = g_ql + bh * NN * DH;
        const u16* Kh = g_kh + bh * NN * DH;
        const u16* Kl = g_kl + bh * NN * DH;
        const u32 base = sbase + buf * SC_BUF;
#pragma unroll
        for (int rep = 0; rep < 2; rep++) {
            const int idx = t + rep * 512;
            const int row = idx >> 3, c8 = (idx & 7) * 8;
            const u32 off = (u32)(row * PS2 + c8) * 2u;
            cp16(base + off,                &Qh[(size_t)(n0 + row) * DH + c8]);
            cp16(base + SC_PLANE + off,     &Ql[(size_t)(n0 + row) * DH + c8]);
            cp16(base + 2 * SC_PLANE + off, &Kh[(size_t)(m0 + row) * DH + c8]);
            cp16(base + 3 * SC_PLANE + off, &Kl[(size_t)(m0 + row) * DH + c8]);
        }
        CP_COMMIT();
    };

    // mask tile: 128 rows x 128B = 1024 granules (lands with fill(0)'s group)
#pragma unroll
    for (int rep = 0; rep < 2; rep++) {
        const int idx = t + rep * 512;
        const int row = idx >> 3, c16 = (idx & 7) * 16;
        cp16(sbase + SC_MASK + (u32)(row * 128 + c16),
             g_mask + (size_t)(n0 + row) * NN + m0 + c16);
    }
    fill(0, 0);

    float s8[2][4][4];
#pragma unroll
    for (int i = 0; i < 2; i++)
#pragma unroll
        for (int j = 0; j < 4; j++)
#pragma unroll
            for (int k = 0; k < 4; k++) s8[i][j][k] = 0.f;
    float mn = __int_as_float(0x7f800000);

    for (int h = 0; h < HH; h++) {
        if (h > 0) __syncthreads();           // all reads of buf (h+1)&1 done
        if (h + 1 < HH) fill((h + 1) & 1, h + 1);
        if (h + 1 < HH) { CP_WAIT1(); } else { CP_WAIT0(); }
        __syncthreads();

        float acc[2][4][4];
#pragma unroll
        for (int i = 0; i < 2; i++)
#pragma unroll
            for (int j = 0; j < 4; j++)
#pragma unroll
                for (int k = 0; k < 4; k++) acc[i][j][k] = 0.f;

        const u32 bb = sbase + (h & 1) * SC_BUF;
#pragma unroll
        for (int kk = 0; kk < 64; kk += 16)
            mma_step<2, PS2>(acc, bb, bb + SC_PLANE, bb + 2 * SC_PLANE,
                             bb + 3 * SC_PLANE, lane, wm * 32, wn * 32, kk);

        const size_t bh = (size_t)(b * HH + h);
#pragma unroll
        for (int im = 0; im < 2; im++) {
            const int nl = wm * 32 + im * 16 + (lane >> 2);
            const int n = n0 + nl;
#pragma unroll
            for (int jn = 0; jn < 4; jn++) {
                float* cc = acc[im][jn];
                const int ml = wn * 32 + jn * 8 + 2 * (lane & 3);
                const int m = m0 + ml;
                float2 r0 = make_float2(cc[0] * 0.125f, cc[1] * 0.125f);
                float2 r1 = make_float2(cc[2] * 0.125f, cc[3] * 0.125f);
                mn = fminf(mn, fminf(fminf(r0.x, r0.y), fminf(r1.x, r1.y)));
                s8[im][jn][0] += r0.x; s8[im][jn][1] += r0.y;
                s8[im][jn][2] += r1.x; s8[im][jn][3] += r1.y;
                const u16 mk0 = smask[nl * 64 + (ml >> 1)];
                const u16 mk1 = smask[(nl + 8) * 64 + (ml >> 1)];
                float p0 = (mk0 & 0xff) ? __expf(r0.x) : 0.f;
                float p1 = (mk0 >> 8)   ? __expf(r0.y) : 0.f;
                float p2 = (mk1 & 0xff) ? __expf(r1.x) : 0.f;
                float p3 = (mk1 >> 8)   ? __expf(r1.y) : 0.f;
                __half2 h0 = __floats2half2_rn(p0, p1);
                __half2 h1 = __floats2half2_rn(p2, p3);
                *(u32*)&g_s16[(bh * NN + n) * NN + m]     = *(u32*)&h0;
                *(u32*)&g_s16[(bh * NN + n + 8) * NN + m] = *(u32*)&h1;
            }
        }
    }

    // out2 head-mean (pen added by fixup kernel after global min is final)
#pragma unroll
    for (int im = 0; im < 2; im++) {
        const int n = n0 + wm * 32 + im * 16 + (lane >> 2);
#pragma unroll
        for (int jn = 0; jn < 4; jn++) {
            float* ss = s8[im][jn];
            const int m = m0 + wn * 32 + jn * 8 + 2 * (lane & 3);
            *(float2*)&O2[((size_t)b * NN + n) * NN + m] =
                make_float2(ss[0] * 0.125f, ss[1] * 0.125f);
            *(float2*)&O2[((size_t)b * NN + n + 8) * NN + m] =
                make_float2(ss[2] * 0.125f, ss[3] * 0.125f);
        }
    }

#pragma unroll
    for (int o = 16; o > 0; o >>= 1) mn = fminf(mn, __shfl_xor_sync(0xffffffffu, mn, o));
    if (lane == 0) sred[w] = mn;
    __syncthreads();
    if (t == 0) {
        float v = sred[0];
#pragma unroll
        for (int i = 1; i < 16; i++) v = fminf(v, sred[i]);
        atomicMin(&g_minenc, enc_f(v));
    }
}

// ---------------- out2 pen fixup: O2 += pen * (~mask) ------------------------
__global__ void __launch_bounds__(256)
pen_fixup_kernel(float* __restrict__ O2) {
    const int idx = blockIdx.x * 256 + threadIdx.x;   // float4 index over [n][m]
    const int total = NN * NN / 4;
    if (idx >= total) return;
    const float pen = dec_f(g_minenc) - 20.0f;
    uchar4 mk = ((const uchar4*)g_mask)[idx];
    if (mk.x && mk.y && mk.z && mk.w) return;         // common case: no change
    float4 ad = make_float4(mk.x ? 0.f : pen, mk.y ? 0.f : pen,
                            mk.z ? 0.f : pen, mk.w ? 0.f : pen);
#pragma unroll
    for (int b = 0; b < BB; b++) {
        float4* p = (float4*)&O2[(size_t)b * NN * NN + idx * 4];
        float4 v = *p;
        v.x += ad.x; v.y += ad.y; v.z += ad.z; v.w += ad.w;
        *p = v;
    }
}

// ---------------- PV: reads masked exp fp16; self-normalizing ----------------
#define PV_BUF 30720
#define PV_SMEM (2 * PV_BUF)
__global__ void __launch_bounds__(256)
pv_kernel() {
    extern __shared__ __align__(16) char pvs[];
    __shared__ float sSum[128];
    const int bh = blockIdx.y, n0 = blockIdx.x * 128;
    const int t = threadIdx.x, lane = t & 31, w = t >> 5;
    const int wm = w >> 1, wn = w & 1;
    const u16* Vh = g_vh + (size_t)bh * DH * NN;
    const u16* Vl = g_vl + (size_t)bh * DH * NN;
    const u32 sb = (u32)__cvta_generic_to_shared(pvs);

    const int pr = t >> 2, psv = (t & 3) * 8;
    const int rowA = n0 + pr, rowB = rowA + 64;
    const u16* SA = g_s16 + ((size_t)bh * NN + rowA) * NN;
    const u16* SB = g_s16 + ((size_t)bh * NN + rowB) * NN;

    uint4 psA, psB, pvh, pvl;
    float sumA = 0.f, sumB = 0.f;
    float acc[2][4][4];
#pragma unroll
    for (int i = 0; i < 2; i++)
#pragma unroll
        for (int j = 0; j < 4; j++)
#pragma unroll
            for (int k = 0; k < 4; k++) acc[i][j][k] = 0.f;

    auto load_regs = [&](int m0c) {
        psA = *(const uint4*)&SA[m0c + psv];
        psB = *(const uint4*)&SB[m0c + psv];
        pvh = *(const uint4*)&Vh[(size_t)pr * NN + m0c + psv];
        pvl = *(const uint4*)&Vl[(size_t)pr * NN + m0c + psv];
    };
    auto store_smem = [&](int buf) {
        char* base = pvs + buf * PV_BUF;
        const int roA = (pr * PS + psv) * 2;
        const int roB = ((pr + 64) * PS + psv) * 2;
#pragma unroll
        for (int j = 0; j < 4; j++) {
            float2 fA = __half22float2(((const __half2*)&psA)[j]);
            sumA += fA.x + fA.y;
            ((u32*)(base + roA))[j]          = (u32)b16hi(fA.x) | ((u32)b16hi(fA.y) << 16);
            ((u32*)(base + 10240 + roA))[j]  = (u32)b16lo(fA.x) | ((u32)b16lo(fA.y) << 16);
            float2 fB = __half22float2(((const __half2*)&psB)[j]);
            sumB += fB.x + fB.y;
            ((u32*)(base + roB))[j]          = (u32)b16hi(fB.x) | ((u32)b16hi(fB.y) << 16);
            ((u32*)(base + 10240 + roB))[j]  = (u32)b16lo(fB.x) | ((u32)b16lo(fB.y) << 16);
        }
        const int roV = (pr * PS + psv) * 2;
        *(uint4*)(base + 20480 + roV) = pvh;
        *(uint4*)(base + 25600 + roV) = pvl;
    };

    load_regs(0); store_smem(0); load_regs(32);
    __syncthreads();
    const int NC = NN / 32;  // 48
    for (int c = 0; c < NC; c++) {
        const int cur = c & 1;
        if (c + 1 < NC) store_smem(cur ^ 1);
        if (c + 2 < NC) load_regs((c + 2) * 32);
        const u32 bb = sb + cur * PV_BUF;
        mma_step<2, PS>(acc, bb, bb + 10240, bb + 20480, bb + 25600, lane, wm * 32, wn * 32, 0);
        mma_step<2, PS>(acc, bb, bb + 10240, bb + 20480, bb + 25600, lane, wm * 32, wn * 32, 16);
        __syncthreads();
    }

    // row-sum reduce over the 4 threads sharing a row (lanes xor 1, 2)
    sumA += __shfl_xor_sync(0xffffffffu, sumA, 1);
    sumA += __shfl_xor_sync(0xffffffffu, sumA, 2);
    sumB += __shfl_xor_sync(0xffffffffu, sumB, 1);
    sumB += __shfl_xor_sync(0xffffffffu, sumB, 2);
    if ((t & 3) == 0) { sSum[pr] = sumA; sSum[pr + 64] = sumB; }
    __syncthreads();

    // epilogue: scale by 1/rowsum, packed u32 writes to [b,h,n,d] planes
    const int b = bh >> 3, h = bh & 7;
    u32* Xh32 = (u32*)g_xth;
    u32* Xl32 = (u32*)g_xtl;
    const size_t hb = (size_t)(b * HH + h) * NN * (DH / 2);
#pragma unroll
    for (int im = 0; im < 2; im++) {
        const int rl = wm * 32 + im * 16 + (lane >> 2);
        const int n = n0 + rl;
        const float iv0 = 1.0f / sSum[rl];
        const float iv1 = 1.0f / sSum[rl + 8];
#pragma unroll
        for (int jn = 0; jn < 4; jn++) {
            float* cc = acc[im][jn];
            const int d = wn * 32 + jn * 8 + 2 * (lane & 3);
            size_t r0 = hb + (size_t)n * (DH / 2) + (d >> 1);
            size_t r1 = r0 + (size_t)8 * (DH / 2);
            float a0 = cc[0] * iv0, a1 = cc[1] * iv0;
            float a2 = cc[2] * iv1, a3 = cc[3] * iv1;
            Xh32[r0] = (u32)b16hi(a0) | ((u32)b16hi(a1) << 16);
            Xl32[r0] = (u32)b16lo(a0) | ((u32)b16lo(a1) << 16);
            Xh32[r1] = (u32)b16hi(a2) | ((u32)b16hi(a3) << 16);
            Xl32[r1] = (u32)b16lo(a2) | ((u32)b16lo(a3) << 16);
        }
    }
}

// ---------------- launch ------------------------------------------------------
extern "C" void kernel_launch(void* const* d_in, const int* in_sizes, int n_in,
                              void* d_out, int out_size) {
    const float* query = (const float*)d_in[0];
    const float* key   = (const float*)d_in[1];
    const float* value = (const float*)d_in[2];
    // d_in[3] = dist (unused)
    const void* mask   = d_in[4];
    const float* Wq = (const float*)d_in[5];
    const float* bq = (const float*)d_in[6];
    const float* Wk = (const float*)d_in[7];
    const float* bk = (const float*)d_in[8];
    const float* Wv = (const float*)d_in[9];
    const float* bv = (const float*)d_in[10];
    const float* Wm = (const float*)d_in[11];
    const float* bm = (const float*)d_in[12];

    float* out  = (float*)d_out;                 // [B, D, N]
    float* out2 = out + (size_t)BB * DD * NN;    // [B, N, N]

    void *pih, *pil, *pwh, *pwl, *pqh, *pql, *pkh, *pkl, *pvh, *pvl, *pxth, *pxtl;
    cudaGetSymbolAddress(&pih, g_ith);
    cudaGetSymbolAddress(&pil, g_itl);
    cudaGetSymbolAddress(&pwh, g_wh);
    cudaGetSymbolAddress(&pwl, g_wl);
    cudaGetSymbolAddress(&pqh, g_qh);
    cudaGetSymbolAddress(&pql, g_ql);
    cudaGetSymbolAddress(&pkh, g_kh);
    cudaGetSymbolAddress(&pkl, g_kl);
    cudaGetSymbolAddress(&pvh, g_vh);
    cudaGetSymbolAddress(&pvl, g_vl);
    cudaGetSymbolAddress(&pxth, g_xth);
    cudaGetSymbolAddress(&pxtl, g_xtl);

    const u16* ith = (const u16*)pih;
    const u16* itl = (const u16*)pil;
    const u16* wh  = (const u16*)pwh;
    const u16* wl  = (const u16*)pwl;
    const size_t WB = (size_t)DD * DD;

    // One-time setup on the first (uncaptured) call: attrs, side stream, events.
    static cudaStream_t s2 = nullptr;
    static cudaEvent_t evA = nullptr, evB = nullptr, evC = nullptr, evD = nullptr;
    if (s2 == nullptr) {
        cudaFuncSetAttribute(scores_kernel,
                             cudaFuncAttributeMaxDynamicSharedMemorySize, SC_SMEM);
        cudaFuncSetAttribute(projqkv_kernel,
                             cudaFuncAttributeMaxDynamicSharedMemorySize, PJ_SMEM);
        cudaFuncSetAttribute(proj0_kernel,
                             cudaFuncAttributeMaxDynamicSharedMemorySize, PJ_SMEM);
        cudaFuncSetAttribute(pv_kernel,
                             cudaFuncAttributeMaxDynamicSharedMemorySize, PV_SMEM);
        cudaStreamCreateWithFlags(&s2, cudaStreamNonBlocking);
        cudaEventCreateWithFlags(&evA, cudaEventDisableTiming);
        cudaEventCreateWithFlags(&evB, cudaEventDisableTiming);
        cudaEventCreateWithFlags(&evC, cudaEventDisableTiming);
        cudaEventCreateWithFlags(&evD, cudaEventDisableTiming);
    }

    init_kernel<<<1, 1>>>();
    cudaEventRecord(evA, 0);

    // side stream: mask dtype chain (consumed by scores & pen_fixup)
    cudaStreamWaitEvent(s2, evA, 0);
    mask_classify_kernel<<<256, 256, 0, s2>>>((const u32*)mask);
    mask_convert_kernel<<<256, 256, 0, s2>>>(mask);
    cudaEventRecord(evB, s2);

    // main stream: presplits + QKV projection (independent of mask)
    presplit_in_kernel<<<dim3(NN / 32, DD / 32, 3 * BB), dim3(32, 8)>>>(query, key, value);
    presplit_w_kernel<<<1024, 256>>>(Wq, Wk, Wv, Wm);
    projqkv_kernel<<<dim3(NN / 128, DD / 64, 3 * BB), 256, PJ_SMEM>>>(
        ith, itl, wh, wl, bq, bk, bv,
        (u32*)pqh, (u32*)pql, (u32*)pkh, (u32*)pkl, (u32*)pvh, (u32*)pvl);

    cudaStreamWaitEvent(0, evB, 0);   // mask ready before scores
    scores_kernel<<<dim3(NN / 128, NN / 128, BB), 512, SC_SMEM>>>(out2);
    cudaEventRecord(evC, 0);

    // side stream: out2 penalty fixup (|| pv + proj0)
    cudaStreamWaitEvent(s2, evC, 0);
    pen_fixup_kernel<<<(NN * NN / 4 + 255) / 256, 256, 0, s2>>>(out2);
    cudaEventRecord(evD, s2);

    pv_kernel<<<dim3(NN / 128, BB * HH), 256, PV_SMEM>>>();
    proj0_kernel<<<dim3(NN / 128, DD / 64, BB), 256, PJ_SMEM>>>(
        (const u16*)pxth, (const u16*)pxtl, wh + 3 * WB, wl + 3 * WB, bm, out);

    cudaStreamWaitEvent(0, evD, 0);   // join side stream before capture ends
}

// round 15
// speedup vs baseline: 1.3946x; 1.1099x over previous
#include <cuda_runtime.h>
#include <cuda_bf16.h>
#include <cuda_fp16.h>
#include <cstdint>

#define BB 4
#define DD 512
#define NN 1536
#define HH 8
#define DH 64
#define PS 40   // smem row stride in halves (32 k + 8 pad -> conflict-free ldmatrix)

typedef unsigned short u16;
typedef unsigned int   u32;

// ---------------- scratch (device globals) -----------------------------------
__device__ __align__(16) u16 g_ith[(size_t)3 * BB * NN * DD];  // inputs^T hi [which][b][n][c]
__device__ __align__(16) u16 g_itl[(size_t)3 * BB * NN * DD];  // inputs^T lo
__device__ __align__(16) u16 g_wh[(size_t)4 * DD * DD];        // weights hi [which][o][c] (Wm col-permuted)
__device__ __align__(16) u16 g_wl[(size_t)4 * DD * DD];
__device__ __align__(16) u16 g_qh[(size_t)BB * HH * NN * DH];  // bf16 [b,h,n,d]
__device__ __align__(16) u16 g_ql[(size_t)BB * HH * NN * DH];
__device__ __align__(16) u16 g_kh[(size_t)BB * HH * NN * DH];  // bf16 [b,h,m,d]
__device__ __align__(16) u16 g_kl[(size_t)BB * HH * NN * DH];
__device__ __align__(16) u16 g_vh[(size_t)BB * HH * DH * NN];  // fp16 [b,h,d,m]
__device__ __align__(16) u16 g_vl[(size_t)BB * HH * DH * NN];  // fp16
__device__ __align__(16) u16 g_s16[(size_t)BB * HH * NN * NN]; // fp16 MASKED exp(s) [bh][n][m]
__device__ __align__(16) u16 g_xth[(size_t)BB * HH * NN * DH]; // PV out hi bf16 [b,h,n,d]
__device__ __align__(16) u16 g_xtl[(size_t)BB * HH * NN * DH];
__device__ __align__(16) unsigned char g_mask[(size_t)NN * NN];
__device__ u32 g_minenc;
__device__ u32 g_maskflags;

// ---------------- helpers ----------------------------------------------------
__device__ __forceinline__ u32 enc_f(float x) {
    u32 b = __float_as_uint(x);
    return (b & 0x80000000u) ? ~b : (b | 0x80000000u);
}
__device__ __forceinline__ float dec_f(u32 e) {
    return (e & 0x80000000u) ? __uint_as_float(e ^ 0x80000000u)
                             : __uint_as_float(~e);
}
__device__ __forceinline__ u16 b16hi(float x) {
    return __bfloat16_as_ushort(__float2bfloat16(x));
}
__device__ __forceinline__ u16 b16lo(float x) {
    float hf = __bfloat162float(__float2bfloat16(x));
    return __bfloat16_as_ushort(__float2bfloat16(x - hf));
}
__device__ __forceinline__ u16 f16hi(float x) {
    return __half_as_ushort(__float2half_rn(x));
}
__device__ __forceinline__ u16 f16lo(float x) {
    float hf = __half2float(__float2half_rn(x));
    return __half_as_ushort(__float2half_rn(x - hf));
}
__device__ __forceinline__ void cp16(u32 dst, const void* src) {
    asm volatile("cp.async.ca.shared.global [%0], [%1], 16;" :: "r"(dst), "l"(src));
}
#define CP_COMMIT() asm volatile("cp.async.commit_group;" ::: "memory")
#define CP_WAIT0()  asm volatile("cp.async.wait_group 0;" ::: "memory")
#define CP_WAIT1()  asm volatile("cp.async.wait_group 1;" ::: "memory")

__global__ void init_kernel() { g_minenc = 0xFFFFFFFFu; g_maskflags = 0u; }

// ---------------- mask dtype classification + normalization ------------------
__global__ void __launch_bounds__(256)
mask_classify_kernel(const u32* __restrict__ mw) {
    const int total = NN * NN / 4;
    u32 local = 0;
    for (int i = blockIdx.x * 256 + threadIdx.x; i < total; i += gridDim.x * 256) {
        u32 w = mw[i];
        if (w != 0u && w != 1u)          local |= 1u;
        if (w != 0u && w != 0x3f800000u) local |= 2u;
    }
#pragma unroll
    for (int o = 16; o > 0; o >>= 1) local |= __shfl_xor_sync(0xffffffffu, local, o);
    if ((threadIdx.x & 31) == 0 && local) atomicOr(&g_maskflags, local);
}

__global__ void __launch_bounds__(256)
mask_convert_kernel(const void* __restrict__ mraw) {
    const u32 f = g_maskflags;
    const int mode = ((f & 2u) == 0u) ? 2 : (((f & 1u) == 0u) ? 1 : 0);
    const int total = NN * NN;
    if (mode == 0) {
        const unsigned char* m8 = (const unsigned char*)mraw;
        for (int i = blockIdx.x * 256 + threadIdx.x; i < total; i += gridDim.x * 256)
            g_mask[i] = m8[i] ? 1 : 0;
    } else if (mode == 1) {
        const int* mi = (const int*)mraw;
        for (int i = blockIdx.x * 256 + threadIdx.x; i < total; i += gridDim.x * 256)
            g_mask[i] = mi[i] ? 1 : 0;
    } else {
        const float* mf = (const float*)mraw;
        for (int i = blockIdx.x * 256 + threadIdx.x; i < total; i += gridDim.x * 256)
            g_mask[i] = (mf[i] != 0.0f) ? 1 : 0;
    }
}

// ---------------- prepasses: split inputs/weights into bf16 planes -----------
__global__ void __launch_bounds__(256)
presplit_in_kernel(const float* __restrict__ q, const float* __restrict__ k,
                   const float* __restrict__ v) {
    __shared__ float tile[32][33];
    const int which = blockIdx.z >> 2, b = blockIdx.z & 3;
    const float* src = (which == 0 ? q : which == 1 ? k : v) + (size_t)b * DD * NN;
    const int n0 = blockIdx.x * 32, c0 = blockIdx.y * 32;
    const int tx = threadIdx.x, ty = threadIdx.y;  // 32 x 8
#pragma unroll
    for (int i = 0; i < 32; i += 8)
        tile[ty + i][tx] = src[(size_t)(c0 + ty + i) * NN + n0 + tx];
    __syncthreads();
    u16* dh = g_ith + (size_t)(which * BB + b) * NN * DD;
    u16* dl = g_itl + (size_t)(which * BB + b) * NN * DD;
#pragma unroll
    for (int i = 0; i < 32; i += 8) {
        float x = tile[tx][ty + i];
        size_t o = (size_t)(n0 + ty + i) * DD + c0 + tx;
        dh[o] = b16hi(x);
        dl[o] = b16lo(x);
    }
}

// Wm (w==3) columns permuted: c = d*8+h stored at c' = h*64+d.
__global__ void __launch_bounds__(256)
presplit_w_kernel(const float* __restrict__ Wq, const float* __restrict__ Wk,
                  const float* __restrict__ Wv, const float* __restrict__ Wm) {
    const int total = 4 * DD * DD;
    for (int i = blockIdx.x * 256 + threadIdx.x; i < total; i += gridDim.x * 256) {
        int w = i >> 18;
        int r = i & (DD * DD - 1);
        const float* src = (w == 0 ? Wq : w == 1 ? Wk : w == 2 ? Wv : Wm);
        float x = src[r];
        int dst = i;
        if (w == 3) {
            int o = r >> 9, c = r & 511;
            int d = c >> 3, h = c & 7;
            dst = (3 << 18) | (o << 9) | (h * 64 + d);
        }
        g_wh[dst] = b16hi(x);
        g_wl[dst] = b16lo(x);
    }
}

// ---------------- mma.sync machinery -----------------------------------------
__device__ __forceinline__ void ldm4(u32& r0, u32& r1, u32& r2, u32& r3, u32 addr) {
    asm volatile("ldmatrix.sync.aligned.m8n8.x4.shared.b16 {%0,%1,%2,%3}, [%4];"
                 : "=r"(r0), "=r"(r1), "=r"(r2), "=r"(r3) : "r"(addr));
}
__device__ __forceinline__ void mma16816(float* c, u32 a0, u32 a1, u32 a2, u32 a3,
                                         u32 b0, u32 b1) {
    asm volatile("mma.sync.aligned.m16n8k16.row.col.f32.bf16.bf16.f32 "
                 "{%0,%1,%2,%3}, {%4,%5,%6,%7}, {%8,%9}, {%0,%1,%2,%3};"
                 : "+f"(c[0]), "+f"(c[1]), "+f"(c[2]), "+f"(c[3])
                 : "r"(a0), "r"(a1), "r"(a2), "r"(a3), "r"(b0), "r"(b1));
}
__device__ __forceinline__ void mma16816h(float* c, u32 a0, u32 a1, u32 a2, u32 a3,
                                          u32 b0, u32 b1) {
    asm volatile("mma.sync.aligned.m16n8k16.row.col.f32.f16.f16.f32 "
                 "{%0,%1,%2,%3}, {%4,%5,%6,%7}, {%8,%9}, {%0,%1,%2,%3};"
                 : "+f"(c[0]), "+f"(c[1]), "+f"(c[2]), "+f"(c[3])
                 : "r"(a0), "r"(a1), "r"(a2), "r"(a3), "r"(b0), "r"(b1));
}
template <int SPS>
__device__ __forceinline__ u32 ldm_addr(u32 base, int lane, int row0, int col0) {
    int r = row0 + (lane & 7) + ((lane >> 3) & 1) * 8;
    int c = col0 + (lane >> 4) * 8;
    return base + (u32)(r * SPS + c) * 2u;
}
// One k16 step of split-bf16: acc += Ah*Bh + Ah*Bl + Al*Bh
template <int IM, int SPS>
__device__ __forceinline__ void mma_step(float (*acc)[4][4],
                                         u32 baAh, u32 baAl, u32 baBh, u32 baBl,
                                         int lane, int mBase, int nBase, int kk) {
    u32 A[IM][4], B[4][2], C[4][2];
    u32 x0, x1, x2, x3;
#pragma unroll
    for (int im = 0; im < IM; im++)
        ldm4(A[im][0], A[im][1], A[im][2], A[im][3],
             ldm_addr<SPS>(baAh, lane, mBase + im * 16, kk));
    ldm4(x0, x1, x2, x3, ldm_addr<SPS>(baBh, lane, nBase, kk));
    B[0][0] = x0; B[0][1] = x2; B[1][0] = x1; B[1][1] = x3;
    ldm4(x0, x1, x2, x3, ldm_addr<SPS>(baBh, lane, nBase + 16, kk));
    B[2][0] = x0; B[2][1] = x2; B[3][0] = x1; B[3][1] = x3;
#pragma unroll
    for (int im = 0; im < IM; im++)
#pragma unroll
        for (int jn = 0; jn < 4; jn++)
            mma16816(acc[im][jn], A[im][0], A[im][1], A[im][2], A[im][3], B[jn][0], B[jn][1]);
    ldm4(x0, x1, x2, x3, ldm_addr<SPS>(baBl, lane, nBase, kk));
    C[0][0] = x0; C[0][1] = x2; C[1][0] = x1; C[1][1] = x3;
    ldm4(x0, x1, x2, x3, ldm_addr<SPS>(baBl, lane, nBase + 16, kk));
    C[2][0] = x0; C[2][1] = x2; C[3][0] = x1; C[3][1] = x3;
#pragma unroll
    for (int im = 0; im < IM; im++)
#pragma unroll
        for (int jn = 0; jn < 4; jn++)
            mma16816(acc[im][jn], A[im][0], A[im][1], A[im][2], A[im][3], C[jn][0], C[jn][1]);
#pragma unroll
    for (int im = 0; im < IM; im++)
        ldm4(A[im][0], A[im][1], A[im][2], A[im][3],
             ldm_addr<SPS>(baAl, lane, mBase + im * 16, kk));
#pragma unroll
    for (int im = 0; im < IM; im++)
#pragma unroll
        for (int jn = 0; jn < 4; jn++)
            mma16816(acc[im][jn], A[im][0], A[im][1], A[im][2], A[im][3], B[jn][0], B[jn][1]);
}
// One k16 step fp16: acc += A*(Bh) + A*(Bl)  (A exact fp16; 2 combos)
template <int SPS>
__device__ __forceinline__ void pv_step(float (*acc)[4][4],
                                        u32 baP, u32 baVh, u32 baVl,
                                        int lane, int mBase, int nBase, int kk) {
    u32 A[2][4], B[4][2];
    u32 x0, x1, x2, x3;
#pragma unroll
    for (int im = 0; im < 2; im++)
        ldm4(A[im][0], A[im][1], A[im][2], A[im][3],
             ldm_addr<SPS>(baP, lane, mBase + im * 16, kk));
    ldm4(x0, x1, x2, x3, ldm_addr<SPS>(baVh, lane, nBase, kk));
    B[0][0] = x0; B[0][1] = x2; B[1][0] = x1; B[1][1] = x3;
    ldm4(x0, x1, x2, x3, ldm_addr<SPS>(baVh, lane, nBase + 16, kk));
    B[2][0] = x0; B[2][1] = x2; B[3][0] = x1; B[3][1] = x3;
#pragma unroll
    for (int im = 0; im < 2; im++)
#pragma unroll
        for (int jn = 0; jn < 4; jn++)
            mma16816h(acc[im][jn], A[im][0], A[im][1], A[im][2], A[im][3], B[jn][0], B[jn][1]);
    ldm4(x0, x1, x2, x3, ldm_addr<SPS>(baVl, lane, nBase, kk));
    B[0][0] = x0; B[0][1] = x2; B[1][0] = x1; B[1][1] = x3;
    ldm4(x0, x1, x2, x3, ldm_addr<SPS>(baVl, lane, nBase + 16, kk));
    B[2][0] = x0; B[2][1] = x2; B[3][0] = x1; B[3][1] = x3;
#pragma unroll
    for (int im = 0; im < 2; im++)
#pragma unroll
        for (int jn = 0; jn < 4; jn++)
            mma16816h(acc[im][jn], A[im][0], A[im][1], A[im][2], A[im][3], B[jn][0], B[jn][1]);
}

// ---------------- merged QKV projection (one launch, which = z>>2) -----------
#define PJ_BUF 30720
#define PJ_SMEM (2 * PJ_BUF)
__global__ void __launch_bounds__(256)
projqkv_kernel(const u16* __restrict__ ITh, const u16* __restrict__ ITl,
               const u16* __restrict__ WHp, const u16* __restrict__ WLp,
               const float* __restrict__ bq, const float* __restrict__ bk,
               const float* __restrict__ bv,
               u32* __restrict__ qh, u32* __restrict__ ql,
               u32* __restrict__ kh, u32* __restrict__ kl,
               u32* __restrict__ vh, u32* __restrict__ vl) {
    extern __shared__ __align__(16) char pjs[];
    const int z = blockIdx.z, which = z >> 2, b = z & 3;
    const int o0 = blockIdx.y * 64, n0 = blockIdx.x * 128;
    const int t = threadIdx.x, lane = t & 31, w = t >> 5;
    const int wm = w & 1, wn = w >> 1;
    const u16* Xh = ITh + (size_t)(which * BB + b) * NN * DD;
    const u16* Xl = ITl + (size_t)(which * BB + b) * NN * DD;
    const u16* Wh = WHp + (size_t)which * DD * DD;
    const u16* Wl = WLp + (size_t)which * DD * DD;
    const float* bias = (which == 0) ? bq : (which == 1) ? bk : bv;
    const int ar = t >> 2, as = (t & 3) * 8;
    const u32 sb = (u32)__cvta_generic_to_shared(pjs);

    uint4 pa0, pa1, pbh[2], pbl[2];
    float acc[2][4][4];
#pragma unroll
    for (int i = 0; i < 2; i++)
#pragma unroll
        for (int j = 0; j < 4; j++)
#pragma unroll
            for (int k = 0; k < 4; k++) acc[i][j][k] = 0.f;

    auto load_regs = [&](int c0) {
        pa0    = *(const uint4*)&Wh[(size_t)(o0 + ar) * DD + c0 + as];
        pa1    = *(const uint4*)&Wl[(size_t)(o0 + ar) * DD + c0 + as];
        pbh[0] = *(const uint4*)&Xh[(size_t)(n0 + ar) * DD + c0 + as];
        pbl[0] = *(const uint4*)&Xl[(size_t)(n0 + ar) * DD + c0 + as];
        pbh[1] = *(const uint4*)&Xh[(size_t)(n0 + ar + 64) * DD + c0 + as];
        pbl[1] = *(const uint4*)&Xl[(size_t)(n0 + ar + 64) * DD + c0 + as];
    };
    auto store_smem = [&](int buf) {
        char* base = pjs + buf * PJ_BUF;
        const int ro = (ar * PS + as) * 2;
        const int r1 = ((ar + 64) * PS + as) * 2;
        *(uint4*)(base + ro)             = pa0;
        *(uint4*)(base + 5120 + ro)      = pa1;
        *(uint4*)(base + 10240 + ro)     = pbh[0];
        *(uint4*)(base + 20480 + ro)     = pbl[0];
        *(uint4*)(base + 10240 + r1)     = pbh[1];
        *(uint4*)(base + 20480 + r1)     = pbl[1];
    };

    load_regs(0); store_smem(0); load_regs(32);
    __syncthreads();
    const int NC = DD / 32;  // 16
    for (int c = 0; c < NC; c++) {
        const int cur = c & 1;
        if (c + 1 < NC) store_smem(cur ^ 1);
        if (c + 2 < NC) load_regs((c + 2) * 32);
        const u32 bb = sb + cur * PJ_BUF;
        mma_step<2, PS>(acc, bb, bb + 5120, bb + 10240, bb + 20480, lane, wm * 32, wn * 32, 0);
        mma_step<2, PS>(acc, bb, bb + 5120, bb + 10240, bb + 20480, lane, wm * 32, wn * 32, 16);
        __syncthreads();
    }

    u32* Yh = (which == 0) ? qh : (which == 1) ? kh : vh;
    u32* Yl = (which == 0) ? ql : (which == 1) ? kl : vl;
#pragma unroll
    for (int im = 0; im < 2; im++) {
        const int ob = o0 + wm * 32 + im * 16 + (lane >> 2);
        const float bs0 = bias[ob], bs1 = bias[ob + 8];
#pragma unroll
        for (int jn = 0; jn < 4; jn++) {
            float* cc = acc[im][jn];
            const int n = n0 + wn * 32 + jn * 8 + 2 * (lane & 3);
            const float v0 = cc[0] + bs0, v1 = cc[1] + bs0;
            const float v2 = cc[2] + bs1, v3 = cc[3] + bs1;
            if (which < 2) {
                const int h = ob & 7, d = ob >> 3;
                size_t i0 = (((size_t)(b * HH + h) * NN + n) * DH + d) >> 1;
                Yh[i0]      = (u32)b16hi(v0) | ((u32)b16hi(v2) << 16);
                Yl[i0]      = (u32)b16lo(v0) | ((u32)b16lo(v2) << 16);
                Yh[i0 + 32] = (u32)b16hi(v1) | ((u32)b16hi(v3) << 16);
                Yl[i0 + 32] = (u32)b16lo(v1) | ((u32)b16lo(v3) << 16);
            } else {
                // V planes fp16 [b,h,d,m]
                const int h = ob & 7, d = ob >> 3;
                size_t i0 = (((size_t)(b * HH + h) * DH + d) * NN + n) >> 1;
                Yh[i0] = (u32)f16hi(v0) | ((u32)f16hi(v1) << 16);
                Yl[i0] = (u32)f16lo(v0) | ((u32)f16lo(v1) << 16);
                size_t i1 = i0 + (NN >> 1);
                Yh[i1] = (u32)f16hi(v2) | ((u32)f16hi(v3) << 16);
                Yl[i1] = (u32)f16lo(v2) | ((u32)f16lo(v3) << 16);
            }
        }
    }
}

// ---------------- final projection: X from [b,h,n,d] planes, Wm permuted -----
__global__ void __launch_bounds__(256)
proj0_kernel(const u16* __restrict__ XTh, const u16* __restrict__ XTl,
             const u16* __restrict__ Wh, const u16* __restrict__ Wl,
             const float* __restrict__ bias, float* __restrict__ Y) {
    extern __shared__ __align__(16) char pjs[];
    const int b = blockIdx.z, o0 = blockIdx.y * 64, n0 = blockIdx.x * 128;
    const int t = threadIdx.x, lane = t & 31, w = t >> 5;
    const int wm = w & 1, wn = w >> 1;
    const int ar = t >> 2, as = (t & 3) * 8;
    const u32 sb = (u32)__cvta_generic_to_shared(pjs);

    uint4 pa0, pa1, pbh[2], pbl[2];
    float acc[2][4][4];
#pragma unroll
    for (int i = 0; i < 2; i++)
#pragma unroll
        for (int j = 0; j < 4; j++)
#pragma unroll
            for (int k = 0; k < 4; k++) acc[i][j][k] = 0.f;

    auto load_regs = [&](int c0) {
        pa0 = *(const uint4*)&Wh[(size_t)(o0 + ar) * DD + c0 + as];
        pa1 = *(const uint4*)&Wl[(size_t)(o0 + ar) * DD + c0 + as];
        const int h = c0 >> 6, off = (c0 & 63) + as;
        const size_t hb = (size_t)(b * HH + h) * NN * DH;
        pbh[0] = *(const uint4*)&XTh[hb + (size_t)(n0 + ar) * DH + off];
        pbl[0] = *(const uint4*)&XTl[hb + (size_t)(n0 + ar) * DH + off];
        pbh[1] = *(const uint4*)&XTh[hb + (size_t)(n0 + ar + 64) * DH + off];
        pbl[1] = *(const uint4*)&XTl[hb + (size_t)(n0 + ar + 64) * DH + off];
    };
    auto store_smem = [&](int buf) {
        char* base = pjs + buf * PJ_BUF;
        const int ro = (ar * PS + as) * 2;
        const int r1 = ((ar + 64) * PS + as) * 2;
        *(uint4*)(base + ro)             = pa0;
        *(uint4*)(base + 5120 + ro)      = pa1;
        *(uint4*)(base + 10240 + ro)     = pbh[0];
        *(uint4*)(base + 20480 + ro)     = pbl[0];
        *(uint4*)(base + 10240 + r1)     = pbh[1];
        *(uint4*)(base + 20480 + r1)     = pbl[1];
    };

    load_regs(0); store_smem(0); load_regs(32);
    __syncthreads();
    const int NC = DD / 32;
    for (int c = 0; c < NC; c++) {
        const int cur = c & 1;
        if (c + 1 < NC) store_smem(cur ^ 1);
        if (c + 2 < NC) load_regs((c + 2) * 32);
        const u32 bb = sb + cur * PJ_BUF;
        mma_step<2, PS>(acc, bb, bb + 5120, bb + 10240, bb + 20480, lane, wm * 32, wn * 32, 0);
        mma_step<2, PS>(acc, bb, bb + 5120, bb + 10240, bb + 20480, lane, wm * 32, wn * 32, 16);
        __syncthreads();
    }

#pragma unroll
    for (int im = 0; im < 2; im++) {
        const int ob = o0 + wm * 32 + im * 16 + (lane >> 2);
        const float bs0 = bias[ob], bs1 = bias[ob + 8];
#pragma unroll
        for (int jn = 0; jn < 4; jn++) {
            float* cc = acc[im][jn];
            const int n = n0 + wn * 32 + jn * 8 + 2 * (lane & 3);
            *(float2*)&Y[((size_t)b * DD + ob) * NN + n]     = make_float2(cc[0] + bs0, cc[1] + bs0);
            *(float2*)&Y[((size_t)b * DD + ob + 8) * NN + n] = make_float2(cc[2] + bs1, cc[3] + bs1);
        }
    }
}

// ---------------- scores: head loop, fused out2, writes MASKED exp(s) --------
#define PS2 72
#define SC_PLANE (128 * PS2 * 2)              // 18432 B
#define SC_BUF   (4 * SC_PLANE)               // 73728 B
#define SC_MASK  (2 * SC_BUF)                 // mask tile offset
#define SC_SMEM  (2 * SC_BUF + 128 * 128)     // + 16KB mask tile = 163840 B
__global__ void __launch_bounds__(512)
scores_kernel(float* __restrict__ O2) {
    extern __shared__ __align__(16) char dsm[];
    __shared__ float sred[16];
    const int b = blockIdx.z, n0 = blockIdx.y * 128, m0 = blockIdx.x * 128;
    const int t = threadIdx.x, lane = t & 31, w = t >> 5;
    const int wm = w & 3, wn = w >> 2;   // warp tile 32(n) x 32(m)
    const u32 sbase = (u32)__cvta_generic_to_shared(dsm);
    const u16* smask = (const u16*)(dsm + SC_MASK);  // [128 n][128 m] bytes

    auto fill = [&](int buf, int h) {
        const size_t bh = (size_t)(b * HH + h);
        const u16* Qh = g_qh + bh * NN * DH;
        const u16* Ql = g_ql + bh * NN * DH;
        const u16* Kh = g_kh + bh * NN * DH;
        const u16* Kl = g_kl + bh * NN * DH;
        const u32 base = sbase + buf * SC_BUF;
#pragma unroll
        for (int rep = 0; rep < 2; rep++) {
            const int idx = t + rep * 512;
            const int row = idx >> 3, c8 = (idx & 7) * 8;
            const u32 off = (u32)(row * PS2 + c8) * 2u;
            cp16(base + off,                &Qh[(size_t)(n0 + row) * DH + c8]);
            cp16(base + SC_PLANE + off,     &Ql[(size_t)(n0 + row) * DH + c8]);
            cp16(base + 2 * SC_PLANE + off, &Kh[(size_t)(m0 + row) * DH + c8]);
            cp16(base + 3 * SC_PLANE + off, &Kl[(size_t)(m0 + row) * DH + c8]);
        }
        CP_COMMIT();
    };

    // mask tile: 128 rows x 128B = 1024 granules (lands with fill(0)'s group)
#pragma unroll
    for (int rep = 0; rep < 2; rep++) {
        const int idx = t + rep * 512;
        const int row = idx >> 3, c16 = (idx & 7) * 16;
        cp16(sbase + SC_MASK + (u32)(row * 128 + c16),
             g_mask + (size_t)(n0 + row) * NN + m0 + c16);
    }
    fill(0, 0);

    float s8[2][4][4];
#pragma unroll
    for (int i = 0; i < 2; i++)
#pragma unroll
        for (int j = 0; j < 4; j++)
#pragma unroll
            for (int k = 0; k < 4; k++) s8[i][j][k] = 0.f;
    float mn = __int_as_float(0x7f800000);

    for (int h = 0; h < HH; h++) {
        if (h > 0) __syncthreads();           // all reads of buf (h+1)&1 done
        if (h + 1 < HH) fill((h + 1) & 1, h + 1);
        if (h + 1 < HH) { CP_WAIT1(); } else { CP_WAIT0(); }
        __syncthreads();

        float acc[2][4][4];
#pragma unroll
        for (int i = 0; i < 2; i++)
#pragma unroll
            for (int j = 0; j < 4; j++)
#pragma unroll
                for (int k = 0; k < 4; k++) acc[i][j][k] = 0.f;

        const u32 bb = sbase + (h & 1) * SC_BUF;
#pragma unroll
        for (int kk = 0; kk < 64; kk += 16)
            mma_step<2, PS2>(acc, bb, bb + SC_PLANE, bb + 2 * SC_PLANE,
                             bb + 3 * SC_PLANE, lane, wm * 32, wn * 32, kk);

        const size_t bh = (size_t)(b * HH + h);
#pragma unroll
        for (int im = 0; im < 2; im++) {
            const int nl = wm * 32 + im * 16 + (lane >> 2);
            const int n = n0 + nl;
#pragma unroll
            for (int jn = 0; jn < 4; jn++) {
                float* cc = acc[im][jn];
                const int ml = wn * 32 + jn * 8 + 2 * (lane & 3);
                const int m = m0 + ml;
                float2 r0 = make_float2(cc[0] * 0.125f, cc[1] * 0.125f);
                float2 r1 = make_float2(cc[2] * 0.125f, cc[3] * 0.125f);
                mn = fminf(mn, fminf(fminf(r0.x, r0.y), fminf(r1.x, r1.y)));
                s8[im][jn][0] += r0.x; s8[im][jn][1] += r0.y;
                s8[im][jn][2] += r1.x; s8[im][jn][3] += r1.y;
                const u16 mk0 = smask[nl * 64 + (ml >> 1)];
                const u16 mk1 = smask[(nl + 8) * 64 + (ml >> 1)];
                float p0 = (mk0 & 0xff) ? __expf(r0.x) : 0.f;
                float p1 = (mk0 >> 8)   ? __expf(r0.y) : 0.f;
                float p2 = (mk1 & 0xff) ? __expf(r1.x) : 0.f;
                float p3 = (mk1 >> 8)   ? __expf(r1.y) : 0.f;
                __half2 h0 = __floats2half2_rn(p0, p1);
                __half2 h1 = __floats2half2_rn(p2, p3);
                *(u32*)&g_s16[(bh * NN + n) * NN + m]     = *(u32*)&h0;
                *(u32*)&g_s16[(bh * NN + n + 8) * NN + m] = *(u32*)&h1;
            }
        }
    }

    // out2 head-mean (pen added by fixup kernel after global min is final)
#pragma unroll
    for (int im = 0; im < 2; im++) {
        const int n = n0 + wm * 32 + im * 16 + (lane >> 2);
#pragma unroll
        for (int jn = 0; jn < 4; jn++) {
            float* ss = s8[im][jn];
            const int m = m0 + wn * 32 + jn * 8 + 2 * (lane & 3);
            *(float2*)&O2[((size_t)b * NN + n) * NN + m] =
                make_float2(ss[0] * 0.125f, ss[1] * 0.125f);
            *(float2*)&O2[((size_t)b * NN + n + 8) * NN + m] =
                make_float2(ss[2] * 0.125f, ss[3] * 0.125f);
        }
    }

#pragma unroll
    for (int o = 16; o > 0; o >>= 1) mn = fminf(mn, __shfl_xor_sync(0xffffffffu, mn, o));
    if (lane == 0) sred[w] = mn;
    __syncthreads();
    if (t == 0) {
        float v = sred[0];
#pragma unroll
        for (int i = 1; i < 16; i++) v = fminf(v, sred[i]);
        atomicMin(&g_minenc, enc_f(v));
    }
}

// ---------------- out2 pen fixup: O2 += pen * (~mask) ------------------------
__global__ void __launch_bounds__(256)
pen_fixup_kernel(float* __restrict__ O2) {
    const int idx = blockIdx.x * 256 + threadIdx.x;   // float4 index over [n][m]
    const int total = NN * NN / 4;
    if (idx >= total) return;
    const float pen = dec_f(g_minenc) - 20.0f;
    uchar4 mk = ((const uchar4*)g_mask)[idx];
    if (mk.x && mk.y && mk.z && mk.w) return;         // common case: no change
    float4 ad = make_float4(mk.x ? 0.f : pen, mk.y ? 0.f : pen,
                            mk.z ? 0.f : pen, mk.w ? 0.f : pen);
#pragma unroll
    for (int b = 0; b < BB; b++) {
        float4* p = (float4*)&O2[(size_t)b * NN * NN + idx * 4];
        float4 v = *p;
        v.x += ad.x; v.y += ad.y; v.z += ad.z; v.w += ad.w;
        *p = v;
    }
}

// ---------------- PV fp16: P raw copy, V via cp.async, 2-combo mma -----------
// per buffer: P 0 (10240B) | Vh 10240 (5120B) | Vl 15360 (5120B)
#define PV2_BUF 20480
#define PV2_SMEM (2 * PV2_BUF)
__global__ void __launch_bounds__(256)
pv_kernel() {
    extern __shared__ __align__(16) char pvs[];
    __shared__ float sSum[128];
    const int bh = blockIdx.y, n0 = blockIdx.x * 128;
    const int t = threadIdx.x, lane = t & 31, w = t >> 5;
    const int wm = w >> 1, wn = w & 1;
    const u16* Vh = g_vh + (size_t)bh * DH * NN;
    const u16* Vl = g_vl + (size_t)bh * DH * NN;
    const u32 sb = (u32)__cvta_generic_to_shared(pvs);

    const int pr = t >> 2, psv = (t & 3) * 8;
    const int rowA = n0 + pr, rowB = rowA + 64;
    const u16* SA = g_s16 + ((size_t)bh * NN + rowA) * NN;
    const u16* SB = g_s16 + ((size_t)bh * NN + rowB) * NN;

    uint4 psA, psB;
    float sumA = 0.f, sumB = 0.f;
    float acc[2][4][4];
#pragma unroll
    for (int i = 0; i < 2; i++)
#pragma unroll
        for (int j = 0; j < 4; j++)
#pragma unroll
            for (int k = 0; k < 4; k++) acc[i][j][k] = 0.f;

    auto load_P = [&](int m0c) {
        psA = *(const uint4*)&SA[m0c + psv];
        psB = *(const uint4*)&SB[m0c + psv];
    };
    // V tiles straight to smem via cp.async: 512 granules (2/thread)
    auto issue_V = [&](int m0c, int buf) {
        const u32 base = sb + buf * PV2_BUF;
#pragma unroll
        for (int rep = 0; rep < 2; rep++) {
            const int idx = t + rep * 256;
            const int pl = idx >> 8, r = (idx >> 2) & 63, g = (idx & 3) * 8;
            const u16* src = (pl ? Vl : Vh) + (size_t)r * NN + m0c + g;
            cp16(base + (pl ? 15360 : 10240) + (u32)(r * PS + g) * 2u, src);
        }
    };
    auto store_P = [&](int buf) {
        char* base = pvs + buf * PV2_BUF;
#pragma unroll
        for (int j = 0; j < 4; j++) {
            float2 fA = __half22float2(((const __half2*)&psA)[j]);
            sumA += fA.x + fA.y;
            float2 fB = __half22float2(((const __half2*)&psB)[j]);
            sumB += fB.x + fB.y;
        }
        *(uint4*)(base + (pr * PS + psv) * 2)        = psA;
        *(uint4*)(base + ((pr + 64) * PS + psv) * 2) = psB;
    };

    load_P(0);
    issue_V(0, 0);
    store_P(0);
    CP_COMMIT();
    load_P(32);
    CP_WAIT0();
    __syncthreads();

    const int NC = NN / 32;  // 48
    for (int c = 0; c < NC; c++) {
        const int cur = c & 1;
        if (c + 1 < NC) {
            issue_V((c + 1) * 32, cur ^ 1);
            store_P(cur ^ 1);
            CP_COMMIT();
        }
        if (c + 2 < NC) load_P((c + 2) * 32);
        const u32 bb = sb + cur * PV2_BUF;
        pv_step<PS>(acc, bb, bb + 10240, bb + 15360, lane, wm * 32, wn * 32, 0);
        pv_step<PS>(acc, bb, bb + 10240, bb + 15360, lane, wm * 32, wn * 32, 16);
        if (c + 1 < NC) CP_WAIT0();
        __syncthreads();
    }

    // row-sum reduce over the 4 threads sharing a row (lanes xor 1, 2)
    sumA += __shfl_xor_sync(0xffffffffu, sumA, 1);
    sumA += __shfl_xor_sync(0xffffffffu, sumA, 2);
    sumB += __shfl_xor_sync(0xffffffffu, sumB, 1);
    sumB += __shfl_xor_sync(0xffffffffu, sumB, 2);
    if ((t & 3) == 0) { sSum[pr] = sumA; sSum[pr + 64] = sumB; }
    __syncthreads();

    // epilogue: scale by 1/rowsum, packed u32 writes to [b,h,n,d] bf16 planes
    const int b = bh >> 3, h = bh & 7;
    u32* Xh32 = (u32*)g_xth;
    u32* Xl32 = (u32*)g_xtl;
    const size_t hb = (size_t)(b * HH + h) * NN * (DH / 2);
#pragma unroll
    for (int im = 0; im < 2; im++) {
        const int rl = wm * 32 + im * 16 + (lane >> 2);
        const int n = n0 + rl;
        const float iv0 = 1.0f / sSum[rl];
        const float iv1 = 1.0f / sSum[rl + 8];
#pragma unroll
        for (int jn = 0; jn < 4; jn++) {
            float* cc = acc[im][jn];
            const int d = wn * 32 + jn * 8 + 2 * (lane & 3);
            size_t r0 = hb + (size_t)n * (DH / 2) + (d >> 1);
            size_t r1 = r0 + (size_t)8 * (DH / 2);
            float a0 = cc[0] * iv0, a1 = cc[1] * iv0;
            float a2 = cc[2] * iv1, a3 = cc[3] * iv1;
            Xh32[r0] = (u32)b16hi(a0) | ((u32)b16hi(a1) << 16);
            Xl32[r0] = (u32)b16lo(a0) | ((u32)b16lo(a1) << 16);
            Xh32[r1] = (u32)b16hi(a2) | ((u32)b16hi(a3) << 16);
            Xl32[r1] = (u32)b16lo(a2) | ((u32)b16lo(a3) << 16);
        }
    }
}

// ---------------- launch ------------------------------------------------------
extern "C" void kernel_launch(void* const* d_in, const int* in_sizes, int n_in,
                              void* d_out, int out_size) {
    const float* query = (const float*)d_in[0];
    const float* key   = (const float*)d_in[1];
    const float* value = (const float*)d_in[2];
    // d_in[3] = dist (unused)
    const void* mask   = d_in[4];
    const float* Wq = (const float*)d_in[5];
    const float* bq = (const float*)d_in[6];
    const float* Wk = (const float*)d_in[7];
    const float* bk = (const float*)d_in[8];
    const float* Wv = (const float*)d_in[9];
    const float* bv = (const float*)d_in[10];
    const float* Wm = (const float*)d_in[11];
    const float* bm = (const float*)d_in[12];

    float* out  = (float*)d_out;                 // [B, D, N]
    float* out2 = out + (size_t)BB * DD * NN;    // [B, N, N]

    void *pih, *pil, *pwh, *pwl, *pqh, *pql, *pkh, *pkl, *pvh, *pvl, *pxth, *pxtl;
    cudaGetSymbolAddress(&pih, g_ith);
    cudaGetSymbolAddress(&pil, g_itl);
    cudaGetSymbolAddress(&pwh, g_wh);
    cudaGetSymbolAddress(&pwl, g_wl);
    cudaGetSymbolAddress(&pqh, g_qh);
    cudaGetSymbolAddress(&pql, g_ql);
    cudaGetSymbolAddress(&pkh, g_kh);
    cudaGetSymbolAddress(&pkl, g_kl);
    cudaGetSymbolAddress(&pvh, g_vh);
    cudaGetSymbolAddress(&pvl, g_vl);
    cudaGetSymbolAddress(&pxth, g_xth);
    cudaGetSymbolAddress(&pxtl, g_xtl);

    const u16* ith = (const u16*)pih;
    const u16* itl = (const u16*)pil;
    const u16* wh  = (const u16*)pwh;
    const u16* wl  = (const u16*)pwl;
    const size_t WB = (size_t)DD * DD;

    // One-time setup on the first (uncaptured) call: attrs, side stream, events.
    static cudaStream_t s2 = nullptr;
    static cudaEvent_t evA = nullptr, evB = nullptr, evC = nullptr, evD = nullptr;
    if (s2 == nullptr) {
        cudaFuncSetAttribute(scores_kernel,
                             cudaFuncAttributeMaxDynamicSharedMemorySize, SC_SMEM);
        cudaFuncSetAttribute(projqkv_kernel,
                             cudaFuncAttributeMaxDynamicSharedMemorySize, PJ_SMEM);
        cudaFuncSetAttribute(proj0_kernel,
                             cudaFuncAttributeMaxDynamicSharedMemorySize, PJ_SMEM);
        cudaFuncSetAttribute(pv_kernel,
                             cudaFuncAttributeMaxDynamicSharedMemorySize, PV2_SMEM);
        cudaStreamCreateWithFlags(&s2, cudaStreamNonBlocking);
        cudaEventCreateWithFlags(&evA, cudaEventDisableTiming);
        cudaEventCreateWithFlags(&evB, cudaEventDisableTiming);
        cudaEventCreateWithFlags(&evC, cudaEventDisableTiming);
        cudaEventCreateWithFlags(&evD, cudaEventDisableTiming);
    }

    init_kernel<<<1, 1>>>();
    cudaEventRecord(evA, 0);

    // side stream: mask dtype chain (consumed by scores & pen_fixup)
    cudaStreamWaitEvent(s2, evA, 0);
    mask_classify_kernel<<<256, 256, 0, s2>>>((const u32*)mask);
    mask_convert_kernel<<<256, 256, 0, s2>>>(mask);
    cudaEventRecord(evB, s2);

    // main stream: presplits + QKV projection (independent of mask)
    presplit_in_kernel<<<dim3(NN / 32, DD / 32, 3 * BB), dim3(32, 8)>>>(query, key, value);
    presplit_w_kernel<<<1024, 256>>>(Wq, Wk, Wv, Wm);
    projqkv_kernel<<<dim3(NN / 128, DD / 64, 3 * BB), 256, PJ_SMEM>>>(
        ith, itl, wh, wl, bq, bk, bv,
        (u32*)pqh, (u32*)pql, (u32*)pkh, (u32*)pkl, (u32*)pvh, (u32*)pvl);

    cudaStreamWaitEvent(0, evB, 0);   // mask ready before scores
    scores_kernel<<<dim3(NN / 128, NN / 128, BB), 512, SC_SMEM>>>(out2);
    cudaEventRecord(evC, 0);

    // side stream: out2 penalty fixup (|| pv + proj0)
    cudaStreamWaitEvent(s2, evC, 0);
    pen_fixup_kernel<<<(NN * NN / 4 + 255) / 256, 256, 0, s2>>>(out2);
    cudaEventRecord(evD, s2);

    pv_kernel<<<dim3(NN / 128, BB * HH), 256, PV2_SMEM>>>();
    proj0_kernel<<<dim3(NN / 128, DD / 64, BB), 256, PJ_SMEM>>>(
        (const u16*)pxth, (const u16*)pxtl, wh + 3 * WB, wl + 3 * WB, bm, out);

    cudaStreamWaitEvent(0, evD, 0);   // join side stream before capture ends
}

// round 17
// speedup vs baseline: 1.4015x; 1.0049x over previous
#include <cuda_runtime.h>
#include <cuda_bf16.h>
#include <cuda_fp16.h>
#include <cstdint>

#define BB 4
#define DD 512
#define NN 1536
#define HH 8
#define DH 64
#define PS 40   // smem row stride in halves (32 k + 8 pad -> conflict-free ldmatrix)

typedef unsigned short u16;
typedef unsigned int   u32;

// ---------------- scratch (device globals) -----------------------------------
__device__ __align__(16) u16 g_ith[(size_t)3 * BB * NN * DD];  // inputs^T hi [which][b][n][c]
__device__ __align__(16) u16 g_itl[(size_t)3 * BB * NN * DD];  // inputs^T lo
__device__ __align__(16) u16 g_wh[(size_t)4 * DD * DD];        // weights hi [which][o][c] (Wm col-permuted)
__device__ __align__(16) u16 g_wl[(size_t)4 * DD * DD];
__device__ __align__(16) u16 g_qh[(size_t)BB * HH * NN * DH];  // bf16 [b,h,n,d]
__device__ __align__(16) u16 g_ql[(size_t)BB * HH * NN * DH];
__device__ __align__(16) u16 g_kh[(size_t)BB * HH * NN * DH];  // bf16 [b,h,m,d]
__device__ __align__(16) u16 g_kl[(size_t)BB * HH * NN * DH];
__device__ __align__(16) u16 g_vh[(size_t)BB * HH * DH * NN];  // fp16 [b,h,d,m]
__device__ __align__(16) u16 g_vl[(size_t)BB * HH * DH * NN];  // fp16
__device__ __align__(16) u16 g_s16[(size_t)BB * HH * NN * NN]; // fp16 MASKED exp(s) [bh][n][m]
__device__ __align__(16) u16 g_xth[(size_t)BB * HH * NN * DH]; // PV out hi bf16 [b,h,n,d]
__device__ __align__(16) u16 g_xtl[(size_t)BB * HH * NN * DH];
__device__ __align__(16) unsigned char g_mask[(size_t)NN * NN];
__device__ u32 g_minenc;
__device__ u32 g_maskflags;

// ---------------- helpers ----------------------------------------------------
__device__ __forceinline__ u32 enc_f(float x) {
    u32 b = __float_as_uint(x);
    return (b & 0x80000000u) ? ~b : (b | 0x80000000u);
}
__device__ __forceinline__ float dec_f(u32 e) {
    return (e & 0x80000000u) ? __uint_as_float(e ^ 0x80000000u)
                             : __uint_as_float(~e);
}
__device__ __forceinline__ u16 b16hi(float x) {
    return __bfloat16_as_ushort(__float2bfloat16(x));
}
__device__ __forceinline__ u16 b16lo(float x) {
    float hf = __bfloat162float(__float2bfloat16(x));
    return __bfloat16_as_ushort(__float2bfloat16(x - hf));
}
__device__ __forceinline__ u16 f16hi(float x) {
    return __half_as_ushort(__float2half_rn(x));
}
__device__ __forceinline__ u16 f16lo(float x) {
    float hf = __half2float(__float2half_rn(x));
    return __half_as_ushort(__float2half_rn(x - hf));
}
__device__ __forceinline__ void cp16(u32 dst, const void* src) {
    asm volatile("cp.async.ca.shared.global [%0], [%1], 16;" :: "r"(dst), "l"(src));
}
#define CP_COMMIT() asm volatile("cp.async.commit_group;" ::: "memory")
#define CP_WAIT0()  asm volatile("cp.async.wait_group 0;" ::: "memory")
#define CP_WAIT1()  asm volatile("cp.async.wait_group 1;" ::: "memory")

__global__ void init_kernel() { g_minenc = 0xFFFFFFFFu; g_maskflags = 0u; }

// ---------------- mask dtype classification + normalization ------------------
__global__ void __launch_bounds__(256)
mask_classify_kernel(const u32* __restrict__ mw) {
    const int total = NN * NN / 4;
    u32 local = 0;
    for (int i = blockIdx.x * 256 + threadIdx.x; i < total; i += gridDim.x * 256) {
        u32 w = mw[i];
        if (w != 0u && w != 1u)          local |= 1u;
        if (w != 0u && w != 0x3f800000u) local |= 2u;
    }
#pragma unroll
    for (int o = 16; o > 0; o >>= 1) local |= __shfl_xor_sync(0xffffffffu, local, o);
    if ((threadIdx.x & 31) == 0 && local) atomicOr(&g_maskflags, local);
}

__global__ void __launch_bounds__(256)
mask_convert_kernel(const void* __restrict__ mraw) {
    const u32 f = g_maskflags;
    const int mode = ((f & 2u) == 0u) ? 2 : (((f & 1u) == 0u) ? 1 : 0);
    const int total = NN * NN;
    if (mode == 0) {
        const unsigned char* m8 = (const unsigned char*)mraw;
        for (int i = blockIdx.x * 256 + threadIdx.x; i < total; i += gridDim.x * 256)
            g_mask[i] = m8[i] ? 1 : 0;
    } else if (mode == 1) {
        const int* mi = (const int*)mraw;
        for (int i = blockIdx.x * 256 + threadIdx.x; i < total; i += gridDim.x * 256)
            g_mask[i] = mi[i] ? 1 : 0;
    } else {
        const float* mf = (const float*)mraw;
        for (int i = blockIdx.x * 256 + threadIdx.x; i < total; i += gridDim.x * 256)
            g_mask[i] = (mf[i] != 0.0f) ? 1 : 0;
    }
}

// ---------------- prepasses: split inputs/weights into bf16 planes -----------
__global__ void __launch_bounds__(256)
presplit_in_kernel(const float* __restrict__ q, const float* __restrict__ k,
                   const float* __restrict__ v) {
    __shared__ float tile[32][33];
    const int which = blockIdx.z >> 2, b = blockIdx.z & 3;
    const float* src = (which == 0 ? q : which == 1 ? k : v) + (size_t)b * DD * NN;
    const int n0 = blockIdx.x * 32, c0 = blockIdx.y * 32;
    const int tx = threadIdx.x, ty = threadIdx.y;  // 32 x 8
#pragma unroll
    for (int i = 0; i < 32; i += 8)
        tile[ty + i][tx] = src[(size_t)(c0 + ty + i) * NN + n0 + tx];
    __syncthreads();
    u16* dh = g_ith + (size_t)(which * BB + b) * NN * DD;
    u16* dl = g_itl + (size_t)(which * BB + b) * NN * DD;
#pragma unroll
    for (int i = 0; i < 32; i += 8) {
        float x = tile[tx][ty + i];
        size_t o = (size_t)(n0 + ty + i) * DD + c0 + tx;
        dh[o] = b16hi(x);
        dl[o] = b16lo(x);
    }
}

// Wm (w==3) columns permuted: c = d*8+h stored at c' = h*64+d.
__global__ void __launch_bounds__(256)
presplit_w_kernel(const float* __restrict__ Wq, const float* __restrict__ Wk,
                  const float* __restrict__ Wv, const float* __restrict__ Wm) {
    const int total = 4 * DD * DD;
    for (int i = blockIdx.x * 256 + threadIdx.x; i < total; i += gridDim.x * 256) {
        int w = i >> 18;
        int r = i & (DD * DD - 1);
        const float* src = (w == 0 ? Wq : w == 1 ? Wk : w == 2 ? Wv : Wm);
        float x = src[r];
        int dst = i;
        if (w == 3) {
            int o = r >> 9, c = r & 511;
            int d = c >> 3, h = c & 7;
            dst = (3 << 18) | (o << 9) | (h * 64 + d);
        }
        g_wh[dst] = b16hi(x);
        g_wl[dst] = b16lo(x);
    }
}

// ---------------- mma.sync machinery -----------------------------------------
__device__ __forceinline__ void ldm4(u32& r0, u32& r1, u32& r2, u32& r3, u32 addr) {
    asm volatile("ldmatrix.sync.aligned.m8n8.x4.shared.b16 {%0,%1,%2,%3}, [%4];"
                 : "=r"(r0), "=r"(r1), "=r"(r2), "=r"(r3) : "r"(addr));
}
__device__ __forceinline__ void mma16816(float* c, u32 a0, u32 a1, u32 a2, u32 a3,
                                         u32 b0, u32 b1) {
    asm volatile("mma.sync.aligned.m16n8k16.row.col.f32.bf16.bf16.f32 "
                 "{%0,%1,%2,%3}, {%4,%5,%6,%7}, {%8,%9}, {%0,%1,%2,%3};"
                 : "+f"(c[0]), "+f"(c[1]), "+f"(c[2]), "+f"(c[3])
                 : "r"(a0), "r"(a1), "r"(a2), "r"(a3), "r"(b0), "r"(b1));
}
__device__ __forceinline__ void mma16816h(float* c, u32 a0, u32 a1, u32 a2, u32 a3,
                                          u32 b0, u32 b1) {
    asm volatile("mma.sync.aligned.m16n8k16.row.col.f32.f16.f16.f32 "
                 "{%0,%1,%2,%3}, {%4,%5,%6,%7}, {%8,%9}, {%0,%1,%2,%3};"
                 : "+f"(c[0]), "+f"(c[1]), "+f"(c[2]), "+f"(c[3])
                 : "r"(a0), "r"(a1), "r"(a2), "r"(a3), "r"(b0), "r"(b1));
}
template <int SPS>
__device__ __forceinline__ u32 ldm_addr(u32 base, int lane, int row0, int col0) {
    int r = row0 + (lane & 7) + ((lane >> 3) & 1) * 8;
    int c = col0 + (lane >> 4) * 8;
    return base + (u32)(r * SPS + c) * 2u;
}
// One k16 step of split-bf16: acc += Ah*Bh + Ah*Bl + Al*Bh
template <int IM, int SPS>
__device__ __forceinline__ void mma_step(float (*acc)[4][4],
                                         u32 baAh, u32 baAl, u32 baBh, u32 baBl,
                                         int lane, int mBase, int nBase, int kk) {
    u32 A[IM][4], B[4][2], C[4][2];
    u32 x0, x1, x2, x3;
#pragma unroll
    for (int im = 0; im < IM; im++)
        ldm4(A[im][0], A[im][1], A[im][2], A[im][3],
             ldm_addr<SPS>(baAh, lane, mBase + im * 16, kk));
    ldm4(x0, x1, x2, x3, ldm_addr<SPS>(baBh, lane, nBase, kk));
    B[0][0] = x0; B[0][1] = x2; B[1][0] = x1; B[1][1] = x3;
    ldm4(x0, x1, x2, x3, ldm_addr<SPS>(baBh, lane, nBase + 16, kk));
    B[2][0] = x0; B[2][1] = x2; B[3][0] = x1; B[3][1] = x3;
#pragma unroll
    for (int im = 0; im < IM; im++)
#pragma unroll
        for (int jn = 0; jn < 4; jn++)
            mma16816(acc[im][jn], A[im][0], A[im][1], A[im][2], A[im][3], B[jn][0], B[jn][1]);
    ldm4(x0, x1, x2, x3, ldm_addr<SPS>(baBl, lane, nBase, kk));
    C[0][0] = x0; C[0][1] = x2; C[1][0] = x1; C[1][1] = x3;
    ldm4(x0, x1, x2, x3, ldm_addr<SPS>(baBl, lane, nBase + 16, kk));
    C[2][0] = x0; C[2][1] = x2; C[3][0] = x1; C[3][1] = x3;
#pragma unroll
    for (int im = 0; im < IM; im++)
#pragma unroll
        for (int jn = 0; jn < 4; jn++)
            mma16816(acc[im][jn], A[im][0], A[im][1], A[im][2], A[im][3], C[jn][0], C[jn][1]);
#pragma unroll
    for (int im = 0; im < IM; im++)
        ldm4(A[im][0], A[im][1], A[im][2], A[im][3],
             ldm_addr<SPS>(baAl, lane, mBase + im * 16, kk));
#pragma unroll
    for (int im = 0; im < IM; im++)
#pragma unroll
        for (int jn = 0; jn < 4; jn++)
            mma16816(acc[im][jn], A[im][0], A[im][1], A[im][2], A[im][3], B[jn][0], B[jn][1]);
}
// One k16 step fp16: acc += A*(Bh) + A*(Bl)  (A exact fp16; 2 combos)
template <int SPS>
__device__ __forceinline__ void pv_step(float (*acc)[4][4],
                                        u32 baP, u32 baVh, u32 baVl,
                                        int lane, int mBase, int nBase, int kk) {
    u32 A[2][4], B[4][2];
    u32 x0, x1, x2, x3;
#pragma unroll
    for (int im = 0; im < 2; im++)
        ldm4(A[im][0], A[im][1], A[im][2], A[im][3],
             ldm_addr<SPS>(baP, lane, mBase + im * 16, kk));
    ldm4(x0, x1, x2, x3, ldm_addr<SPS>(baVh, lane, nBase, kk));
    B[0][0] = x0; B[0][1] = x2; B[1][0] = x1; B[1][1] = x3;
    ldm4(x0, x1, x2, x3, ldm_addr<SPS>(baVh, lane, nBase + 16, kk));
    B[2][0] = x0; B[2][1] = x2; B[3][0] = x1; B[3][1] = x3;
#pragma unroll
    for (int im = 0; im < 2; im++)
#pragma unroll
        for (int jn = 0; jn < 4; jn++)
            mma16816h(acc[im][jn], A[im][0], A[im][1], A[im][2], A[im][3], B[jn][0], B[jn][1]);
    ldm4(x0, x1, x2, x3, ldm_addr<SPS>(baVl, lane, nBase, kk));
    B[0][0] = x0; B[0][1] = x2; B[1][0] = x1; B[1][1] = x3;
    ldm4(x0, x1, x2, x3, ldm_addr<SPS>(baVl, lane, nBase + 16, kk));
    B[2][0] = x0; B[2][1] = x2; B[3][0] = x1; B[3][1] = x3;
#pragma unroll
    for (int im = 0; im < 2; im++)
#pragma unroll
        for (int jn = 0; jn < 4; jn++)
            mma16816h(acc[im][jn], A[im][0], A[im][1], A[im][2], A[im][3], B[jn][0], B[jn][1]);
}

// ---------------- QKV projection (which = wbase + z>>2) ----------------------
#define PJ_BUF 30720
#define PJ_SMEM (2 * PJ_BUF)
__global__ void __launch_bounds__(256)
projqkv_kernel(int wbase,
               const u16* __restrict__ ITh, const u16* __restrict__ ITl,
               const u16* __restrict__ WHp, const u16* __restrict__ WLp,
               const float* __restrict__ bq, const float* __restrict__ bk,
               const float* __restrict__ bv,
               u32* __restrict__ qh, u32* __restrict__ ql,
               u32* __restrict__ kh, u32* __restrict__ kl,
               u32* __restrict__ vh, u32* __restrict__ vl) {
    extern __shared__ __align__(16) char pjs[];
    const int z = blockIdx.z, which = wbase + (z >> 2), b = z & 3;
    const int o0 = blockIdx.y * 64, n0 = blockIdx.x * 128;
    const int t = threadIdx.x, lane = t & 31, w = t >> 5;
    const int wm = w & 1, wn = w >> 1;
    const u16* Xh = ITh + (size_t)(which * BB + b) * NN * DD;
    const u16* Xl = ITl + (size_t)(which * BB + b) * NN * DD;
    const u16* Wh = WHp + (size_t)which * DD * DD;
    const u16* Wl = WLp + (size_t)which * DD * DD;
    const float* bias = (which == 0) ? bq : (which == 1) ? bk : bv;
    const int ar = t >> 2, as = (t & 3) * 8;
    const u32 sb = (u32)__cvta_generic_to_shared(pjs);

    uint4 pa0, pa1, pbh[2], pbl[2];
    float acc[2][4][4];
#pragma unroll
    for (int i = 0; i < 2; i++)
#pragma unroll
        for (int j = 0; j < 4; j++)
#pragma unroll
            for (int k = 0; k < 4; k++) acc[i][j][k] = 0.f;

    auto load_regs = [&](int c0) {
        pa0    = *(const uint4*)&Wh[(size_t)(o0 + ar) * DD + c0 + as];
        pa1    = *(const uint4*)&Wl[(size_t)(o0 + ar) * DD + c0 + as];
        pbh[0] = *(const uint4*)&Xh[(size_t)(n0 + ar) * DD + c0 + as];
        pbl[0] = *(const uint4*)&Xl[(size_t)(n0 + ar) * DD + c0 + as];
        pbh[1] = *(const uint4*)&Xh[(size_t)(n0 + ar + 64) * DD + c0 + as];
        pbl[1] = *(const uint4*)&Xl[(size_t)(n0 + ar + 64) * DD + c0 + as];
    };
    auto store_smem = [&](int buf) {
        char* base = pjs + buf * PJ_BUF;
        const int ro = (ar * PS + as) * 2;
        const int r1 = ((ar + 64) * PS + as) * 2;
        *(uint4*)(base + ro)             = pa0;
        *(uint4*)(base + 5120 + ro)      = pa1;
        *(uint4*)(base + 10240 + ro)     = pbh[0];
        *(uint4*)(base + 20480 + ro)     = pbl[0];
        *(uint4*)(base + 10240 + r1)     = pbh[1];
        *(uint4*)(base + 20480 + r1)     = pbl[1];
    };

    load_regs(0); store_smem(0); load_regs(32);
    __syncthreads();
    const int NC = DD / 32;  // 16
    for (int c = 0; c < NC; c++) {
        const int cur = c & 1;
        if (c + 1 < NC) store_smem(cur ^ 1);
        if (c + 2 < NC) load_regs((c + 2) * 32);
        const u32 bb = sb + cur * PJ_BUF;
        mma_step<2, PS>(acc, bb, bb + 5120, bb + 10240, bb + 20480, lane, wm * 32, wn * 32, 0);
        mma_step<2, PS>(acc, bb, bb + 5120, bb + 10240, bb + 20480, lane, wm * 32, wn * 32, 16);
        __syncthreads();
    }

    u32* Yh = (which == 0) ? qh : (which == 1) ? kh : vh;
    u32* Yl = (which == 0) ? ql : (which == 1) ? kl : vl;
#pragma unroll
    for (int im = 0; im < 2; im++) {
        const int ob = o0 + wm * 32 + im * 16 + (lane >> 2);
        const float bs0 = bias[ob], bs1 = bias[ob + 8];
#pragma unroll
        for (int jn = 0; jn < 4; jn++) {
            float* cc = acc[im][jn];
            const int n = n0 + wn * 32 + jn * 8 + 2 * (lane & 3);
            const float v0 = cc[0] + bs0, v1 = cc[1] + bs0;
            const float v2 = cc[2] + bs1, v3 = cc[3] + bs1;
            if (which < 2) {
                const int h = ob & 7, d = ob >> 3;
                size_t i0 = (((size_t)(b * HH + h) * NN + n) * DH + d) >> 1;
                Yh[i0]      = (u32)b16hi(v0) | ((u32)b16hi(v2) << 16);
                Yl[i0]      = (u32)b16lo(v0) | ((u32)b16lo(v2) << 16);
                Yh[i0 + 32] = (u32)b16hi(v1) | ((u32)b16hi(v3) << 16);
                Yl[i0 + 32] = (u32)b16lo(v1) | ((u32)b16lo(v3) << 16);
            } else {
                // V planes fp16 [b,h,d,m]
                const int h = ob & 7, d = ob >> 3;
                size_t i0 = (((size_t)(b * HH + h) * DH + d) * NN + n) >> 1;
                Yh[i0] = (u32)f16hi(v0) | ((u32)f16hi(v1) << 16);
                Yl[i0] = (u32)f16lo(v0) | ((u32)f16lo(v1) << 16);
                size_t i1 = i0 + (NN >> 1);
                Yh[i1] = (u32)f16hi(v2) | ((u32)f16hi(v3) << 16);
                Yl[i1] = (u32)f16lo(v2) | ((u32)f16lo(v3) << 16);
            }
        }
    }
}

// ---------------- final projection: X from [b,h,n,d] planes, Wm permuted -----
__global__ void __launch_bounds__(256)
proj0_kernel(const u16* __restrict__ XTh, const u16* __restrict__ XTl,
             const u16* __restrict__ Wh, const u16* __restrict__ Wl,
             const float* __restrict__ bias, float* __restrict__ Y) {
    extern __shared__ __align__(16) char pjs[];
    const int b = blockIdx.z, o0 = blockIdx.y * 64, n0 = blockIdx.x * 128;
    const int t = threadIdx.x, lane = t & 31, w = t >> 5;
    const int wm = w & 1, wn = w >> 1;
    const int ar = t >> 2, as = (t & 3) * 8;
    const u32 sb = (u32)__cvta_generic_to_shared(pjs);

    uint4 pa0, pa1, pbh[2], pbl[2];
    float acc[2][4][4];
#pragma unroll
    for (int i = 0; i < 2; i++)
#pragma unroll
        for (int j = 0; j < 4; j++)
#pragma unroll
            for (int k = 0; k < 4; k++) acc[i][j][k] = 0.f;

    auto load_regs = [&](int c0) {
        pa0 = *(const uint4*)&Wh[(size_t)(o0 + ar) * DD + c0 + as];
        pa1 = *(const uint4*)&Wl[(size_t)(o0 + ar) * DD + c0 + as];
        const int h = c0 >> 6, off = (c0 & 63) + as;
        const size_t hb = (size_t)(b * HH + h) * NN * DH;
        pbh[0] = *(const uint4*)&XTh[hb + (size_t)(n0 + ar) * DH + off];
        pbl[0] = *(const uint4*)&XTl[hb + (size_t)(n0 + ar) * DH + off];
        pbh[1] = *(const uint4*)&XTh[hb + (size_t)(n0 + ar + 64) * DH + off];
        pbl[1] = *(const uint4*)&XTl[hb + (size_t)(n0 + ar + 64) * DH + off];
    };
    auto store_smem = [&](int buf) {
        char* base = pjs + buf * PJ_BUF;
        const int ro = (ar * PS + as) * 2;
        const int r1 = ((ar + 64) * PS + as) * 2;
        *(uint4*)(base + ro)             = pa0;
        *(uint4*)(base + 5120 + ro)      = pa1;
        *(uint4*)(base + 10240 + ro)     = pbh[0];
        *(uint4*)(base + 20480 + ro)     = pbl[0];
        *(uint4*)(base + 10240 + r1)     = pbh[1];
        *(uint4*)(base + 20480 + r1)     = pbl[1];
    };

    load_regs(0); store_smem(0); load_regs(32);
    __syncthreads();
    const int NC = DD / 32;
    for (int c = 0; c < NC; c++) {
        const int cur = c & 1;
        if (c + 1 < NC) store_smem(cur ^ 1);
        if (c + 2 < NC) load_regs((c + 2) * 32);
        const u32 bb = sb + cur * PJ_BUF;
        mma_step<2, PS>(acc, bb, bb + 5120, bb + 10240, bb + 20480, lane, wm * 32, wn * 32, 0);
        mma_step<2, PS>(acc, bb, bb + 5120, bb + 10240, bb + 20480, lane, wm * 32, wn * 32, 16);
        __syncthreads();
    }

#pragma unroll
    for (int im = 0; im < 2; im++) {
        const int ob = o0 + wm * 32 + im * 16 + (lane >> 2);
        const float bs0 = bias[ob], bs1 = bias[ob + 8];
#pragma unroll
        for (int jn = 0; jn < 4; jn++) {
            float* cc = acc[im][jn];
            const int n = n0 + wn * 32 + jn * 8 + 2 * (lane & 3);
            *(float2*)&Y[((size_t)b * DD + ob) * NN + n]     = make_float2(cc[0] + bs0, cc[1] + bs0);
            *(float2*)&Y[((size_t)b * DD + ob + 8) * NN + n] = make_float2(cc[2] + bs1, cc[3] + bs1);
        }
    }
}

// ---------------- scores: head loop, fused out2, writes MASKED exp(s) --------
#define PS2 72
#define SC_PLANE (128 * PS2 * 2)              // 18432 B
#define SC_BUF   (4 * SC_PLANE)               // 73728 B
#define SC_MASK  (2 * SC_BUF)                 // mask tile offset
#define SC_SMEM  (2 * SC_BUF + 128 * 128)     // + 16KB mask tile = 163840 B
__global__ void __launch_bounds__(512)
scores_kernel(float* __restrict__ O2) {
    extern __shared__ __align__(16) char dsm[];
    __shared__ float sred[16];
    const int b = blockIdx.z, n0 = blockIdx.y * 128, m0 = blockIdx.x * 128;
    const int t = threadIdx.x, lane = t & 31, w = t >> 5;
    const int wm = w & 3, wn = w >> 2;   // warp tile 32(n) x 32(m)
    const u32 sbase = (u32)__cvta_generic_to_shared(dsm);
    const u16* smask = (const u16*)(dsm + SC_MASK);  // [128 n][128 m] bytes

    auto fill = [&](int buf, int h) {
        const size_t bh = (size_t)(b * HH + h);
        const u16* Qh = g_qh + bh * NN * DH;
        const u16* Ql = g_ql + bh * NN * DH;
        const u16* Kh = g_kh + bh * NN * DH;
        const u16* Kl = g_kl + bh * NN * DH;
        const u32 base = sbase + buf * SC_BUF;
#pragma unroll
        for (int rep = 0; rep < 2; rep++) {
            const int idx = t + rep * 512;
            const int row = idx >> 3, c8 = (idx & 7) * 8;
            const u32 off = (u32)(row * PS2 + c8) * 2u;
            cp16(base + off,                &Qh[(size_t)(n0 + row) * DH + c8]);
            cp16(base + SC_PLANE + off,     &Ql[(size_t)(n0 + row) * DH + c8]);
            cp16(base + 2 * SC_PLANE + off, &Kh[(size_t)(m0 + row) * DH + c8]);
            cp16(base + 3 * SC_PLANE + off, &Kl[(size_t)(m0 + row) * DH + c8]);
        }
        CP_COMMIT();
    };

    // mask tile: 128 rows x 128B = 1024 granules (lands with fill(0)'s group)
#pragma unroll
    for (int rep = 0; rep < 2; rep++) {
        const int idx = t + rep * 512;
        const int row = idx >> 3, c16 = (idx & 7) * 16;
        cp16(sbase + SC_MASK + (u32)(row * 128 + c16),
             g_mask + (size_t)(n0 + row) * NN + m0 + c16);
    }
    fill(0, 0);

    float s8[2][4][4];
#pragma unroll
    for (int i = 0; i < 2; i++)
#pragma unroll
        for (int j = 0; j < 4; j++)
#pragma unroll
            for (int k = 0; k < 4; k++) s8[i][j][k] = 0.f;
    float mn = __int_as_float(0x7f800000);

    for (int h = 0; h < HH; h++) {
        if (h > 0) __syncthreads();           // all reads of buf (h+1)&1 done
        if (h + 1 < HH) fill((h + 1) & 1, h + 1);
        if (h + 1 < HH) { CP_WAIT1(); } else { CP_WAIT0(); }
        __syncthreads();

        float acc[2][4][4];
#pragma unroll
        for (int i = 0; i < 2; i++)
#pragma unroll
            for (int j = 0; j < 4; j++)
#pragma unroll
                for (int k = 0; k < 4; k++) acc[i][j][k] = 0.f;

        const u32 bb = sbase + (h & 1) * SC_BUF;
#pragma unroll
        for (int kk = 0; kk < 64; kk += 16)
            mma_step<2, PS2>(acc, bb, bb + SC_PLANE, bb + 2 * SC_PLANE,
                             bb + 3 * SC_PLANE, lane, wm * 32, wn * 32, kk);

        const size_t bh = (size_t)(b * HH + h);
#pragma unroll
        for (int im = 0; im < 2; im++) {
            const int nl = wm * 32 + im * 16 + (lane >> 2);
            const int n = n0 + nl;
#pragma unroll
            for (int jn = 0; jn < 4; jn++) {
                float* cc = acc[im][jn];
                const int ml = wn * 32 + jn * 8 + 2 * (lane & 3);
                const int m = m0 + ml;
                float2 r0 = make_float2(cc[0] * 0.125f, cc[1] * 0.125f);
                float2 r1 = make_float2(cc[2] * 0.125f, cc[3] * 0.125f);
                mn = fminf(mn, fminf(fminf(r0.x, r0.y), fminf(r1.x, r1.y)));
                s8[im][jn][0] += r0.x; s8[im][jn][1] += r0.y;
                s8[im][jn][2] += r1.x; s8[im][jn][3] += r1.y;
                const u16 mk0 = smask[nl * 64 + (ml >> 1)];
                const u16 mk1 = smask[(nl + 8) * 64 + (ml >> 1)];
                float p0 = (mk0 & 0xff) ? __expf(r0.x) : 0.f;
                float p1 = (mk0 >> 8)   ? __expf(r0.y) : 0.f;
                float p2 = (mk1 & 0xff) ? __expf(r1.x) : 0.f;
                float p3 = (mk1 >> 8)   ? __expf(r1.y) : 0.f;
                __half2 h0 = __floats2half2_rn(p0, p1);
                __half2 h1 = __floats2half2_rn(p2, p3);
                *(u32*)&g_s16[(bh * NN + n) * NN + m]     = *(u32*)&h0;
                *(u32*)&g_s16[(bh * NN + n + 8) * NN + m] = *(u32*)&h1;
            }
        }
    }

    // out2 head-mean (pen added by fixup kernel after global min is final)
#pragma unroll
    for (int im = 0; im < 2; im++) {
        const int n = n0 + wm * 32 + im * 16 + (lane >> 2);
#pragma unroll
        for (int jn = 0; jn < 4; jn++) {
            float* ss = s8[im][jn];
            const int m = m0 + wn * 32 + jn * 8 + 2 * (lane & 3);
            *(float2*)&O2[((size_t)b * NN + n) * NN + m] =
                make_float2(ss[0] * 0.125f, ss[1] * 0.125f);
            *(float2*)&O2[((size_t)b * NN + n + 8) * NN + m] =
                make_float2(ss[2] * 0.125f, ss[3] * 0.125f);
        }
    }

#pragma unroll
    for (int o = 16; o > 0; o >>= 1) mn = fminf(mn, __shfl_xor_sync(0xffffffffu, mn, o));
    if (lane == 0) sred[w] = mn;
    __syncthreads();
    if (t == 0) {
        float v = sred[0];
#pragma unroll
        for (int i = 1; i < 16; i++) v = fminf(v, sred[i]);
        atomicMin(&g_minenc, enc_f(v));
    }
}

// ---------------- out2 pen fixup: O2 += pen * (~mask) ------------------------
__global__ void __launch_bounds__(256)
pen_fixup_kernel(float* __restrict__ O2) {
    const int idx = blockIdx.x * 256 + threadIdx.x;   // float4 index over [n][m]
    const int total = NN * NN / 4;
    if (idx >= total) return;
    const float pen = dec_f(g_minenc) - 20.0f;
    uchar4 mk = ((const uchar4*)g_mask)[idx];
    if (mk.x && mk.y && mk.z && mk.w) return;         // common case: no change
    float4 ad = make_float4(mk.x ? 0.f : pen, mk.y ? 0.f : pen,
                            mk.z ? 0.f : pen, mk.w ? 0.f : pen);
#pragma unroll
    for (int b = 0; b < BB; b++) {
        float4* p = (float4*)&O2[(size_t)b * NN * NN + idx * 4];
        float4 v = *p;
        v.x += ad.x; v.y += ad.y; v.z += ad.z; v.w += ad.w;
        *p = v;
    }
}

// ---------------- PV fp16: P raw copy, V via cp.async, 2-combo mma -----------
// per buffer: P 0 (10240B) | Vh 10240 (5120B) | Vl 15360 (5120B)
#define PV2_BUF 20480
#define PV2_SMEM (2 * PV2_BUF)
__global__ void __launch_bounds__(256)
pv_kernel() {
    extern __shared__ __align__(16) char pvs[];
    __shared__ float sSum[128];
    const int bh = blockIdx.y, n0 = blockIdx.x * 128;
    const int t = threadIdx.x, lane = t & 31, w = t >> 5;
    const int wm = w >> 1, wn = w & 1;
    const u16* Vh = g_vh + (size_t)bh * DH * NN;
    const u16* Vl = g_vl + (size_t)bh * DH * NN;
    const u32 sb = (u32)__cvta_generic_to_shared(pvs);

    const int pr = t >> 2, psv = (t & 3) * 8;
    const int rowA = n0 + pr, rowB = rowA + 64;
    const u16* SA = g_s16 + ((size_t)bh * NN + rowA) * NN;
    const u16* SB = g_s16 + ((size_t)bh * NN + rowB) * NN;

    uint4 psA, psB;
    float sumA = 0.f, sumB = 0.f;
    float acc[2][4][4];
#pragma unroll
    for (int i = 0; i < 2; i++)
#pragma unroll
        for (int j = 0; j < 4; j++)
#pragma unroll
            for (int k = 0; k < 4; k++) acc[i][j][k] = 0.f;

    auto load_P = [&](int m0c) {
        psA = *(const uint4*)&SA[m0c + psv];
        psB = *(const uint4*)&SB[m0c + psv];
    };
    // V tiles straight to smem via cp.async: 512 granules (2/thread)
    auto issue_V = [&](int m0c, int buf) {
        const u32 base = sb + buf * PV2_BUF;
#pragma unroll
        for (int rep = 0; rep < 2; rep++) {
            const int idx = t + rep * 256;
            const int pl = idx >> 8, r = (idx >> 2) & 63, g = (idx & 3) * 8;
            const u16* src = (pl ? Vl : Vh) + (size_t)r * NN + m0c + g;
            cp16(base + (pl ? 15360 : 10240) + (u32)(r * PS + g) * 2u, src);
        }
    };
    auto store_P = [&](int buf) {
        char* base = pvs + buf * PV2_BUF;
#pragma unroll
        for (int j = 0; j < 4; j++) {
            float2 fA = __half22float2(((const __half2*)&psA)[j]);
            sumA += fA.x + fA.y;
            float2 fB = __half22float2(((const __half2*)&psB)[j]);
            sumB += fB.x + fB.y;
        }
        *(uint4*)(base + (pr * PS + psv) * 2)        = psA;
        *(uint4*)(base + ((pr + 64) * PS + psv) * 2) = psB;
    };

    load_P(0);
    issue_V(0, 0);
    store_P(0);
    CP_COMMIT();
    load_P(32);
    CP_WAIT0();
    __syncthreads();

    const int NC = NN / 32;  // 48
    for (int c = 0; c < NC; c++) {
        const int cur = c & 1;
        if (c + 1 < NC) {
            issue_V((c + 1) * 32, cur ^ 1);
            store_P(cur ^ 1);
            CP_COMMIT();
        }
        if (c + 2 < NC) load_P((c + 2) * 32);
        const u32 bb = sb + cur * PV2_BUF;
        pv_step<PS>(acc, bb, bb + 10240, bb + 15360, lane, wm * 32, wn * 32, 0);
        pv_step<PS>(acc, bb, bb + 10240, bb + 15360, lane, wm * 32, wn * 32, 16);
        if (c + 1 < NC) CP_WAIT0();
        __syncthreads();
    }

    // row-sum reduce over the 4 threads sharing a row (lanes xor 1, 2)
    sumA += __shfl_xor_sync(0xffffffffu, sumA, 1);
    sumA += __shfl_xor_sync(0xffffffffu, sumA, 2);
    sumB += __shfl_xor_sync(0xffffffffu, sumB, 1);
    sumB += __shfl_xor_sync(0xffffffffu, sumB, 2);
    if ((t & 3) == 0) { sSum[pr] = sumA; sSum[pr + 64] = sumB; }
    __syncthreads();

    // epilogue: scale by 1/rowsum, packed u32 writes to [b,h,n,d] bf16 planes
    const int b = bh >> 3, h = bh & 7;
    u32* Xh32 = (u32*)g_xth;
    u32* Xl32 = (u32*)g_xtl;
    const size_t hb = (size_t)(b * HH + h) * NN * (DH / 2);
#pragma unroll
    for (int im = 0; im < 2; im++) {
        const int rl = wm * 32 + im * 16 + (lane >> 2);
        const int n = n0 + rl;
        const float iv0 = 1.0f / sSum[rl];
        const float iv1 = 1.0f / sSum[rl + 8];
#pragma unroll
        for (int jn = 0; jn < 4; jn++) {
            float* cc = acc[im][jn];
            const int d = wn * 32 + jn * 8 + 2 * (lane & 3);
            size_t r0 = hb + (size_t)n * (DH / 2) + (d >> 1);
            size_t r1 = r0 + (size_t)8 * (DH / 2);
            float a0 = cc[0] * iv0, a1 = cc[1] * iv0;
            float a2 = cc[2] * iv1, a3 = cc[3] * iv1;
            Xh32[r0] = (u32)b16hi(a0) | ((u32)b16hi(a1) << 16);
            Xl32[r0] = (u32)b16lo(a0) | ((u32)b16lo(a1) << 16);
            Xh32[r1] = (u32)b16hi(a2) | ((u32)b16hi(a3) << 16);
            Xl32[r1] = (u32)b16lo(a2) | ((u32)b16lo(a3) << 16);
        }
    }
}

// ---------------- launch ------------------------------------------------------
extern "C" void kernel_launch(void* const* d_in, const int* in_sizes, int n_in,
                              void* d_out, int out_size) {
    const float* query = (const float*)d_in[0];
    const float* key   = (const float*)d_in[1];
    const float* value = (const float*)d_in[2];
    // d_in[3] = dist (unused)
    const void* mask   = d_in[4];
    const float* Wq = (const float*)d_in[5];
    const float* bq = (const float*)d_in[6];
    const float* Wk = (const float*)d_in[7];
    const float* bk = (const float*)d_in[8];
    const float* Wv = (const float*)d_in[9];
    const float* bv = (const float*)d_in[10];
    const float* Wm = (const float*)d_in[11];
    const float* bm = (const float*)d_in[12];

    float* out  = (float*)d_out;                 // [B, D, N]
    float* out2 = out + (size_t)BB * DD * NN;    // [B, N, N]

    void *pih, *pil, *pwh, *pwl, *pqh, *pql, *pkh, *pkl, *pvh, *pvl, *pxth, *pxtl;
    cudaGetSymbolAddress(&pih, g_ith);
    cudaGetSymbolAddress(&pil, g_itl);
    cudaGetSymbolAddress(&pwh, g_wh);
    cudaGetSymbolAddress(&pwl, g_wl);
    cudaGetSymbolAddress(&pqh, g_qh);
    cudaGetSymbolAddress(&pql, g_ql);
    cudaGetSymbolAddress(&pkh, g_kh);
    cudaGetSymbolAddress(&pkl, g_kl);
    cudaGetSymbolAddress(&pvh, g_vh);
    cudaGetSymbolAddress(&pvl, g_vl);
    cudaGetSymbolAddress(&pxth, g_xth);
    cudaGetSymbolAddress(&pxtl, g_xtl);

    const u16* ith = (const u16*)pih;
    const u16* itl = (const u16*)pil;
    const u16* wh  = (const u16*)pwh;
    const u16* wl  = (const u16*)pwl;
    const size_t WB = (size_t)DD * DD;

    // One-time setup on the first (uncaptured) call: attrs, side stream, events.
    static cudaStream_t s2 = nullptr;
    static cudaEvent_t evF = nullptr, evA = nullptr, evW = nullptr, evI = nullptr,
                       evB = nullptr, evV = nullptr, evC = nullptr, evD = nullptr;
    if (s2 == nullptr) {
        cudaFuncSetAttribute(scores_kernel,
                             cudaFuncAttributeMaxDynamicSharedMemorySize, SC_SMEM);
        cudaFuncSetAttribute(projqkv_kernel,
                             cudaFuncAttributeMaxDynamicSharedMemorySize, PJ_SMEM);
        cudaFuncSetAttribute(proj0_kernel,
                             cudaFuncAttributeMaxDynamicSharedMemorySize, PJ_SMEM);
        cudaFuncSetAttribute(pv_kernel,
                             cudaFuncAttributeMaxDynamicSharedMemorySize, PV2_SMEM);
        cudaStreamCreateWithFlags(&s2, cudaStreamNonBlocking);
        cudaEventCreateWithFlags(&evF, cudaEventDisableTiming);
        cudaEventCreateWithFlags(&evA, cudaEventDisableTiming);
        cudaEventCreateWithFlags(&evW, cudaEventDisableTiming);
        cudaEventCreateWithFlags(&evI, cudaEventDisableTiming);
        cudaEventCreateWithFlags(&evB, cudaEventDisableTiming);
        cudaEventCreateWithFlags(&evV, cudaEventDisableTiming);
        cudaEventCreateWithFlags(&evC, cudaEventDisableTiming);
        cudaEventCreateWithFlags(&evD, cudaEventDisableTiming);
    }

    // main: init first, then record the fork event (s2 must fork FROM the
    // captured origin stream before any s2 launch — graph-capture rule).
    init_kernel<<<1, 1>>>();
    cudaEventRecord(evA, 0);

    // fork s2 from the capture
    cudaStreamWaitEvent(s2, evA, 0);

    // s2: weight presplit (|| presplit_in), then mask chain
    presplit_w_kernel<<<1024, 256, 0, s2>>>(Wq, Wk, Wv, Wm);
    cudaEventRecord(evW, s2);
    mask_classify_kernel<<<256, 256, 0, s2>>>((const u32*)mask);
    mask_convert_kernel<<<256, 256, 0, s2>>>(mask);
    cudaEventRecord(evB, s2);

    // main: input presplit (|| s2 weight presplit)
    presplit_in_kernel<<<dim3(NN / 32, DD / 32, 3 * BB), dim3(32, 8)>>>(query, key, value);
    cudaEventRecord(evI, 0);

    // main: Q,K projection (needs weights + inputs)
    cudaStreamWaitEvent(0, evW, 0);
    projqkv_kernel<<<dim3(NN / 128, DD / 64, 2 * BB), 256, PJ_SMEM>>>(
        0, ith, itl, wh, wl, bq, bk, bv,
        (u32*)pqh, (u32*)pql, (u32*)pkh, (u32*)pkl, (u32*)pvh, (u32*)pvl);

    // s2: V projection (needs inputs; || projQK tail + scores head)
    cudaStreamWaitEvent(s2, evI, 0);
    projqkv_kernel<<<dim3(NN / 128, DD / 64, BB), 256, PJ_SMEM, s2>>>(
        2, ith, itl, wh, wl, bq, bk, bv,
        (u32*)pqh, (u32*)pql, (u32*)pkh, (u32*)pkl, (u32*)pvh, (u32*)pvl);
    cudaEventRecord(evV, s2);

    // main: scores (needs Q,K + mask)
    cudaStreamWaitEvent(0, evB, 0);
    scores_kernel<<<dim3(NN / 128, NN / 128, BB), 512, SC_SMEM>>>(out2);
    cudaEventRecord(evC, 0);

    // s2: out2 penalty fixup (|| pv + proj0)
    cudaStreamWaitEvent(s2, evC, 0);
    pen_fixup_kernel<<<(NN * NN / 4 + 255) / 256, 256, 0, s2>>>(out2);
    cudaEventRecord(evD, s2);

    // main: pv (needs scores + V) then final projection
    cudaStreamWaitEvent(0, evV, 0);
    pv_kernel<<<dim3(NN / 128, BB * HH), 256, PV2_SMEM>>>();
    proj0_kernel<<<dim3(NN / 128, DD / 64, BB), 256, PJ_SMEM>>>(
        (const u16*)pxth, (const u16*)pxtl, wh + 3 * WB, wl + 3 * WB, bm, out);

    cudaStreamWaitEvent(0, evD, 0);   // join side stream before capture ends
}